// round 9
// baseline (speedup 1.0000x reference)
#include <cuda_runtime.h>
#include <cuda_fp16.h>
#include <math.h>

// Problem constants (fixed by dataset): B=1, N=384, C=H=128
#define NN   384
#define CC   128
#define MTOT (NN*NN)
#define EPS  1e-5f
#define XPAD 136      // data plane row stride (fp16 elems)
#define BPAD 136      // weight / right row stride (fp16 elems)
#define APAD 72       // kernelB left-tile row stride (fp16 elems)
#define T    512      // threads per block (16 warps)

// ---------------- scratch ------------------------------------------------------
// All GEMM operands single fp16 (accumulate fp32). Calibrated error model:
// one rounded operand per GEMM measured 4.8e-5 end-to-end (R8); two operands
// per GEMM adds an independent 2^-12 source -> ~1e-4, >=7x under 1e-3.
__device__ __half g_leftH [(size_t)CC * MTOT];   // [h][i][k]
__device__ __half g_rightH[(size_t)CC * MTOT];   // [h][k][j]
__device__ __half g_gateh [(size_t)CC * MTOT];   // [h][i*N+j] fp16 sigmoid
__device__ __half g_v     [(size_t)CC * MTOT];   // [h][i*N+j] fp16 out*gate
__device__ __half g_Wl[CC*CC], g_Wr[CC*CC], g_Wg[CC*CC], g_Wo[CC*CC];
__device__ float g_bLE[CC], g_bRE[CC], g_WgS[CC];

// ---------------- helpers (baseline PTX only) ----------------------------------
__device__ __forceinline__ unsigned smem_u32(const void* p) {
    return (unsigned)__cvta_generic_to_shared(p);
}
__device__ __forceinline__ void cp16(unsigned saddr, const void* g) {
    asm volatile("cp.async.cg.shared.global [%0], [%1], 16;" :: "r"(saddr), "l"(g));
}
__device__ __forceinline__ void cp_commit() {
    asm volatile("cp.async.commit_group;" ::: "memory");
}
template<int N>
__device__ __forceinline__ void cp_wait() {
    asm volatile("cp.async.wait_group %0;" :: "n"(N) : "memory");
}
__device__ __forceinline__ void ldmx4(unsigned r[4], unsigned addr) {
    asm volatile("ldmatrix.sync.aligned.m8n8.x4.shared.b16 {%0,%1,%2,%3}, [%4];"
        : "=r"(r[0]), "=r"(r[1]), "=r"(r[2]), "=r"(r[3]) : "r"(addr));
}
__device__ __forceinline__ void ldmx4t(unsigned r[4], unsigned addr) {
    asm volatile("ldmatrix.sync.aligned.m8n8.x4.trans.shared.b16 {%0,%1,%2,%3}, [%4];"
        : "=r"(r[0]), "=r"(r[1]), "=r"(r[2]), "=r"(r[3]) : "r"(addr));
}
__device__ __forceinline__ void mma16816(float d[4], const unsigned a[4],
                                         unsigned b0, unsigned b1) {
    asm volatile(
        "mma.sync.aligned.m16n8k16.row.col.f32.f16.f16.f32 "
        "{%0,%1,%2,%3}, {%4,%5,%6,%7}, {%8,%9}, {%0,%1,%2,%3};"
        : "+f"(d[0]), "+f"(d[1]), "+f"(d[2]), "+f"(d[3])
        : "r"(a[0]), "r"(a[1]), "r"(a[2]), "r"(a[3]), "r"(b0), "r"(b1));
}

// ---------------- prep kernels --------------------------------------------------
__global__ void prep_fold(const float* __restrict__ W,
                          const float* __restrict__ g,
                          const float* __restrict__ beta,
                          const float* __restrict__ b,
                          __half* __restrict__ WH,
                          float* __restrict__ bE)
{
    int k = blockIdx.x, n = threadIdx.x;
    WH[k*CC + n] = __float2half_rn(g[k] * W[k*CC + n]);
    if (k == 0) {
        float s = b[n];
        for (int kk = 0; kk < CC; kk++) s += beta[kk] * W[kk*CC + n];
        bE[n] = s;
    }
}
__global__ void prep_pack(const float* __restrict__ W,
                          __half* __restrict__ WH,
                          float* __restrict__ S)
{
    int k = blockIdx.x, n = threadIdx.x;
    WH[k*CC + n] = __float2half_rn(W[k*CC + n]);
    if (k == 0 && S) {
        float s = 0.f;
        for (int kk = 0; kk < CC; kk++) s += W[kk*CC + n];
        S[n] = s;
    }
}

// ---------------- HMMA projection GEMM: single x single, 1 MMA -----------------
// A plane [128][XPAD] in smem; weight plane streamed 2-stage from global.
__device__ __forceinline__ void hmma_proj(
    const __half* __restrict__ aP,
    const __half* __restrict__ W,
    __half* __restrict__ wst,
    float acc[8][4],
    int tid, int wm, int wn,
    int a_row, int a_kh, int b_kr, int b_nc)
{
    const int PLANE = 64*BPAD;
#pragma unroll
    for (int nj = 0; nj < 8; nj++)
#pragma unroll
        for (int q = 0; q < 4; q++) acc[nj][q] = 0.f;

#pragma unroll
    for (int s = 0; s < 2; s++) {
        __half* d = wst + s*PLANE;
        int k0 = s*64;
#pragma unroll
        for (int t = 0; t < 2; t++) {
            int idx = tid + t*T;            // 0..1023 (64 rows x 16 chunks)
            int r = idx >> 4, c = idx & 15;
            cp16(smem_u32(d + r*BPAD + c*8), W + (k0 + r)*CC + c*8);
        }
        cp_commit();
    }

#pragma unroll
    for (int s = 0; s < 2; s++) {
        if (s == 0) cp_wait<1>(); else cp_wait<0>();
        __syncthreads();
        const __half* bP = wst + s*PLANE;
        int k0 = s*64;
#pragma unroll
        for (int kk = 0; kk < 64; kk += 16) {
            unsigned aF[4];
            ldmx4(aF, smem_u32(aP + (wm + a_row)*XPAD + k0 + kk + a_kh));
#pragma unroll
            for (int nh = 0; nh < 4; nh++) {
                unsigned bF[4];
                ldmx4t(bF, smem_u32(bP + (kk + b_kr)*BPAD + wn + nh*16 + b_nc));
                mma16816(acc[nh*2 + 0], aF, bF[0], bF[1]);
                mma16816(acc[nh*2 + 1], aF, bF[2], bF[3]);
            }
        }
    }
    __syncthreads();   // protect wst for next call
}

// fragment -> transposed channel-major, single fp16 plane
__device__ __forceinline__ void frag_store_half(
    const float acc[8][4], const float* __restrict__ bias,
    unsigned* __restrict__ stage,
    __half* __restrict__ dstH,
    size_t R0, int lane, int wm, int wn, int tid)
{
    int r = wm + (lane >> 2);
#pragma unroll
    for (int nj = 0; nj < 8; nj++) {
        int c = wn + nj*8 + (lane & 3)*2;
        float b0 = __ldg(bias + c), b1 = __ldg(bias + c + 1);
        stage[c*129 + r]       = (unsigned)__half_as_ushort(__float2half_rn(acc[nj][0] + b0));
        stage[(c+1)*129 + r]   = (unsigned)__half_as_ushort(__float2half_rn(acc[nj][1] + b1));
        stage[c*129 + r+8]     = (unsigned)__half_as_ushort(__float2half_rn(acc[nj][2] + b0));
        stage[(c+1)*129 + r+8] = (unsigned)__half_as_ushort(__float2half_rn(acc[nj][3] + b1));
    }
    __syncthreads();
    for (int idx = tid; idx < 128*64; idx += T) {
        int n = idx >> 6, r2 = idx & 63;
        unsigned w0 = stage[n*129 + 2*r2], w1 = stage[n*129 + 2*r2 + 1];
        unsigned hw = (w0 & 0xFFFFu) | (w1 << 16);
        *reinterpret_cast<unsigned*>(dstH + (size_t)n*MTOT + R0 + 2*r2) = hw;
    }
    __syncthreads();
}

// gate: logit = sd[r]*acc + mu[r]*S[c] + bg[c]; sigmoid; fp16 channel-major
__device__ __forceinline__ void frag_store_gate(
    const float acc[8][4], const float* __restrict__ bg,
    const float* __restrict__ Sg,
    const float* __restrict__ sd_s, const float* __restrict__ mu_s,
    float* __restrict__ stage, __half* __restrict__ dst,
    size_t R0, int lane, int wm, int wn, int tid)
{
    int r = wm + (lane >> 2);
    float sd0 = sd_s[r], mu0 = mu_s[r];
    float sd1 = sd_s[r+8], mu1 = mu_s[r+8];
#pragma unroll
    for (int nj = 0; nj < 8; nj++) {
        int c = wn + nj*8 + (lane & 3)*2;
        float S0 = __ldg(Sg + c) , B0 = __ldg(bg + c);
        float S1 = __ldg(Sg + c+1), B1 = __ldg(bg + c+1);
        float z;
        z = sd0*acc[nj][0] + mu0*S0 + B0; stage[c*129 + r]       = 1.f/(1.f+expf(-z));
        z = sd0*acc[nj][1] + mu0*S1 + B1; stage[(c+1)*129 + r]   = 1.f/(1.f+expf(-z));
        z = sd1*acc[nj][2] + mu1*S0 + B0; stage[c*129 + r+8]     = 1.f/(1.f+expf(-z));
        z = sd1*acc[nj][3] + mu1*S1 + B1; stage[(c+1)*129 + r+8] = 1.f/(1.f+expf(-z));
    }
    __syncthreads();
    for (int idx = tid; idx < 128*64; idx += T) {
        int n = idx >> 6, r2 = idx & 63;
        __half h0 = __float2half_rn(stage[n*129 + 2*r2]);
        __half h1 = __float2half_rn(stage[n*129 + 2*r2 + 1]);
        unsigned hw = (unsigned)__half_as_ushort(h0) | ((unsigned)__half_as_ushort(h1) << 16);
        *reinterpret_cast<unsigned*>(dst + (size_t)n*MTOT + R0 + 2*r2) = hw;
    }
    __syncthreads();
}

// ---------------- kernel A: LN + 3 projections ---------------------------------
__global__ void __launch_bounds__(T, 1)
kernelA(const float* __restrict__ pair,
        const float* __restrict__ bg)
{
    extern __shared__ __align__(16) char smA[];
    __half* xh  = (__half*)smA;                    // [128][XPAD]            (34816 B)
    __half* wst = xh + 128*XPAD;                   // 2 stages x 64*BPAD     (34816 B)
    char* stg = smA + 69632;                       // [128][129] stage       (66048 B)
    unsigned* stageU = (unsigned*)stg;
    float*    stageF = (float*)stg;
    float* mu_s = (float*)(smA + 135680);
    float* rs_s = mu_s + 128;
    float* sd_s = rs_s + 128;

    const int tid = threadIdx.x;
    const int lane = tid & 31, wid = tid >> 5;
    const int wm = (wid & 7)*16, wn = (wid >> 3)*64;
    const int a_row = (lane & 7) + ((lane >> 3) & 1)*8;
    const int a_kh  = (lane >> 4)*8;
    const int b_kr  = (lane & 7) + ((lane >> 3) & 1)*8;
    const int b_nc  = (lane >> 4)*8;
    const size_t R0 = (size_t)blockIdx.x * 128;

    // LN stats: warp per 8 rows, coalesced global float4 read + shuffle reduce
#pragma unroll
    for (int rr = 0; rr < 8; rr++) {
        int r = wid*8 + rr;
        float4 v = *reinterpret_cast<const float4*>(pair + (R0 + r)*CC + lane*4);
        float s  = v.x + v.y + v.z + v.w;
        float s2 = v.x*v.x + v.y*v.y + v.z*v.z + v.w*v.w;
#pragma unroll
        for (int off = 16; off > 0; off >>= 1) {
            s  += __shfl_xor_sync(0xffffffffu, s,  off);
            s2 += __shfl_xor_sync(0xffffffffu, s2, off);
        }
        if (lane == 0) {
            float mu  = s * (1.f/128.f);
            float var = fmaxf(s2 * (1.f/128.f) - mu*mu, 0.f) + EPS;
            mu_s[r] = mu;
            rs_s[r] = rsqrtf(var);
            sd_s[r] = sqrtf(var);
        }
    }
    __syncthreads();

    // xhat -> single fp16 plane (pair re-read is L2-hot)
    for (int i = tid; i < 128*32; i += T) {
        int r = i >> 5, c4 = i & 31;
        float4 v = *reinterpret_cast<const float4*>(pair + (R0 + r)*CC + c4*4);
        float mu = mu_s[r], rs = rs_s[r];
        __half2 h0 = __floats2half2_rn((v.x - mu)*rs, (v.y - mu)*rs);
        __half2 h1 = __floats2half2_rn((v.z - mu)*rs, (v.w - mu)*rs);
        *reinterpret_cast<uint2*>(xh + r*XPAD + c4*4) =
            make_uint2(*(unsigned*)&h0, *(unsigned*)&h1);
    }
    // hmma_proj's internal sync (post cp_wait) orders plane writes before ldmatrix

    float acc[8][4];
    hmma_proj(xh, g_Wl, wst, acc, tid, wm, wn, a_row, a_kh, b_kr, b_nc);
    frag_store_half(acc, g_bLE, stageU, g_leftH, R0, lane, wm, wn, tid);
    hmma_proj(xh, g_Wr, wst, acc, tid, wm, wn, a_row, a_kh, b_kr, b_nc);
    frag_store_half(acc, g_bRE, stageU, g_rightH, R0, lane, wm, wn, tid);
    hmma_proj(xh, g_Wg, wst, acc, tid, wm, wn, a_row, a_kh, b_kr, b_nc);
    frag_store_gate(acc, bg, g_WgS, sd_s, mu_s, stageF, g_gateh, R0, lane, wm, wn, tid);
}

// ---------------- kernel B: per-channel 384^3 GEMM + fused gate ----------------
#define KB_STG (128*APAD + 64*BPAD)   // fp16 elements per stage (17920)

__device__ __forceinline__ void kb_prefetch(
    __half* st,
    const __half* __restrict__ AgH,
    const __half* __restrict__ BgH,
    int k0, int tid)
{
    __half* aH = st;
    __half* bH = st + 128*APAD;
#pragma unroll
    for (int t = 0; t < 2; t++) {
        int idx = tid + t*T;                // 0..1023 (128 rows x 8 chunks)
        int r = idx >> 3, c = idx & 7;
        cp16(smem_u32(aH + r*APAD + c*8), AgH + (size_t)r*NN + k0 + c*8);
    }
#pragma unroll
    for (int t = 0; t < 2; t++) {
        int idx = tid + t*T;                // 0..1023 (64 rows x 16 chunks)
        int r = idx >> 4, c = idx & 15;
        cp16(smem_u32(bH + r*BPAD + c*8), BgH + (size_t)(k0 + r)*NN + c*8);
    }
}

__global__ void __launch_bounds__(T, 1)
kernelB_mma()
{
    extern __shared__ __align__(16) __half smb[];
    const int tid  = threadIdx.x;
    const int lane = tid & 31, wid = tid >> 5;
    const int J0 = blockIdx.x*128, I0 = blockIdx.y*128, h = blockIdx.z;
    const int wm = (wid & 7)*16, wn = (wid >> 3)*64;

    const __half* __restrict__ AgH = g_leftH  + (size_t)h*MTOT + (size_t)I0*NN;
    const __half* __restrict__ BgH = g_rightH + (size_t)h*MTOT + J0;

    float acc[8][4];
#pragma unroll
    for (int nj = 0; nj < 8; nj++)
#pragma unroll
        for (int q = 0; q < 4; q++) acc[nj][q] = 0.f;

    const int a_row = (lane & 7) + ((lane >> 3) & 1)*8;
    const int a_kh  = (lane >> 4)*8;
    const int b_kr  = (lane & 7) + ((lane >> 3) & 1)*8;
    const int b_nc  = (lane >> 4)*8;

    kb_prefetch(smb, AgH, BgH, 0, tid);
    cp_commit();

    for (int ch = 0; ch < 6; ch++) {
        if (ch + 1 < 6) {
            kb_prefetch(smb + ((ch+1)&1)*KB_STG, AgH, BgH, (ch+1)*64, tid);
            cp_commit();
            cp_wait<1>();
        } else {
            cp_wait<0>();
        }
        __syncthreads();

        const __half* aH = smb + (ch&1)*KB_STG;
        const __half* bH = aH + 128*APAD;
#pragma unroll
        for (int kk = 0; kk < 64; kk += 16) {
            unsigned aF[4];
            ldmx4(aF, smem_u32(aH + (wm + a_row)*APAD + kk + a_kh));
#pragma unroll
            for (int nh = 0; nh < 4; nh++) {
                unsigned bF[4];
                ldmx4t(bF, smem_u32(bH + (kk + b_kr)*BPAD + wn + nh*16 + b_nc));
                mma16816(acc[nh*2 + 0], aF, bF[0], bF[1]);
                mma16816(acc[nh*2 + 1], aF, bF[2], bF[3]);
            }
        }
        __syncthreads();
    }

    // epilogue: v = out * gate, fp16
    const __half* __restrict__ Gg = g_gateh + (size_t)h*MTOT;
    __half* __restrict__       Vd = g_v     + (size_t)h*MTOT;
    int r0 = I0 + wm + (lane >> 2);
#pragma unroll
    for (int nj = 0; nj < 8; nj++) {
        int c = J0 + wn + nj*8 + (lane & 3)*2;
        size_t o0 = (size_t)r0*NN + c;
        size_t o1 = (size_t)(r0+8)*NN + c;
        float2 ga0 = __half22float2(*reinterpret_cast<const __half2*>(Gg + o0));
        float2 ga1 = __half22float2(*reinterpret_cast<const __half2*>(Gg + o1));
        __half2 v0 = __floats2half2_rn(acc[nj][0]*ga0.x, acc[nj][1]*ga0.y);
        __half2 v1 = __floats2half2_rn(acc[nj][2]*ga1.x, acc[nj][3]*ga1.y);
        *reinterpret_cast<__half2*>(Vd + o0) = v0;
        *reinterpret_cast<__half2*>(Vd + o1) = v1;
    }
}

// ---------------- kernel C: v @ Wo + bo + residual + LN ------------------------
__global__ void __launch_bounds__(T, 1)
kernelC(const float* __restrict__ pair,
        const float* __restrict__ bo,
        const float* __restrict__ ng,
        const float* __restrict__ nb,
        float* __restrict__ out)
{
    extern __shared__ __align__(16) char smC[];
    __half* vP  = (__half*)smC;                    // [128][XPAD]
    __half* wst = vP + 128*XPAD;                   // 2 stages x 64*BPAD
    float* y_s  = (float*)(smC + 69632);           // [128][129]
    float* mu_s = (float*)(smC + 135680);
    float* rs_s = mu_s + 128;

    const int tid = threadIdx.x;
    const int lane = tid & 31, wid = tid >> 5;
    const int wm = (wid & 7)*16, wn = (wid >> 3)*64;
    const int a_row = (lane & 7) + ((lane >> 3) & 1)*8;
    const int a_kh  = (lane >> 4)*8;
    const int b_kr  = (lane & 7) + ((lane >> 3) & 1)*8;
    const int b_nc  = (lane >> 4)*8;
    const size_t IJ0 = (size_t)blockIdx.x * 128;

    // v (fp16, channel-major) -> transposed plane vP[r][h]
    for (int i = tid; i < 128*64; i += T) {
        int h = i >> 6, r2 = i & 63;
        __half2 v = *reinterpret_cast<const __half2*>(g_v + (size_t)h*MTOT + IJ0 + 2*r2);
        vP[(2*r2)*XPAD + h]   = __low2half(v);
        vP[(2*r2+1)*XPAD + h] = __high2half(v);
    }
    // hmma_proj's internal sync covers plane visibility

    float acc[8][4];
    hmma_proj(vP, g_Wo, wst, acc, tid, wm, wn, a_row, a_kh, b_kr, b_nc);

    // y = acc + bo + pair residual -> y_s
    {
        int r = wm + (lane >> 2);
#pragma unroll
        for (int nj = 0; nj < 8; nj++) {
            int c = wn + nj*8 + (lane & 3)*2;
            float b0 = __ldg(bo + c), b1 = __ldg(bo + c + 1);
            float2 p0 = *reinterpret_cast<const float2*>(pair + (IJ0 + r)*CC + c);
            float2 p1 = *reinterpret_cast<const float2*>(pair + (IJ0 + r + 8)*CC + c);
            y_s[r*129 + c]       = acc[nj][0] + b0 + p0.x;
            y_s[r*129 + c+1]     = acc[nj][1] + b1 + p0.y;
            y_s[(r+8)*129 + c]   = acc[nj][2] + b0 + p1.x;
            y_s[(r+8)*129 + c+1] = acc[nj][3] + b1 + p1.y;
        }
    }
    __syncthreads();

    // row LN: warp per 8 rows via shuffle — SCALAR smem loads (516B row stride)
#pragma unroll
    for (int rr = 0; rr < 8; rr++) {
        int r = wid*8 + rr;
        const float* row = y_s + r*129 + lane*4;
        float v0 = row[0], v1 = row[1], v2 = row[2], v3 = row[3];
        float s  = v0 + v1 + v2 + v3;
        float s2 = v0*v0 + v1*v1 + v2*v2 + v3*v3;
#pragma unroll
        for (int off = 16; off > 0; off >>= 1) {
            s  += __shfl_xor_sync(0xffffffffu, s,  off);
            s2 += __shfl_xor_sync(0xffffffffu, s2, off);
        }
        if (lane == 0) {
            float mu  = s * (1.f/128.f);
            float var = fmaxf(s2 * (1.f/128.f) - mu*mu, 0.f) + EPS;
            mu_s[r] = mu;
            rs_s[r] = rsqrtf(var);
        }
    }
    __syncthreads();

    for (int i = tid; i < 128*128; i += T) {
        int r = i >> 7, c = i & 127;
        float z = y_s[r*129 + c];
        out[(IJ0 + r)*CC + c] = (z - mu_s[r]) * rs_s[r] * __ldg(ng + c) + __ldg(nb + c);
    }
}

// ---------------- launch --------------------------------------------------------
extern "C" void kernel_launch(void* const* d_in, const int* in_sizes, int n_in,
                              void* d_out, int out_size)
{
    const float* pair   = (const float*)d_in[0];
    const float* ln_l_g = (const float*)d_in[1];
    const float* ln_l_b = (const float*)d_in[2];
    const float* ln_r_g = (const float*)d_in[3];
    const float* ln_r_b = (const float*)d_in[4];
    const float* Wl     = (const float*)d_in[5];
    const float* bl     = (const float*)d_in[6];
    const float* Wr     = (const float*)d_in[7];
    const float* br     = (const float*)d_in[8];
    const float* Wg     = (const float*)d_in[9];
    const float* bg     = (const float*)d_in[10];
    const float* Wo     = (const float*)d_in[11];
    const float* bo     = (const float*)d_in[12];
    const float* n_g    = (const float*)d_in[13];
    const float* n_b    = (const float*)d_in[14];
    float* out = (float*)d_out;

    static __half *pWl = nullptr, *pWr, *pWg, *pWo;
    static float *pbLE, *pbRE, *pWgS;
    if (!pWl) {
        cudaGetSymbolAddress((void**)&pWl, g_Wl);
        cudaGetSymbolAddress((void**)&pWr, g_Wr);
        cudaGetSymbolAddress((void**)&pWg, g_Wg);
        cudaGetSymbolAddress((void**)&pWo, g_Wo);
        cudaGetSymbolAddress((void**)&pbLE, g_bLE);
        cudaGetSymbolAddress((void**)&pbRE, g_bRE);
        cudaGetSymbolAddress((void**)&pWgS, g_WgS);
    }

    // smem: plane 34816 | wst 34816 | stage 66048 | stats
    const size_t smemA = 137728;
    const size_t smemC = 137728;
    const size_t smemB = (size_t)2*KB_STG*sizeof(__half);   // 71680
    cudaFuncSetAttribute(kernelA,     cudaFuncAttributeMaxDynamicSharedMemorySize, (int)smemA);
    cudaFuncSetAttribute(kernelC,     cudaFuncAttributeMaxDynamicSharedMemorySize, (int)smemC);
    cudaFuncSetAttribute(kernelB_mma, cudaFuncAttributeMaxDynamicSharedMemorySize, (int)smemB);

    prep_fold<<<CC, CC>>>(Wl, ln_l_g, ln_l_b, bl, pWl, pbLE);
    prep_fold<<<CC, CC>>>(Wr, ln_r_g, ln_r_b, br, pWr, pbRE);
    prep_pack<<<CC, CC>>>(Wg, pWg, pWgS);
    prep_pack<<<CC, CC>>>(Wo, pWo, nullptr);

    kernelA<<<MTOT/128, T, smemA>>>(pair, bg);
    kernelB_mma<<<dim3(NN/128, NN/128, CC), T, smemB>>>();
    kernelC<<<MTOT/128, T, smemC>>>(pair, bo, n_g, n_b, out);
}

// round 10
// speedup vs baseline: 1.2360x; 1.2360x over previous
#include <cuda_runtime.h>
#include <cuda_fp16.h>
#include <math.h>

// Problem constants (fixed by dataset): B=1, N=384, C=H=128
#define NN   384
#define CC   128
#define MTOT (NN*NN)
#define EPS  1e-5f
#define XPAD 136      // data plane row stride (fp16 elems)
#define BPAD 136      // weight / right row stride (fp16 elems)
#define APAD 72       // kernelB left-tile row stride (fp16 elems)
#define T    512      // threads per block (16 warps)

// ---------------- scratch ------------------------------------------------------
// R8 structure (fastest known): split-fp16 on ONE operand per GEMM (2 MMAs),
// other operand single fp16. R10: outm + gate stored fp16 (calibrated error
// budget: each extra rounded tensor adds an independent ~2^-12 source).
__device__ __half g_leftH [(size_t)CC * MTOT];   // [h][i][k]
__device__ __half g_leftL [(size_t)CC * MTOT];
__device__ __half g_rightH[(size_t)CC * MTOT];   // [h][k][j]  (single plane)
__device__ __half g_gateh [(size_t)CC * MTOT];   // [h][i*N+j] fp16 sigmoid
__device__ __half g_outm  [(size_t)CC * MTOT];   // [h][i*N+j] fp16 einsum out
__device__ __half g_WlH[CC*CC], g_WlL[CC*CC];    // LN-folded split weights [k][n]
__device__ __half g_WrH[CC*CC], g_WrL[CC*CC];
__device__ __half g_WgH[CC*CC], g_WgL[CC*CC];
__device__ __half g_WoH[CC*CC], g_WoL[CC*CC];
__device__ float g_bLE[CC], g_bRE[CC], g_WgS[CC];

// ---------------- helpers (baseline PTX only) ----------------------------------
__device__ __forceinline__ unsigned smem_u32(const void* p) {
    return (unsigned)__cvta_generic_to_shared(p);
}
__device__ __forceinline__ void cp16(unsigned saddr, const void* g) {
    asm volatile("cp.async.cg.shared.global [%0], [%1], 16;" :: "r"(saddr), "l"(g));
}
__device__ __forceinline__ void cp_commit() {
    asm volatile("cp.async.commit_group;" ::: "memory");
}
template<int N>
__device__ __forceinline__ void cp_wait() {
    asm volatile("cp.async.wait_group %0;" :: "n"(N) : "memory");
}
__device__ __forceinline__ void ldmx4(unsigned r[4], unsigned addr) {
    asm volatile("ldmatrix.sync.aligned.m8n8.x4.shared.b16 {%0,%1,%2,%3}, [%4];"
        : "=r"(r[0]), "=r"(r[1]), "=r"(r[2]), "=r"(r[3]) : "r"(addr));
}
__device__ __forceinline__ void ldmx4t(unsigned r[4], unsigned addr) {
    asm volatile("ldmatrix.sync.aligned.m8n8.x4.trans.shared.b16 {%0,%1,%2,%3}, [%4];"
        : "=r"(r[0]), "=r"(r[1]), "=r"(r[2]), "=r"(r[3]) : "r"(addr));
}
__device__ __forceinline__ void mma16816(float d[4], const unsigned a[4],
                                         unsigned b0, unsigned b1) {
    asm volatile(
        "mma.sync.aligned.m16n8k16.row.col.f32.f16.f16.f32 "
        "{%0,%1,%2,%3}, {%4,%5,%6,%7}, {%8,%9}, {%0,%1,%2,%3};"
        : "+f"(d[0]), "+f"(d[1]), "+f"(d[2]), "+f"(d[3])
        : "r"(a[0]), "r"(a[1]), "r"(a[2]), "r"(a[3]), "r"(b0), "r"(b1));
}
__device__ __forceinline__ unsigned pack_splitH(float v) {   // hi<<16 | lo (fp16)
    __half hi = __float2half_rn(v);
    float r = v - __half2float(hi);
    __half lo = __float2half_rn(r);
    return ((unsigned)__half_as_ushort(hi) << 16) | (unsigned)__half_as_ushort(lo);
}

// ---------------- prep kernels --------------------------------------------------
__global__ void prep_fold(const float* __restrict__ W,
                          const float* __restrict__ g,
                          const float* __restrict__ beta,
                          const float* __restrict__ b,
                          __half* __restrict__ WH,
                          __half* __restrict__ WL,
                          float* __restrict__ bE)
{
    int k = blockIdx.x, n = threadIdx.x;
    float v = g[k] * W[k*CC + n];
    __half hi = __float2half_rn(v);
    WH[k*CC + n] = hi;
    WL[k*CC + n] = __float2half_rn(v - __half2float(hi));
    if (k == 0) {
        float s = b[n];
        for (int kk = 0; kk < CC; kk++) s += beta[kk] * W[kk*CC + n];
        bE[n] = s;
    }
}
__global__ void prep_pack(const float* __restrict__ W,
                          __half* __restrict__ WH,
                          __half* __restrict__ WL,
                          float* __restrict__ S)
{
    int k = blockIdx.x, n = threadIdx.x;
    float v = W[k*CC + n];
    __half hi = __float2half_rn(v);
    WH[k*CC + n] = hi;
    WL[k*CC + n] = __float2half_rn(v - __half2float(hi));
    if (k == 0 && S) {
        float s = 0.f;
        for (int kk = 0; kk < CC; kk++) s += W[kk*CC + n];
        S[n] = s;
    }
}

// ---------------- HMMA projection GEMM: xhat(single) x W(split), 2 MMAs --------
__device__ __forceinline__ void hmma_proj(
    const __half* __restrict__ aP,
    const __half* __restrict__ WH,
    const __half* __restrict__ WL,
    __half* __restrict__ wst,
    float acc[8][4],
    int tid, int wm, int wn,
    int a_row, int a_kh, int b_kr, int b_nc)
{
    const int PLANE = 64*BPAD;
#pragma unroll
    for (int nj = 0; nj < 8; nj++)
#pragma unroll
        for (int q = 0; q < 4; q++) acc[nj][q] = 0.f;

#pragma unroll
    for (int s = 0; s < 2; s++) {
        __half* dH = wst + s*2*PLANE;
        __half* dL = dH + PLANE;
        int k0 = s*64;
#pragma unroll
        for (int t = 0; t < 4; t++) {
            int idx = tid + t*T;            // 0..2047
            int r = idx >> 5, rem = idx & 31;
            int pl = rem >> 4, c = rem & 15;
            const __half* src = (pl ? WL : WH) + (k0 + r)*CC + c*8;
            __half* dst = (pl ? dL : dH) + r*BPAD + c*8;
            cp16(smem_u32(dst), src);
        }
        cp_commit();
    }

#pragma unroll
    for (int s = 0; s < 2; s++) {
        if (s == 0) cp_wait<1>(); else cp_wait<0>();
        __syncthreads();
        const __half* bH = wst + s*2*PLANE;
        int k0 = s*64;
#pragma unroll
        for (int kk = 0; kk < 64; kk += 16) {
            unsigned aF[4];
            ldmx4(aF, smem_u32(aP + (wm + a_row)*XPAD + k0 + kk + a_kh));
#pragma unroll
            for (int nh = 0; nh < 4; nh++) {
                const __half* pb = bH + (kk + b_kr)*BPAD + wn + nh*16 + b_nc;
                unsigned bHf[4], bLf[4];
                ldmx4t(bHf, smem_u32(pb));
                ldmx4t(bLf, smem_u32(pb + PLANE));
#pragma unroll
                for (int sub = 0; sub < 2; sub++) {
                    int nj = nh*2 + sub;
                    mma16816(acc[nj], aF, bHf[sub*2], bHf[sub*2+1]);
                    mma16816(acc[nj], aF, bLf[sub*2], bLf[sub*2+1]);
                }
            }
        }
    }
    __syncthreads();   // protect wst for next call
}

// fragment -> transposed channel-major global, split H/L fp16 planes (left)
__device__ __forceinline__ void frag_store_pack(
    const float acc[8][4], const float* __restrict__ bias,
    unsigned* __restrict__ stage,
    __half* __restrict__ dstH, __half* __restrict__ dstL,
    size_t R0, int lane, int wm, int wn, int tid)
{
    int r = wm + (lane >> 2);
#pragma unroll
    for (int nj = 0; nj < 8; nj++) {
        int c = wn + nj*8 + (lane & 3)*2;
        float b0 = __ldg(bias + c), b1 = __ldg(bias + c + 1);
        stage[c*129 + r]       = pack_splitH(acc[nj][0] + b0);
        stage[(c+1)*129 + r]   = pack_splitH(acc[nj][1] + b1);
        stage[c*129 + r+8]     = pack_splitH(acc[nj][2] + b0);
        stage[(c+1)*129 + r+8] = pack_splitH(acc[nj][3] + b1);
    }
    __syncthreads();
    for (int idx = tid; idx < 128*64; idx += T) {
        int n = idx >> 6, r2 = idx & 63;
        unsigned w0 = stage[n*129 + 2*r2], w1 = stage[n*129 + 2*r2 + 1];
        unsigned hw = (w0 >> 16) | (w1 & 0xFFFF0000u);
        unsigned lw = (w0 & 0xFFFFu) | (w1 << 16);
        size_t base = (size_t)n*MTOT + R0 + 2*r2;
        *reinterpret_cast<unsigned*>(dstH + base) = hw;
        *reinterpret_cast<unsigned*>(dstL + base) = lw;
    }
    __syncthreads();
}

// fragment -> transposed channel-major, SINGLE fp16 plane (right)
__device__ __forceinline__ void frag_store_single(
    const float acc[8][4], const float* __restrict__ bias,
    unsigned* __restrict__ stage,
    __half* __restrict__ dstH,
    size_t R0, int lane, int wm, int wn, int tid)
{
    int r = wm + (lane >> 2);
#pragma unroll
    for (int nj = 0; nj < 8; nj++) {
        int c = wn + nj*8 + (lane & 3)*2;
        float b0 = __ldg(bias + c), b1 = __ldg(bias + c + 1);
        stage[c*129 + r]       = (unsigned)__half_as_ushort(__float2half_rn(acc[nj][0] + b0));
        stage[(c+1)*129 + r]   = (unsigned)__half_as_ushort(__float2half_rn(acc[nj][1] + b1));
        stage[c*129 + r+8]     = (unsigned)__half_as_ushort(__float2half_rn(acc[nj][2] + b0));
        stage[(c+1)*129 + r+8] = (unsigned)__half_as_ushort(__float2half_rn(acc[nj][3] + b1));
    }
    __syncthreads();
    for (int idx = tid; idx < 128*64; idx += T) {
        int n = idx >> 6, r2 = idx & 63;
        unsigned w0 = stage[n*129 + 2*r2], w1 = stage[n*129 + 2*r2 + 1];
        unsigned hw = (w0 & 0xFFFFu) | (w1 << 16);
        size_t base = (size_t)n*MTOT + R0 + 2*r2;
        *reinterpret_cast<unsigned*>(dstH + base) = hw;
    }
    __syncthreads();
}

// gate: logit = sd[r]*acc + mu[r]*S[c] + bg[c]; sigmoid; fp16 channel-major
__device__ __forceinline__ void frag_store_gate(
    const float acc[8][4], const float* __restrict__ bg,
    const float* __restrict__ Sg,
    const float* __restrict__ sd_s, const float* __restrict__ mu_s,
    float* __restrict__ stage, __half* __restrict__ dst,
    size_t R0, int lane, int wm, int wn, int tid)
{
    int r = wm + (lane >> 2);
    float sd0 = sd_s[r], mu0 = mu_s[r];
    float sd1 = sd_s[r+8], mu1 = mu_s[r+8];
#pragma unroll
    for (int nj = 0; nj < 8; nj++) {
        int c = wn + nj*8 + (lane & 3)*2;
        float S0 = __ldg(Sg + c) , B0 = __ldg(bg + c);
        float S1 = __ldg(Sg + c+1), B1 = __ldg(bg + c+1);
        float z;
        z = sd0*acc[nj][0] + mu0*S0 + B0; stage[c*129 + r]       = 1.f/(1.f+expf(-z));
        z = sd0*acc[nj][1] + mu0*S1 + B1; stage[(c+1)*129 + r]   = 1.f/(1.f+expf(-z));
        z = sd1*acc[nj][2] + mu1*S0 + B0; stage[c*129 + r+8]     = 1.f/(1.f+expf(-z));
        z = sd1*acc[nj][3] + mu1*S1 + B1; stage[(c+1)*129 + r+8] = 1.f/(1.f+expf(-z));
    }
    __syncthreads();
    for (int idx = tid; idx < 128*64; idx += T) {
        int n = idx >> 6, r2 = idx & 63;
        __half h0 = __float2half_rn(stage[n*129 + 2*r2]);
        __half h1 = __float2half_rn(stage[n*129 + 2*r2 + 1]);
        unsigned hw = (unsigned)__half_as_ushort(h0) | ((unsigned)__half_as_ushort(h1) << 16);
        *reinterpret_cast<unsigned*>(dst + (size_t)n*MTOT + R0 + 2*r2) = hw;
    }
    __syncthreads();
}

// ---------------- kernel A: LN + 3 projections ---------------------------------
__global__ void __launch_bounds__(T, 1)
kernelA(const float* __restrict__ pair,
        const float* __restrict__ bg)
{
    extern __shared__ __align__(16) char smA[];
    __half* xh  = (__half*)smA;                    // [128][XPAD] single plane (34816 B)
    __half* wst = xh + 128*XPAD;                   // 2 stages x 2 planes x 64*BPAD (69632 B)
    char* stg = smA + 104448;                      // [128][129] u32/f32 stage (66048 B)
    unsigned* stageU = (unsigned*)stg;
    float*    stageF = (float*)stg;
    float* mu_s = (float*)(smA + 170496);
    float* rs_s = mu_s + 128;
    float* sd_s = rs_s + 128;

    const int tid = threadIdx.x;
    const int lane = tid & 31, wid = tid >> 5;
    const int wm = (wid & 7)*16, wn = (wid >> 3)*64;
    const int a_row = (lane & 7) + ((lane >> 3) & 1)*8;
    const int a_kh  = (lane >> 4)*8;
    const int b_kr  = (lane & 7) + ((lane >> 3) & 1)*8;
    const int b_nc  = (lane >> 4)*8;
    const size_t R0 = (size_t)blockIdx.x * 128;

    // LN stats: warp per 8 rows, coalesced global float4 read + shuffle reduce
#pragma unroll
    for (int rr = 0; rr < 8; rr++) {
        int r = wid*8 + rr;
        float4 v = *reinterpret_cast<const float4*>(pair + (R0 + r)*CC + lane*4);
        float s  = v.x + v.y + v.z + v.w;
        float s2 = v.x*v.x + v.y*v.y + v.z*v.z + v.w*v.w;
#pragma unroll
        for (int off = 16; off > 0; off >>= 1) {
            s  += __shfl_xor_sync(0xffffffffu, s,  off);
            s2 += __shfl_xor_sync(0xffffffffu, s2, off);
        }
        if (lane == 0) {
            float mu  = s * (1.f/128.f);
            float var = fmaxf(s2 * (1.f/128.f) - mu*mu, 0.f) + EPS;
            mu_s[r] = mu;
            rs_s[r] = rsqrtf(var);
            sd_s[r] = sqrtf(var);
        }
    }
    __syncthreads();

    // xhat -> single fp16 plane (pair re-read is L2-hot)
    for (int i = tid; i < 128*32; i += T) {
        int r = i >> 5, c4 = i & 31;
        float4 v = *reinterpret_cast<const float4*>(pair + (R0 + r)*CC + c4*4);
        float mu = mu_s[r], rs = rs_s[r];
        __half2 h0 = __floats2half2_rn((v.x - mu)*rs, (v.y - mu)*rs);
        __half2 h1 = __floats2half2_rn((v.z - mu)*rs, (v.w - mu)*rs);
        *reinterpret_cast<uint2*>(xh + r*XPAD + c4*4) =
            make_uint2(*(unsigned*)&h0, *(unsigned*)&h1);
    }
    // hmma_proj's internal sync (post cp_wait) orders plane writes before ldmatrix

    float acc[8][4];
    hmma_proj(xh, g_WlH, g_WlL, wst, acc, tid, wm, wn, a_row, a_kh, b_kr, b_nc);
    frag_store_pack(acc, g_bLE, stageU, g_leftH, g_leftL, R0, lane, wm, wn, tid);
    hmma_proj(xh, g_WrH, g_WrL, wst, acc, tid, wm, wn, a_row, a_kh, b_kr, b_nc);
    frag_store_single(acc, g_bRE, stageU, g_rightH, R0, lane, wm, wn, tid);
    hmma_proj(xh, g_WgH, g_WgL, wst, acc, tid, wm, wn, a_row, a_kh, b_kr, b_nc);
    frag_store_gate(acc, bg, g_WgS, sd_s, mu_s, stageF, g_gateh, R0, lane, wm, wn, tid);
}

// ---------------- kernel B: per-channel 384^3 GEMM, left split x right single --
#define KB_STG (2*128*APAD + 64*BPAD)   // fp16 elements per stage (27136)

__device__ __forceinline__ void kb_prefetch(
    __half* st,
    const __half* __restrict__ AgH, const __half* __restrict__ AgL,
    const __half* __restrict__ BgH,
    int k0, int tid)
{
    __half* aH = st;
    __half* aL = st + 128*APAD;
    __half* bH = st + 2*128*APAD;
#pragma unroll
    for (int t = 0; t < 4; t++) {
        int idx = tid + t*T;                // 0..2047
        int r = idx >> 4, rem = idx & 15;
        int pl = rem >> 3, c = rem & 7;
        const __half* src = (pl ? AgL : AgH) + (size_t)r*NN + k0 + c*8;
        __half* dst = (pl ? aL : aH) + r*APAD + c*8;
        cp16(smem_u32(dst), src);
    }
#pragma unroll
    for (int t = 0; t < 2; t++) {
        int idx = tid + t*T;                // 0..1023 (64 rows x 16 chunks)
        int r = idx >> 4, c = idx & 15;
        cp16(smem_u32(bH + r*BPAD + c*8), BgH + (size_t)(k0 + r)*NN + c*8);
    }
}

__global__ void __launch_bounds__(T, 1)
kernelB_mma()
{
    extern __shared__ __align__(16) __half smb[];
    const int tid  = threadIdx.x;
    const int lane = tid & 31, wid = tid >> 5;
    const int J0 = blockIdx.x*128, I0 = blockIdx.y*128, h = blockIdx.z;
    const int wm = (wid & 7)*16, wn = (wid >> 3)*64;

    const __half* __restrict__ AgH = g_leftH  + (size_t)h*MTOT + (size_t)I0*NN;
    const __half* __restrict__ AgL = g_leftL  + (size_t)h*MTOT + (size_t)I0*NN;
    const __half* __restrict__ BgH = g_rightH + (size_t)h*MTOT + J0;

    float acc[8][4];
#pragma unroll
    for (int nj = 0; nj < 8; nj++)
#pragma unroll
        for (int q = 0; q < 4; q++) acc[nj][q] = 0.f;

    const int a_row = (lane & 7) + ((lane >> 3) & 1)*8;
    const int a_kh  = (lane >> 4)*8;
    const int b_kr  = (lane & 7) + ((lane >> 3) & 1)*8;
    const int b_nc  = (lane >> 4)*8;

    kb_prefetch(smb, AgH, AgL, BgH, 0, tid);
    cp_commit();

    for (int ch = 0; ch < 6; ch++) {
        if (ch + 1 < 6) {
            kb_prefetch(smb + ((ch+1)&1)*KB_STG, AgH, AgL, BgH, (ch+1)*64, tid);
            cp_commit();
            cp_wait<1>();
        } else {
            cp_wait<0>();
        }
        __syncthreads();

        const __half* aH = smb + (ch&1)*KB_STG;
        const __half* bH = aH + 2*128*APAD;
#pragma unroll
        for (int kk = 0; kk < 64; kk += 16) {
            unsigned lHf[4], lLf[4];
            const __half* pa = aH + (wm + a_row)*APAD + kk + a_kh;
            ldmx4(lHf, smem_u32(pa));
            ldmx4(lLf, smem_u32(pa + 128*APAD));
#pragma unroll
            for (int nh = 0; nh < 4; nh++) {
                unsigned rHf[4];
                ldmx4t(rHf, smem_u32(bH + (kk + b_kr)*BPAD + wn + nh*16 + b_nc));
#pragma unroll
                for (int sub = 0; sub < 2; sub++) {
                    int nj = nh*2 + sub;
                    mma16816(acc[nj], lHf, rHf[sub*2], rHf[sub*2+1]);
                    mma16816(acc[nj], lLf, rHf[sub*2], rHf[sub*2+1]);
                }
            }
        }
        __syncthreads();
    }

    // epilogue: fp16 out (same addresses as R8's float2 stores, half width)
    __half* __restrict__ Od = g_outm + (size_t)h*MTOT;
    int r0 = I0 + wm + (lane >> 2);
#pragma unroll
    for (int nj = 0; nj < 8; nj++) {
        int c = J0 + wn + nj*8 + (lane & 3)*2;
        *reinterpret_cast<__half2*>(Od + (size_t)r0*NN + c) =
            __floats2half2_rn(acc[nj][0], acc[nj][1]);
        *reinterpret_cast<__half2*>(Od + (size_t)(r0+8)*NN + c) =
            __floats2half2_rn(acc[nj][2], acc[nj][3]);
    }
}

// ---------------- kernel C: gate*out @ Wo + bo + residual + LN -----------------
__global__ void __launch_bounds__(T, 1)
kernelC(const float* __restrict__ pair,
        const float* __restrict__ bo,
        const float* __restrict__ ng,
        const float* __restrict__ nb,
        float* __restrict__ out)
{
    extern __shared__ __align__(16) char smC[];
    __half* vP  = (__half*)smC;                    // [128][XPAD] single plane
    __half* wst = vP + 128*XPAD;                   // weight stages
    float* y_s  = (float*)(smC + 104448);          // [128][129]
    float* mu_s = (float*)(smC + 170496);
    float* rs_s = mu_s + 128;

    const int tid = threadIdx.x;
    const int lane = tid & 31, wid = tid >> 5;
    const int wm = (wid & 7)*16, wn = (wid >> 3)*64;
    const int a_row = (lane & 7) + ((lane >> 3) & 1)*8;
    const int a_kh  = (lane >> 4)*8;
    const int b_kr  = (lane & 7) + ((lane >> 3) & 1)*8;
    const int b_nc  = (lane >> 4)*8;
    const size_t IJ0 = (size_t)blockIdx.x * 128;

    // v = out*gate -> y_s (transposed staging), coalesced fp16 channel-major reads
    for (int i = tid; i < 128*128; i += T) {
        int h = i >> 7, r = i & 127;
        size_t g = (size_t)h * MTOT + IJ0 + r;
        y_s[r*129 + h] = __half2float(g_outm[g]) * __half2float(g_gateh[g]);
    }
    __syncthreads();
    // v -> single fp16 plane
    for (int i = tid; i < 128*64; i += T) {
        int r = i >> 6, c2 = i & 63;
        __half2 h2 = __floats2half2_rn(y_s[r*129 + 2*c2], y_s[r*129 + 2*c2 + 1]);
        *reinterpret_cast<unsigned*>(vP + r*XPAD + 2*c2) = *(unsigned*)&h2;
    }

    float acc[8][4];
    hmma_proj(vP, g_WoH, g_WoL, wst, acc, tid, wm, wn, a_row, a_kh, b_kr, b_nc);

    // y = acc + bo + pair residual -> y_s
    {
        int r = wm + (lane >> 2);
#pragma unroll
        for (int nj = 0; nj < 8; nj++) {
            int c = wn + nj*8 + (lane & 3)*2;
            float b0 = __ldg(bo + c), b1 = __ldg(bo + c + 1);
            float2 p0 = *reinterpret_cast<const float2*>(pair + (IJ0 + r)*CC + c);
            float2 p1 = *reinterpret_cast<const float2*>(pair + (IJ0 + r + 8)*CC + c);
            y_s[r*129 + c]       = acc[nj][0] + b0 + p0.x;
            y_s[r*129 + c+1]     = acc[nj][1] + b1 + p0.y;
            y_s[(r+8)*129 + c]   = acc[nj][2] + b0 + p1.x;
            y_s[(r+8)*129 + c+1] = acc[nj][3] + b1 + p1.y;
        }
    }
    __syncthreads();

    // row LN: warp per 8 rows via shuffle — SCALAR smem loads (516B row stride)
#pragma unroll
    for (int rr = 0; rr < 8; rr++) {
        int r = wid*8 + rr;
        const float* row = y_s + r*129 + lane*4;
        float v0 = row[0], v1 = row[1], v2 = row[2], v3 = row[3];
        float s  = v0 + v1 + v2 + v3;
        float s2 = v0*v0 + v1*v1 + v2*v2 + v3*v3;
#pragma unroll
        for (int off = 16; off > 0; off >>= 1) {
            s  += __shfl_xor_sync(0xffffffffu, s,  off);
            s2 += __shfl_xor_sync(0xffffffffu, s2, off);
        }
        if (lane == 0) {
            float mu  = s * (1.f/128.f);
            float var = fmaxf(s2 * (1.f/128.f) - mu*mu, 0.f) + EPS;
            mu_s[r] = mu;
            rs_s[r] = rsqrtf(var);
        }
    }
    __syncthreads();

    for (int i = tid; i < 128*128; i += T) {
        int r = i >> 7, c = i & 127;
        float z = y_s[r*129 + c];
        out[(IJ0 + r)*CC + c] = (z - mu_s[r]) * rs_s[r] * __ldg(ng + c) + __ldg(nb + c);
    }
}

// ---------------- launch --------------------------------------------------------
extern "C" void kernel_launch(void* const* d_in, const int* in_sizes, int n_in,
                              void* d_out, int out_size)
{
    const float* pair   = (const float*)d_in[0];
    const float* ln_l_g = (const float*)d_in[1];
    const float* ln_l_b = (const float*)d_in[2];
    const float* ln_r_g = (const float*)d_in[3];
    const float* ln_r_b = (const float*)d_in[4];
    const float* Wl     = (const float*)d_in[5];
    const float* bl     = (const float*)d_in[6];
    const float* Wr     = (const float*)d_in[7];
    const float* br     = (const float*)d_in[8];
    const float* Wg     = (const float*)d_in[9];
    const float* bg     = (const float*)d_in[10];
    const float* Wo     = (const float*)d_in[11];
    const float* bo     = (const float*)d_in[12];
    const float* n_g    = (const float*)d_in[13];
    const float* n_b    = (const float*)d_in[14];
    float* out = (float*)d_out;

    static __half *pWlH = nullptr, *pWlL, *pWrH, *pWrL, *pWgH, *pWgL, *pWoH, *pWoL;
    static float *pbLE, *pbRE, *pWgS;
    if (!pWlH) {
        cudaGetSymbolAddress((void**)&pWlH, g_WlH);
        cudaGetSymbolAddress((void**)&pWlL, g_WlL);
        cudaGetSymbolAddress((void**)&pWrH, g_WrH);
        cudaGetSymbolAddress((void**)&pWrL, g_WrL);
        cudaGetSymbolAddress((void**)&pWgH, g_WgH);
        cudaGetSymbolAddress((void**)&pWgL, g_WgL);
        cudaGetSymbolAddress((void**)&pWoH, g_WoH);
        cudaGetSymbolAddress((void**)&pWoL, g_WoL);
        cudaGetSymbolAddress((void**)&pbLE, g_bLE);
        cudaGetSymbolAddress((void**)&pbRE, g_bRE);
        cudaGetSymbolAddress((void**)&pWgS, g_WgS);
    }

    // smem: plane 34816 | wst 69632 | stage 66048 | stats
    const size_t smemA = 172032;
    const size_t smemC = 172032;
    const size_t smemB = (size_t)2*KB_STG*sizeof(__half);   // 108544
    cudaFuncSetAttribute(kernelA,     cudaFuncAttributeMaxDynamicSharedMemorySize, (int)smemA);
    cudaFuncSetAttribute(kernelC,     cudaFuncAttributeMaxDynamicSharedMemorySize, (int)smemC);
    cudaFuncSetAttribute(kernelB_mma, cudaFuncAttributeMaxDynamicSharedMemorySize, (int)smemB);

    prep_fold<<<CC, CC>>>(Wl, ln_l_g, ln_l_b, bl, pWlH, pWlL, pbLE);
    prep_fold<<<CC, CC>>>(Wr, ln_r_g, ln_r_b, br, pWrH, pWrL, pbRE);
    prep_pack<<<CC, CC>>>(Wg, pWgH, pWgL, pWgS);
    prep_pack<<<CC, CC>>>(Wo, pWoH, pWoL, nullptr);

    kernelA<<<MTOT/128, T, smemA>>>(pair, bg);
    kernelB_mma<<<dim3(NN/128, NN/128, CC), T, smemB>>>();
    kernelC<<<MTOT/128, T, smemC>>>(pair, bo, n_g, n_b, out);
}

// round 11
// speedup vs baseline: 1.4825x; 1.1994x over previous
#include <cuda_runtime.h>
#include <cuda_fp16.h>
#include <math.h>

// Problem constants (fixed by dataset): B=1, N=384, C=H=128
#define NN   384
#define CC   128
#define MTOT (NN*NN)
#define EPS  1e-5f
#define XPAD 136      // data plane row stride (fp16 elems)
#define BPAD 136      // weight / right row stride (fp16 elems)
#define APAD 72       // kernelB left-tile row stride (fp16 elems)
#define T    512      // threads per block (16 warps)

// ---------------- scratch ------------------------------------------------------
// All GEMM operands single fp16, fp32 accumulate (R9-calibrated: 7.2e-5).
// Epilogues/transposes keep R10's clean coalesced/staged patterns (R9's
// regression was pattern-induced, not math-induced).
__device__ __half g_leftH [(size_t)CC * MTOT];   // [h][i][k]
__device__ __half g_rightH[(size_t)CC * MTOT];   // [h][k][j]
__device__ __half g_gateh [(size_t)CC * MTOT];   // [h][i*N+j] fp16 sigmoid
__device__ __half g_outm  [(size_t)CC * MTOT];   // [h][i*N+j] fp16 einsum out
__device__ __half g_Wl[CC*CC], g_Wr[CC*CC], g_Wg[CC*CC], g_Wo[CC*CC];
__device__ float g_bLE[CC], g_bRE[CC], g_WgS[CC];

// ---------------- helpers (baseline PTX only) ----------------------------------
__device__ __forceinline__ unsigned smem_u32(const void* p) {
    return (unsigned)__cvta_generic_to_shared(p);
}
__device__ __forceinline__ void cp16(unsigned saddr, const void* g) {
    asm volatile("cp.async.cg.shared.global [%0], [%1], 16;" :: "r"(saddr), "l"(g));
}
__device__ __forceinline__ void cp_commit() {
    asm volatile("cp.async.commit_group;" ::: "memory");
}
template<int N>
__device__ __forceinline__ void cp_wait() {
    asm volatile("cp.async.wait_group %0;" :: "n"(N) : "memory");
}
__device__ __forceinline__ void ldmx4(unsigned r[4], unsigned addr) {
    asm volatile("ldmatrix.sync.aligned.m8n8.x4.shared.b16 {%0,%1,%2,%3}, [%4];"
        : "=r"(r[0]), "=r"(r[1]), "=r"(r[2]), "=r"(r[3]) : "r"(addr));
}
__device__ __forceinline__ void ldmx4t(unsigned r[4], unsigned addr) {
    asm volatile("ldmatrix.sync.aligned.m8n8.x4.trans.shared.b16 {%0,%1,%2,%3}, [%4];"
        : "=r"(r[0]), "=r"(r[1]), "=r"(r[2]), "=r"(r[3]) : "r"(addr));
}
__device__ __forceinline__ void mma16816(float d[4], const unsigned a[4],
                                         unsigned b0, unsigned b1) {
    asm volatile(
        "mma.sync.aligned.m16n8k16.row.col.f32.f16.f16.f32 "
        "{%0,%1,%2,%3}, {%4,%5,%6,%7}, {%8,%9}, {%0,%1,%2,%3};"
        : "+f"(d[0]), "+f"(d[1]), "+f"(d[2]), "+f"(d[3])
        : "r"(a[0]), "r"(a[1]), "r"(a[2]), "r"(a[3]), "r"(b0), "r"(b1));
}

// ---------------- prep kernels --------------------------------------------------
__global__ void prep_fold(const float* __restrict__ W,
                          const float* __restrict__ g,
                          const float* __restrict__ beta,
                          const float* __restrict__ b,
                          __half* __restrict__ WH,
                          float* __restrict__ bE)
{
    int k = blockIdx.x, n = threadIdx.x;
    WH[k*CC + n] = __float2half_rn(g[k] * W[k*CC + n]);
    if (k == 0) {
        float s = b[n];
        for (int kk = 0; kk < CC; kk++) s += beta[kk] * W[kk*CC + n];
        bE[n] = s;
    }
}
__global__ void prep_pack(const float* __restrict__ W,
                          __half* __restrict__ WH,
                          float* __restrict__ S)
{
    int k = blockIdx.x, n = threadIdx.x;
    WH[k*CC + n] = __float2half_rn(W[k*CC + n]);
    if (k == 0 && S) {
        float s = 0.f;
        for (int kk = 0; kk < CC; kk++) s += W[kk*CC + n];
        S[n] = s;
    }
}

// ---------------- HMMA projection GEMM: single x single, 1 MMA -----------------
__device__ __forceinline__ void hmma_proj(
    const __half* __restrict__ aP,
    const __half* __restrict__ W,
    __half* __restrict__ wst,
    float acc[8][4],
    int tid, int wm, int wn,
    int a_row, int a_kh, int b_kr, int b_nc)
{
    const int PLANE = 64*BPAD;
#pragma unroll
    for (int nj = 0; nj < 8; nj++)
#pragma unroll
        for (int q = 0; q < 4; q++) acc[nj][q] = 0.f;

#pragma unroll
    for (int s = 0; s < 2; s++) {
        __half* d = wst + s*PLANE;
        int k0 = s*64;
#pragma unroll
        for (int t = 0; t < 2; t++) {
            int idx = tid + t*T;            // 0..1023 (64 rows x 16 chunks)
            int r = idx >> 4, c = idx & 15;
            cp16(smem_u32(d + r*BPAD + c*8), W + (k0 + r)*CC + c*8);
        }
        cp_commit();
    }

#pragma unroll
    for (int s = 0; s < 2; s++) {
        if (s == 0) cp_wait<1>(); else cp_wait<0>();
        __syncthreads();
        const __half* bP = wst + s*PLANE;
        int k0 = s*64;
#pragma unroll
        for (int kk = 0; kk < 64; kk += 16) {
            unsigned aF[4];
            ldmx4(aF, smem_u32(aP + (wm + a_row)*XPAD + k0 + kk + a_kh));
#pragma unroll
            for (int nh = 0; nh < 4; nh++) {
                unsigned bF[4];
                ldmx4t(bF, smem_u32(bP + (kk + b_kr)*BPAD + wn + nh*16 + b_nc));
                mma16816(acc[nh*2 + 0], aF, bF[0], bF[1]);
                mma16816(acc[nh*2 + 1], aF, bF[2], bF[3]);
            }
        }
    }
    __syncthreads();   // protect wst for next call
}

// fragment -> transposed channel-major, single fp16 plane (staged, coalesced)
__device__ __forceinline__ void frag_store_half(
    const float acc[8][4], const float* __restrict__ bias,
    unsigned* __restrict__ stage,
    __half* __restrict__ dstH,
    size_t R0, int lane, int wm, int wn, int tid)
{
    int r = wm + (lane >> 2);
#pragma unroll
    for (int nj = 0; nj < 8; nj++) {
        int c = wn + nj*8 + (lane & 3)*2;
        float b0 = __ldg(bias + c), b1 = __ldg(bias + c + 1);
        stage[c*129 + r]       = (unsigned)__half_as_ushort(__float2half_rn(acc[nj][0] + b0));
        stage[(c+1)*129 + r]   = (unsigned)__half_as_ushort(__float2half_rn(acc[nj][1] + b1));
        stage[c*129 + r+8]     = (unsigned)__half_as_ushort(__float2half_rn(acc[nj][2] + b0));
        stage[(c+1)*129 + r+8] = (unsigned)__half_as_ushort(__float2half_rn(acc[nj][3] + b1));
    }
    __syncthreads();
    for (int idx = tid; idx < 128*64; idx += T) {
        int n = idx >> 6, r2 = idx & 63;
        unsigned w0 = stage[n*129 + 2*r2], w1 = stage[n*129 + 2*r2 + 1];
        unsigned hw = (w0 & 0xFFFFu) | (w1 << 16);
        *reinterpret_cast<unsigned*>(dstH + (size_t)n*MTOT + R0 + 2*r2) = hw;
    }
    __syncthreads();
}

// gate: logit = sd[r]*acc + mu[r]*S[c] + bg[c]; sigmoid; fp16 channel-major
__device__ __forceinline__ void frag_store_gate(
    const float acc[8][4], const float* __restrict__ bg,
    const float* __restrict__ Sg,
    const float* __restrict__ sd_s, const float* __restrict__ mu_s,
    float* __restrict__ stage, __half* __restrict__ dst,
    size_t R0, int lane, int wm, int wn, int tid)
{
    int r = wm + (lane >> 2);
    float sd0 = sd_s[r], mu0 = mu_s[r];
    float sd1 = sd_s[r+8], mu1 = mu_s[r+8];
#pragma unroll
    for (int nj = 0; nj < 8; nj++) {
        int c = wn + nj*8 + (lane & 3)*2;
        float S0 = __ldg(Sg + c) , B0 = __ldg(bg + c);
        float S1 = __ldg(Sg + c+1), B1 = __ldg(bg + c+1);
        float z;
        z = sd0*acc[nj][0] + mu0*S0 + B0; stage[c*129 + r]       = 1.f/(1.f+expf(-z));
        z = sd0*acc[nj][1] + mu0*S1 + B1; stage[(c+1)*129 + r]   = 1.f/(1.f+expf(-z));
        z = sd1*acc[nj][2] + mu1*S0 + B0; stage[c*129 + r+8]     = 1.f/(1.f+expf(-z));
        z = sd1*acc[nj][3] + mu1*S1 + B1; stage[(c+1)*129 + r+8] = 1.f/(1.f+expf(-z));
    }
    __syncthreads();
    for (int idx = tid; idx < 128*64; idx += T) {
        int n = idx >> 6, r2 = idx & 63;
        __half h0 = __float2half_rn(stage[n*129 + 2*r2]);
        __half h1 = __float2half_rn(stage[n*129 + 2*r2 + 1]);
        unsigned hw = (unsigned)__half_as_ushort(h0) | ((unsigned)__half_as_ushort(h1) << 16);
        *reinterpret_cast<unsigned*>(dst + (size_t)n*MTOT + R0 + 2*r2) = hw;
    }
    __syncthreads();
}

// ---------------- kernel A: LN + 3 projections ---------------------------------
__global__ void __launch_bounds__(T, 1)
kernelA(const float* __restrict__ pair,
        const float* __restrict__ bg)
{
    extern __shared__ __align__(16) char smA[];
    __half* xh  = (__half*)smA;                    // [128][XPAD]            (34816 B)
    __half* wst = xh + 128*XPAD;                   // 2 stages x 64*BPAD     (34816 B)
    char* stg = smA + 69632;                       // [128][129] stage       (66048 B)
    unsigned* stageU = (unsigned*)stg;
    float*    stageF = (float*)stg;
    float* mu_s = (float*)(smA + 135680);
    float* rs_s = mu_s + 128;
    float* sd_s = rs_s + 128;

    const int tid = threadIdx.x;
    const int lane = tid & 31, wid = tid >> 5;
    const int wm = (wid & 7)*16, wn = (wid >> 3)*64;
    const int a_row = (lane & 7) + ((lane >> 3) & 1)*8;
    const int a_kh  = (lane >> 4)*8;
    const int b_kr  = (lane & 7) + ((lane >> 3) & 1)*8;
    const int b_nc  = (lane >> 4)*8;
    const size_t R0 = (size_t)blockIdx.x * 128;

    // LN stats: warp per 8 rows, coalesced global float4 read + shuffle reduce
#pragma unroll
    for (int rr = 0; rr < 8; rr++) {
        int r = wid*8 + rr;
        float4 v = *reinterpret_cast<const float4*>(pair + (R0 + r)*CC + lane*4);
        float s  = v.x + v.y + v.z + v.w;
        float s2 = v.x*v.x + v.y*v.y + v.z*v.z + v.w*v.w;
#pragma unroll
        for (int off = 16; off > 0; off >>= 1) {
            s  += __shfl_xor_sync(0xffffffffu, s,  off);
            s2 += __shfl_xor_sync(0xffffffffu, s2, off);
        }
        if (lane == 0) {
            float mu  = s * (1.f/128.f);
            float var = fmaxf(s2 * (1.f/128.f) - mu*mu, 0.f) + EPS;
            mu_s[r] = mu;
            rs_s[r] = rsqrtf(var);
            sd_s[r] = sqrtf(var);
        }
    }
    __syncthreads();

    // xhat -> single fp16 plane (pair re-read is L2-hot)
    for (int i = tid; i < 128*32; i += T) {
        int r = i >> 5, c4 = i & 31;
        float4 v = *reinterpret_cast<const float4*>(pair + (R0 + r)*CC + c4*4);
        float mu = mu_s[r], rs = rs_s[r];
        __half2 h0 = __floats2half2_rn((v.x - mu)*rs, (v.y - mu)*rs);
        __half2 h1 = __floats2half2_rn((v.z - mu)*rs, (v.w - mu)*rs);
        *reinterpret_cast<uint2*>(xh + r*XPAD + c4*4) =
            make_uint2(*(unsigned*)&h0, *(unsigned*)&h1);
    }
    // hmma_proj's internal sync (post cp_wait) orders plane writes before ldmatrix

    float acc[8][4];
    hmma_proj(xh, g_Wl, wst, acc, tid, wm, wn, a_row, a_kh, b_kr, b_nc);
    frag_store_half(acc, g_bLE, stageU, g_leftH, R0, lane, wm, wn, tid);
    hmma_proj(xh, g_Wr, wst, acc, tid, wm, wn, a_row, a_kh, b_kr, b_nc);
    frag_store_half(acc, g_bRE, stageU, g_rightH, R0, lane, wm, wn, tid);
    hmma_proj(xh, g_Wg, wst, acc, tid, wm, wn, a_row, a_kh, b_kr, b_nc);
    frag_store_gate(acc, bg, g_WgS, sd_s, mu_s, stageF, g_gateh, R0, lane, wm, wn, tid);
}

// ---------------- kernel B: per-channel 384^3 GEMM, single x single ------------
#define KB_STG (128*APAD + 64*BPAD)   // fp16 elements per stage (17920)

__device__ __forceinline__ void kb_prefetch(
    __half* st,
    const __half* __restrict__ AgH,
    const __half* __restrict__ BgH,
    int k0, int tid)
{
    __half* aH = st;
    __half* bH = st + 128*APAD;
#pragma unroll
    for (int t = 0; t < 2; t++) {
        int idx = tid + t*T;                // 0..1023 (128 rows x 8 chunks)
        int r = idx >> 3, c = idx & 7;
        cp16(smem_u32(aH + r*APAD + c*8), AgH + (size_t)r*NN + k0 + c*8);
    }
#pragma unroll
    for (int t = 0; t < 2; t++) {
        int idx = tid + t*T;                // 0..1023 (64 rows x 16 chunks)
        int r = idx >> 4, c = idx & 15;
        cp16(smem_u32(bH + r*BPAD + c*8), BgH + (size_t)(k0 + r)*NN + c*8);
    }
}

__global__ void __launch_bounds__(T, 1)
kernelB_mma()
{
    extern __shared__ __align__(16) __half smb[];
    const int tid  = threadIdx.x;
    const int lane = tid & 31, wid = tid >> 5;
    const int J0 = blockIdx.x*128, I0 = blockIdx.y*128, h = blockIdx.z;
    const int wm = (wid & 7)*16, wn = (wid >> 3)*64;

    const __half* __restrict__ AgH = g_leftH  + (size_t)h*MTOT + (size_t)I0*NN;
    const __half* __restrict__ BgH = g_rightH + (size_t)h*MTOT + J0;

    float acc[8][4];
#pragma unroll
    for (int nj = 0; nj < 8; nj++)
#pragma unroll
        for (int q = 0; q < 4; q++) acc[nj][q] = 0.f;

    const int a_row = (lane & 7) + ((lane >> 3) & 1)*8;
    const int a_kh  = (lane >> 4)*8;
    const int b_kr  = (lane & 7) + ((lane >> 3) & 1)*8;
    const int b_nc  = (lane >> 4)*8;

    kb_prefetch(smb, AgH, BgH, 0, tid);
    cp_commit();

    for (int ch = 0; ch < 6; ch++) {
        if (ch + 1 < 6) {
            kb_prefetch(smb + ((ch+1)&1)*KB_STG, AgH, BgH, (ch+1)*64, tid);
            cp_commit();
            cp_wait<1>();
        } else {
            cp_wait<0>();
        }
        __syncthreads();

        const __half* aH = smb + (ch&1)*KB_STG;
        const __half* bH = aH + 128*APAD;
#pragma unroll
        for (int kk = 0; kk < 64; kk += 16) {
            unsigned aF[4];
            ldmx4(aF, smem_u32(aH + (wm + a_row)*APAD + kk + a_kh));
#pragma unroll
            for (int nh = 0; nh < 4; nh++) {
                unsigned bF[4];
                ldmx4t(bF, smem_u32(bH + (kk + b_kr)*BPAD + wn + nh*16 + b_nc));
                mma16816(acc[nh*2 + 0], aF, bF[0], bF[1]);
                mma16816(acc[nh*2 + 1], aF, bF[2], bF[3]);
            }
        }
        __syncthreads();
    }

    // epilogue: fp16 out, coalesced __half2 stores (R10 pattern — known good)
    __half* __restrict__ Od = g_outm + (size_t)h*MTOT;
    int r0 = I0 + wm + (lane >> 2);
#pragma unroll
    for (int nj = 0; nj < 8; nj++) {
        int c = J0 + wn + nj*8 + (lane & 3)*2;
        *reinterpret_cast<__half2*>(Od + (size_t)r0*NN + c) =
            __floats2half2_rn(acc[nj][0], acc[nj][1]);
        *reinterpret_cast<__half2*>(Od + (size_t)(r0+8)*NN + c) =
            __floats2half2_rn(acc[nj][2], acc[nj][3]);
    }
}

// ---------------- kernel C: gate*out @ Wo + bo + residual + LN -----------------
__global__ void __launch_bounds__(T, 1)
kernelC(const float* __restrict__ pair,
        const float* __restrict__ bo,
        const float* __restrict__ ng,
        const float* __restrict__ nb,
        float* __restrict__ out)
{
    extern __shared__ __align__(16) char smC[];
    __half* vP  = (__half*)smC;                    // [128][XPAD]
    __half* wst = vP + 128*XPAD;                   // 2 stages x 64*BPAD
    float* y_s  = (float*)(smC + 69632);           // [128][129]
    float* mu_s = (float*)(smC + 135680);
    float* rs_s = mu_s + 128;

    const int tid = threadIdx.x;
    const int lane = tid & 31, wid = tid >> 5;
    const int wm = (wid & 7)*16, wn = (wid >> 3)*64;
    const int a_row = (lane & 7) + ((lane >> 3) & 1)*8;
    const int a_kh  = (lane >> 4)*8;
    const int b_kr  = (lane & 7) + ((lane >> 3) & 1)*8;
    const int b_nc  = (lane >> 4)*8;
    const size_t IJ0 = (size_t)blockIdx.x * 128;

    // v = out*gate -> y_s (transposed staging), coalesced fp16 channel-major reads
    for (int i = tid; i < 128*128; i += T) {
        int h = i >> 7, r = i & 127;
        size_t g = (size_t)h * MTOT + IJ0 + r;
        y_s[r*129 + h] = __half2float(g_outm[g]) * __half2float(g_gateh[g]);
    }
    __syncthreads();
    // v -> single fp16 plane
    for (int i = tid; i < 128*64; i += T) {
        int r = i >> 6, c2 = i & 63;
        __half2 h2 = __floats2half2_rn(y_s[r*129 + 2*c2], y_s[r*129 + 2*c2 + 1]);
        *reinterpret_cast<unsigned*>(vP + r*XPAD + 2*c2) = *(unsigned*)&h2;
    }

    float acc[8][4];
    hmma_proj(vP, g_Wo, wst, acc, tid, wm, wn, a_row, a_kh, b_kr, b_nc);

    // y = acc + bo + pair residual -> y_s
    {
        int r = wm + (lane >> 2);
#pragma unroll
        for (int nj = 0; nj < 8; nj++) {
            int c = wn + nj*8 + (lane & 3)*2;
            float b0 = __ldg(bo + c), b1 = __ldg(bo + c + 1);
            float2 p0 = *reinterpret_cast<const float2*>(pair + (IJ0 + r)*CC + c);
            float2 p1 = *reinterpret_cast<const float2*>(pair + (IJ0 + r + 8)*CC + c);
            y_s[r*129 + c]       = acc[nj][0] + b0 + p0.x;
            y_s[r*129 + c+1]     = acc[nj][1] + b1 + p0.y;
            y_s[(r+8)*129 + c]   = acc[nj][2] + b0 + p1.x;
            y_s[(r+8)*129 + c+1] = acc[nj][3] + b1 + p1.y;
        }
    }
    __syncthreads();

    // row LN: warp per 8 rows via shuffle — SCALAR smem loads (516B row stride)
#pragma unroll
    for (int rr = 0; rr < 8; rr++) {
        int r = wid*8 + rr;
        const float* row = y_s + r*129 + lane*4;
        float v0 = row[0], v1 = row[1], v2 = row[2], v3 = row[3];
        float s  = v0 + v1 + v2 + v3;
        float s2 = v0*v0 + v1*v1 + v2*v2 + v3*v3;
#pragma unroll
        for (int off = 16; off > 0; off >>= 1) {
            s  += __shfl_xor_sync(0xffffffffu, s,  off);
            s2 += __shfl_xor_sync(0xffffffffu, s2, off);
        }
        if (lane == 0) {
            float mu  = s * (1.f/128.f);
            float var = fmaxf(s2 * (1.f/128.f) - mu*mu, 0.f) + EPS;
            mu_s[r] = mu;
            rs_s[r] = rsqrtf(var);
        }
    }
    __syncthreads();

    for (int i = tid; i < 128*128; i += T) {
        int r = i >> 7, c = i & 127;
        float z = y_s[r*129 + c];
        out[(IJ0 + r)*CC + c] = (z - mu_s[r]) * rs_s[r] * __ldg(ng + c) + __ldg(nb + c);
    }
}

// ---------------- launch --------------------------------------------------------
extern "C" void kernel_launch(void* const* d_in, const int* in_sizes, int n_in,
                              void* d_out, int out_size)
{
    const float* pair   = (const float*)d_in[0];
    const float* ln_l_g = (const float*)d_in[1];
    const float* ln_l_b = (const float*)d_in[2];
    const float* ln_r_g = (const float*)d_in[3];
    const float* ln_r_b = (const float*)d_in[4];
    const float* Wl     = (const float*)d_in[5];
    const float* bl     = (const float*)d_in[6];
    const float* Wr     = (const float*)d_in[7];
    const float* br     = (const float*)d_in[8];
    const float* Wg     = (const float*)d_in[9];
    const float* bg     = (const float*)d_in[10];
    const float* Wo     = (const float*)d_in[11];
    const float* bo     = (const float*)d_in[12];
    const float* n_g    = (const float*)d_in[13];
    const float* n_b    = (const float*)d_in[14];
    float* out = (float*)d_out;

    static __half *pWl = nullptr, *pWr, *pWg, *pWo;
    static float *pbLE, *pbRE, *pWgS;
    if (!pWl) {
        cudaGetSymbolAddress((void**)&pWl, g_Wl);
        cudaGetSymbolAddress((void**)&pWr, g_Wr);
        cudaGetSymbolAddress((void**)&pWg, g_Wg);
        cudaGetSymbolAddress((void**)&pWo, g_Wo);
        cudaGetSymbolAddress((void**)&pbLE, g_bLE);
        cudaGetSymbolAddress((void**)&pbRE, g_bRE);
        cudaGetSymbolAddress((void**)&pWgS, g_WgS);
    }

    // smem: plane 34816 | wst 34816 | stage 66048 | stats
    const size_t smemA = 137728;
    const size_t smemC = 137728;
    const size_t smemB = (size_t)2*KB_STG*sizeof(__half);   // 71680
    cudaFuncSetAttribute(kernelA,     cudaFuncAttributeMaxDynamicSharedMemorySize, (int)smemA);
    cudaFuncSetAttribute(kernelC,     cudaFuncAttributeMaxDynamicSharedMemorySize, (int)smemC);
    cudaFuncSetAttribute(kernelB_mma, cudaFuncAttributeMaxDynamicSharedMemorySize, (int)smemB);

    prep_fold<<<CC, CC>>>(Wl, ln_l_g, ln_l_b, bl, pWl, pbLE);
    prep_fold<<<CC, CC>>>(Wr, ln_r_g, ln_r_b, br, pWr, pbRE);
    prep_pack<<<CC, CC>>>(Wg, pWg, pWgS);
    prep_pack<<<CC, CC>>>(Wo, pWo, nullptr);

    kernelA<<<MTOT/128, T, smemA>>>(pair, bg);
    kernelB_mma<<<dim3(NN/128, NN/128, CC), T, smemB>>>();
    kernelC<<<MTOT/128, T, smemC>>>(pair, bo, n_g, n_b, out);
}

// round 12
// speedup vs baseline: 1.8937x; 1.2774x over previous
#include <cuda_runtime.h>
#include <cuda_fp16.h>
#include <math.h>

// Problem constants (fixed by dataset): B=1, N=384, C=H=128
#define NN   384
#define CC   128
#define MTOT (NN*NN)
#define EPS  1e-5f
#define XPAD 136      // data plane row stride (fp16 elems)
#define BPAD 136      // weight / right row stride (fp16 elems)
#define APAD 72       // kernelB left-tile row stride (fp16 elems)
#define T    512      // threads per block (16 warps)

// ---------------- scratch ------------------------------------------------------
// All GEMM operands single fp16, fp32 accumulate (R9/R11-calibrated ~7.6e-5).
// R12: gate fused into kernelB epilogue (v = out*gate), outm eliminated.
__device__ __half g_leftH [(size_t)CC * MTOT];   // [h][i][k]
__device__ __half g_rightH[(size_t)CC * MTOT];   // [h][k][j]
__device__ __half g_gateh [(size_t)CC * MTOT];   // [h][i*N+j] fp16 sigmoid
__device__ __half g_v     [(size_t)CC * MTOT];   // [h][i*N+j] fp16 out*gate
__device__ __half g_Wl[CC*CC], g_Wr[CC*CC], g_Wg[CC*CC], g_Wo[CC*CC];
__device__ float g_bLE[CC], g_bRE[CC], g_WgS[CC];

// ---------------- helpers (baseline PTX only) ----------------------------------
__device__ __forceinline__ unsigned smem_u32(const void* p) {
    return (unsigned)__cvta_generic_to_shared(p);
}
__device__ __forceinline__ void cp16(unsigned saddr, const void* g) {
    asm volatile("cp.async.cg.shared.global [%0], [%1], 16;" :: "r"(saddr), "l"(g));
}
__device__ __forceinline__ void cp_commit() {
    asm volatile("cp.async.commit_group;" ::: "memory");
}
template<int N>
__device__ __forceinline__ void cp_wait() {
    asm volatile("cp.async.wait_group %0;" :: "n"(N) : "memory");
}
__device__ __forceinline__ void ldmx4(unsigned r[4], unsigned addr) {
    asm volatile("ldmatrix.sync.aligned.m8n8.x4.shared.b16 {%0,%1,%2,%3}, [%4];"
        : "=r"(r[0]), "=r"(r[1]), "=r"(r[2]), "=r"(r[3]) : "r"(addr));
}
__device__ __forceinline__ void ldmx4t(unsigned r[4], unsigned addr) {
    asm volatile("ldmatrix.sync.aligned.m8n8.x4.trans.shared.b16 {%0,%1,%2,%3}, [%4];"
        : "=r"(r[0]), "=r"(r[1]), "=r"(r[2]), "=r"(r[3]) : "r"(addr));
}
__device__ __forceinline__ void mma16816(float d[4], const unsigned a[4],
                                         unsigned b0, unsigned b1) {
    asm volatile(
        "mma.sync.aligned.m16n8k16.row.col.f32.f16.f16.f32 "
        "{%0,%1,%2,%3}, {%4,%5,%6,%7}, {%8,%9}, {%0,%1,%2,%3};"
        : "+f"(d[0]), "+f"(d[1]), "+f"(d[2]), "+f"(d[3])
        : "r"(a[0]), "r"(a[1]), "r"(a[2]), "r"(a[3]), "r"(b0), "r"(b1));
}

// ---------------- prep kernels --------------------------------------------------
__global__ void prep_fold(const float* __restrict__ W,
                          const float* __restrict__ g,
                          const float* __restrict__ beta,
                          const float* __restrict__ b,
                          __half* __restrict__ WH,
                          float* __restrict__ bE)
{
    int k = blockIdx.x, n = threadIdx.x;
    WH[k*CC + n] = __float2half_rn(g[k] * W[k*CC + n]);
    if (k == 0) {
        float s = b[n];
        for (int kk = 0; kk < CC; kk++) s += beta[kk] * W[kk*CC + n];
        bE[n] = s;
    }
}
__global__ void prep_pack(const float* __restrict__ W,
                          __half* __restrict__ WH,
                          float* __restrict__ S)
{
    int k = blockIdx.x, n = threadIdx.x;
    WH[k*CC + n] = __float2half_rn(W[k*CC + n]);
    if (k == 0 && S) {
        float s = 0.f;
        for (int kk = 0; kk < CC; kk++) s += W[kk*CC + n];
        S[n] = s;
    }
}

// ---------------- HMMA projection GEMM: single x single, 1 MMA -----------------
// wst lifetime is strictly inside this function (prefetch at entry, last read
// before the trailing __syncthreads) -> callers may alias wst with buffers that
// are only live outside.
__device__ __forceinline__ void hmma_proj(
    const __half* __restrict__ aP,
    const __half* __restrict__ W,
    __half* __restrict__ wst,
    float acc[8][4],
    int tid, int wm, int wn,
    int a_row, int a_kh, int b_kr, int b_nc)
{
    const int PLANE = 64*BPAD;
#pragma unroll
    for (int nj = 0; nj < 8; nj++)
#pragma unroll
        for (int q = 0; q < 4; q++) acc[nj][q] = 0.f;

#pragma unroll
    for (int s = 0; s < 2; s++) {
        __half* d = wst + s*PLANE;
        int k0 = s*64;
#pragma unroll
        for (int t = 0; t < 2; t++) {
            int idx = tid + t*T;            // 0..1023 (64 rows x 16 chunks)
            int r = idx >> 4, c = idx & 15;
            cp16(smem_u32(d + r*BPAD + c*8), W + (k0 + r)*CC + c*8);
        }
        cp_commit();
    }

#pragma unroll
    for (int s = 0; s < 2; s++) {
        if (s == 0) cp_wait<1>(); else cp_wait<0>();
        __syncthreads();
        const __half* bP = wst + s*PLANE;
        int k0 = s*64;
#pragma unroll
        for (int kk = 0; kk < 64; kk += 16) {
            unsigned aF[4];
            ldmx4(aF, smem_u32(aP + (wm + a_row)*XPAD + k0 + kk + a_kh));
#pragma unroll
            for (int nh = 0; nh < 4; nh++) {
                unsigned bF[4];
                ldmx4t(bF, smem_u32(bP + (kk + b_kr)*BPAD + wn + nh*16 + b_nc));
                mma16816(acc[nh*2 + 0], aF, bF[0], bF[1]);
                mma16816(acc[nh*2 + 1], aF, bF[2], bF[3]);
            }
        }
    }
    __syncthreads();   // all wst reads done before caller reuses the region
}

// fragment -> transposed channel-major, single fp16 plane (staged, coalesced)
__device__ __forceinline__ void frag_store_half(
    const float acc[8][4], const float* __restrict__ bias,
    unsigned* __restrict__ stage,
    __half* __restrict__ dstH,
    size_t R0, int lane, int wm, int wn, int tid)
{
    int r = wm + (lane >> 2);
#pragma unroll
    for (int nj = 0; nj < 8; nj++) {
        int c = wn + nj*8 + (lane & 3)*2;
        float b0 = __ldg(bias + c), b1 = __ldg(bias + c + 1);
        stage[c*129 + r]       = (unsigned)__half_as_ushort(__float2half_rn(acc[nj][0] + b0));
        stage[(c+1)*129 + r]   = (unsigned)__half_as_ushort(__float2half_rn(acc[nj][1] + b1));
        stage[c*129 + r+8]     = (unsigned)__half_as_ushort(__float2half_rn(acc[nj][2] + b0));
        stage[(c+1)*129 + r+8] = (unsigned)__half_as_ushort(__float2half_rn(acc[nj][3] + b1));
    }
    __syncthreads();
    for (int idx = tid; idx < 128*64; idx += T) {
        int n = idx >> 6, r2 = idx & 63;
        unsigned w0 = stage[n*129 + 2*r2], w1 = stage[n*129 + 2*r2 + 1];
        unsigned hw = (w0 & 0xFFFFu) | (w1 << 16);
        *reinterpret_cast<unsigned*>(dstH + (size_t)n*MTOT + R0 + 2*r2) = hw;
    }
    __syncthreads();
}

// gate: logit = sd[r]*acc + mu[r]*S[c] + bg[c]; sigmoid; fp16 channel-major
__device__ __forceinline__ void frag_store_gate(
    const float acc[8][4], const float* __restrict__ bg,
    const float* __restrict__ Sg,
    const float* __restrict__ sd_s, const float* __restrict__ mu_s,
    float* __restrict__ stage, __half* __restrict__ dst,
    size_t R0, int lane, int wm, int wn, int tid)
{
    int r = wm + (lane >> 2);
    float sd0 = sd_s[r], mu0 = mu_s[r];
    float sd1 = sd_s[r+8], mu1 = mu_s[r+8];
#pragma unroll
    for (int nj = 0; nj < 8; nj++) {
        int c = wn + nj*8 + (lane & 3)*2;
        float S0 = __ldg(Sg + c) , B0 = __ldg(bg + c);
        float S1 = __ldg(Sg + c+1), B1 = __ldg(bg + c+1);
        float z;
        z = sd0*acc[nj][0] + mu0*S0 + B0; stage[c*129 + r]       = 1.f/(1.f+expf(-z));
        z = sd0*acc[nj][1] + mu0*S1 + B1; stage[(c+1)*129 + r]   = 1.f/(1.f+expf(-z));
        z = sd1*acc[nj][2] + mu1*S0 + B0; stage[c*129 + r+8]     = 1.f/(1.f+expf(-z));
        z = sd1*acc[nj][3] + mu1*S1 + B1; stage[(c+1)*129 + r+8] = 1.f/(1.f+expf(-z));
    }
    __syncthreads();
    for (int idx = tid; idx < 128*64; idx += T) {
        int n = idx >> 6, r2 = idx & 63;
        __half h0 = __float2half_rn(stage[n*129 + 2*r2]);
        __half h1 = __float2half_rn(stage[n*129 + 2*r2 + 1]);
        unsigned hw = (unsigned)__half_as_ushort(h0) | ((unsigned)__half_as_ushort(h1) << 16);
        *reinterpret_cast<unsigned*>(dst + (size_t)n*MTOT + R0 + 2*r2) = hw;
    }
    __syncthreads();
}

// ---------------- kernel A: LN + 3 projections ---------------------------------
// smem (102400 B, 2 CTAs/SM): xh 34816 | stage 66048 (wst aliases first 34816) | stats
__global__ void __launch_bounds__(T, 2)
kernelA(const float* __restrict__ pair,
        const float* __restrict__ bg)
{
    extern __shared__ __align__(16) char smA[];
    __half* xh  = (__half*)smA;                    // [128][XPAD]
    char* stg = smA + 34816;                       // stage region (66048 B)
    __half* wst = (__half*)stg;                    // aliases stage (wst dead outside hmma_proj)
    unsigned* stageU = (unsigned*)stg;
    float*    stageF = (float*)stg;
    float* mu_s = (float*)(smA + 100864);
    float* rs_s = mu_s + 128;
    float* sd_s = rs_s + 128;

    const int tid = threadIdx.x;
    const int lane = tid & 31, wid = tid >> 5;
    const int wm = (wid & 7)*16, wn = (wid >> 3)*64;
    const int a_row = (lane & 7) + ((lane >> 3) & 1)*8;
    const int a_kh  = (lane >> 4)*8;
    const int b_kr  = (lane & 7) + ((lane >> 3) & 1)*8;
    const int b_nc  = (lane >> 4)*8;
    const size_t R0 = (size_t)blockIdx.x * 128;

    // LN stats: warp per 8 rows, coalesced global float4 read + shuffle reduce
#pragma unroll
    for (int rr = 0; rr < 8; rr++) {
        int r = wid*8 + rr;
        float4 v = *reinterpret_cast<const float4*>(pair + (R0 + r)*CC + lane*4);
        float s  = v.x + v.y + v.z + v.w;
        float s2 = v.x*v.x + v.y*v.y + v.z*v.z + v.w*v.w;
#pragma unroll
        for (int off = 16; off > 0; off >>= 1) {
            s  += __shfl_xor_sync(0xffffffffu, s,  off);
            s2 += __shfl_xor_sync(0xffffffffu, s2, off);
        }
        if (lane == 0) {
            float mu  = s * (1.f/128.f);
            float var = fmaxf(s2 * (1.f/128.f) - mu*mu, 0.f) + EPS;
            mu_s[r] = mu;
            rs_s[r] = rsqrtf(var);
            sd_s[r] = sqrtf(var);
        }
    }
    __syncthreads();

    // xhat -> single fp16 plane (pair re-read is L2-hot)
    for (int i = tid; i < 128*32; i += T) {
        int r = i >> 5, c4 = i & 31;
        float4 v = *reinterpret_cast<const float4*>(pair + (R0 + r)*CC + c4*4);
        float mu = mu_s[r], rs = rs_s[r];
        __half2 h0 = __floats2half2_rn((v.x - mu)*rs, (v.y - mu)*rs);
        __half2 h1 = __floats2half2_rn((v.z - mu)*rs, (v.w - mu)*rs);
        *reinterpret_cast<uint2*>(xh + r*XPAD + c4*4) =
            make_uint2(*(unsigned*)&h0, *(unsigned*)&h1);
    }
    // hmma_proj's internal sync (post cp_wait) orders plane writes before ldmatrix

    float acc[8][4];
    hmma_proj(xh, g_Wl, wst, acc, tid, wm, wn, a_row, a_kh, b_kr, b_nc);
    frag_store_half(acc, g_bLE, stageU, g_leftH, R0, lane, wm, wn, tid);
    hmma_proj(xh, g_Wr, wst, acc, tid, wm, wn, a_row, a_kh, b_kr, b_nc);
    frag_store_half(acc, g_bRE, stageU, g_rightH, R0, lane, wm, wn, tid);
    hmma_proj(xh, g_Wg, wst, acc, tid, wm, wn, a_row, a_kh, b_kr, b_nc);
    frag_store_gate(acc, bg, g_WgS, sd_s, mu_s, stageF, g_gateh, R0, lane, wm, wn, tid);
}

// ---------------- kernel B: per-channel 384^3 GEMM + fused gate ----------------
#define KB_STG (128*APAD + 64*BPAD)   // fp16 elements per stage (17920)

__device__ __forceinline__ void kb_prefetch(
    __half* st,
    const __half* __restrict__ AgH,
    const __half* __restrict__ BgH,
    int k0, int tid)
{
    __half* aH = st;
    __half* bH = st + 128*APAD;
#pragma unroll
    for (int t = 0; t < 2; t++) {
        int idx = tid + t*T;                // 0..1023 (128 rows x 8 chunks)
        int r = idx >> 3, c = idx & 7;
        cp16(smem_u32(aH + r*APAD + c*8), AgH + (size_t)r*NN + k0 + c*8);
    }
#pragma unroll
    for (int t = 0; t < 2; t++) {
        int idx = tid + t*T;                // 0..1023 (64 rows x 16 chunks)
        int r = idx >> 4, c = idx & 15;
        cp16(smem_u32(bH + r*BPAD + c*8), BgH + (size_t)(k0 + r)*NN + c*8);
    }
}

__global__ void __launch_bounds__(T, 2)
kernelB_mma()
{
    extern __shared__ __align__(16) __half smb[];
    const int tid  = threadIdx.x;
    const int lane = tid & 31, wid = tid >> 5;
    const int J0 = blockIdx.x*128, I0 = blockIdx.y*128, h = blockIdx.z;
    const int wm = (wid & 7)*16, wn = (wid >> 3)*64;

    const __half* __restrict__ AgH = g_leftH  + (size_t)h*MTOT + (size_t)I0*NN;
    const __half* __restrict__ BgH = g_rightH + (size_t)h*MTOT + J0;

    float acc[8][4];
#pragma unroll
    for (int nj = 0; nj < 8; nj++)
#pragma unroll
        for (int q = 0; q < 4; q++) acc[nj][q] = 0.f;

    const int a_row = (lane & 7) + ((lane >> 3) & 1)*8;
    const int a_kh  = (lane >> 4)*8;
    const int b_kr  = (lane & 7) + ((lane >> 3) & 1)*8;
    const int b_nc  = (lane >> 4)*8;

    kb_prefetch(smb, AgH, BgH, 0, tid);
    cp_commit();

    for (int ch = 0; ch < 6; ch++) {
        if (ch + 1 < 6) {
            kb_prefetch(smb + ((ch+1)&1)*KB_STG, AgH, BgH, (ch+1)*64, tid);
            cp_commit();
            cp_wait<1>();
        } else {
            cp_wait<0>();
        }
        __syncthreads();

        const __half* aH = smb + (ch&1)*KB_STG;
        const __half* bH = aH + 128*APAD;
#pragma unroll
        for (int kk = 0; kk < 64; kk += 16) {
            unsigned aF[4];
            ldmx4(aF, smem_u32(aH + (wm + a_row)*APAD + kk + a_kh));
#pragma unroll
            for (int nh = 0; nh < 4; nh++) {
                unsigned bF[4];
                ldmx4t(bF, smem_u32(bH + (kk + b_kr)*BPAD + wn + nh*16 + b_nc));
                mma16816(acc[nh*2 + 0], aF, bF[0], bF[1]);
                mma16816(acc[nh*2 + 1], aF, bF[2], bF[3]);
            }
        }
        __syncthreads();
    }

    // epilogue: v = out * gate (per warp-row the nj loop covers 128 contiguous
    // bytes -> fully sectored reads/writes; gate sectors L1-resident across nj)
    const __half* __restrict__ Gg = g_gateh + (size_t)h*MTOT;
    __half* __restrict__       Vd = g_v     + (size_t)h*MTOT;
    int r0 = I0 + wm + (lane >> 2);
#pragma unroll
    for (int nj = 0; nj < 8; nj++) {
        int c = J0 + wn + nj*8 + (lane & 3)*2;
        size_t o0 = (size_t)r0*NN + c;
        size_t o1 = (size_t)(r0+8)*NN + c;
        float2 ga0 = __half22float2(*reinterpret_cast<const __half2*>(Gg + o0));
        float2 ga1 = __half22float2(*reinterpret_cast<const __half2*>(Gg + o1));
        *reinterpret_cast<__half2*>(Vd + o0) =
            __floats2half2_rn(acc[nj][0]*ga0.x, acc[nj][1]*ga0.y);
        *reinterpret_cast<__half2*>(Vd + o1) =
            __floats2half2_rn(acc[nj][2]*ga1.x, acc[nj][3]*ga1.y);
    }
}

// ---------------- kernel C: v @ Wo + bo + residual + LN ------------------------
// smem (101888 B, 2 CTAs/SM): vP 34816 | y_s 66048 (wst aliases first 34816) | stats
__global__ void __launch_bounds__(T, 2)
kernelC(const float* __restrict__ pair,
        const float* __restrict__ bo,
        const float* __restrict__ ng,
        const float* __restrict__ nb,
        float* __restrict__ out)
{
    extern __shared__ __align__(16) char smC[];
    __half* vP  = (__half*)smC;                    // [128][XPAD]
    float* y_s  = (float*)(smC + 34816);           // [128][129]
    __half* wst = (__half*)(smC + 34816);          // aliases y_s (wst dead outside hmma_proj)
    float* mu_s = (float*)(smC + 100864);
    float* rs_s = mu_s + 128;

    const int tid = threadIdx.x;
    const int lane = tid & 31, wid = tid >> 5;
    const int wm = (wid & 7)*16, wn = (wid >> 3)*64;
    const int a_row = (lane & 7) + ((lane >> 3) & 1)*8;
    const int a_kh  = (lane >> 4)*8;
    const int b_kr  = (lane & 7) + ((lane >> 3) & 1)*8;
    const int b_nc  = (lane >> 4)*8;
    const size_t IJ0 = (size_t)blockIdx.x * 128;

    // v (fp16, channel-major) -> y_s (transposed fp32 staging), coalesced reads
    for (int i = tid; i < 128*128; i += T) {
        int h = i >> 7, r = i & 127;
        y_s[r*129 + h] = __half2float(g_v[(size_t)h * MTOT + IJ0 + r]);
    }
    __syncthreads();
    // y_s -> single fp16 plane
    for (int i = tid; i < 128*64; i += T) {
        int r = i >> 6, c2 = i & 63;
        __half2 h2 = __floats2half2_rn(y_s[r*129 + 2*c2], y_s[r*129 + 2*c2 + 1]);
        *reinterpret_cast<unsigned*>(vP + r*XPAD + 2*c2) = *(unsigned*)&h2;
    }
    __syncthreads();   // all y_s reads done before hmma_proj's cp.async hits the alias

    float acc[8][4];
    hmma_proj(vP, g_Wo, wst, acc, tid, wm, wn, a_row, a_kh, b_kr, b_nc);

    // y = acc + bo + pair residual -> y_s (wst dead again)
    {
        int r = wm + (lane >> 2);
#pragma unroll
        for (int nj = 0; nj < 8; nj++) {
            int c = wn + nj*8 + (lane & 3)*2;
            float b0 = __ldg(bo + c), b1 = __ldg(bo + c + 1);
            float2 p0 = *reinterpret_cast<const float2*>(pair + (IJ0 + r)*CC + c);
            float2 p1 = *reinterpret_cast<const float2*>(pair + (IJ0 + r + 8)*CC + c);
            y_s[r*129 + c]       = acc[nj][0] + b0 + p0.x;
            y_s[r*129 + c+1]     = acc[nj][1] + b1 + p0.y;
            y_s[(r+8)*129 + c]   = acc[nj][2] + b0 + p1.x;
            y_s[(r+8)*129 + c+1] = acc[nj][3] + b1 + p1.y;
        }
    }
    __syncthreads();

    // row LN: warp per 8 rows via shuffle — SCALAR smem loads (516B row stride)
#pragma unroll
    for (int rr = 0; rr < 8; rr++) {
        int r = wid*8 + rr;
        const float* row = y_s + r*129 + lane*4;
        float v0 = row[0], v1 = row[1], v2 = row[2], v3 = row[3];
        float s  = v0 + v1 + v2 + v3;
        float s2 = v0*v0 + v1*v1 + v2*v2 + v3*v3;
#pragma unroll
        for (int off = 16; off > 0; off >>= 1) {
            s  += __shfl_xor_sync(0xffffffffu, s,  off);
            s2 += __shfl_xor_sync(0xffffffffu, s2, off);
        }
        if (lane == 0) {
            float mu  = s * (1.f/128.f);
            float var = fmaxf(s2 * (1.f/128.f) - mu*mu, 0.f) + EPS;
            mu_s[r] = mu;
            rs_s[r] = rsqrtf(var);
        }
    }
    __syncthreads();

    for (int i = tid; i < 128*128; i += T) {
        int r = i >> 7, c = i & 127;
        float z = y_s[r*129 + c];
        out[(IJ0 + r)*CC + c] = (z - mu_s[r]) * rs_s[r] * __ldg(ng + c) + __ldg(nb + c);
    }
}

// ---------------- launch --------------------------------------------------------
extern "C" void kernel_launch(void* const* d_in, const int* in_sizes, int n_in,
                              void* d_out, int out_size)
{
    const float* pair   = (const float*)d_in[0];
    const float* ln_l_g = (const float*)d_in[1];
    const float* ln_l_b = (const float*)d_in[2];
    const float* ln_r_g = (const float*)d_in[3];
    const float* ln_r_b = (const float*)d_in[4];
    const float* Wl     = (const float*)d_in[5];
    const float* bl     = (const float*)d_in[6];
    const float* Wr     = (const float*)d_in[7];
    const float* br     = (const float*)d_in[8];
    const float* Wg     = (const float*)d_in[9];
    const float* bg     = (const float*)d_in[10];
    const float* Wo     = (const float*)d_in[11];
    const float* bo     = (const float*)d_in[12];
    const float* n_g    = (const float*)d_in[13];
    const float* n_b    = (const float*)d_in[14];
    float* out = (float*)d_out;

    static __half *pWl = nullptr, *pWr, *pWg, *pWo;
    static float *pbLE, *pbRE, *pWgS;
    if (!pWl) {
        cudaGetSymbolAddress((void**)&pWl, g_Wl);
        cudaGetSymbolAddress((void**)&pWr, g_Wr);
        cudaGetSymbolAddress((void**)&pWg, g_Wg);
        cudaGetSymbolAddress((void**)&pWo, g_Wo);
        cudaGetSymbolAddress((void**)&pbLE, g_bLE);
        cudaGetSymbolAddress((void**)&pbRE, g_bRE);
        cudaGetSymbolAddress((void**)&pWgS, g_WgS);
    }

    const size_t smemA = 102400;   // xh 34816 | stage 66048 (wst alias) | stats
    const size_t smemC = 101888;   // vP 34816 | y_s 66048 (wst alias) | stats
    const size_t smemB = (size_t)2*KB_STG*sizeof(__half);   // 71680
    cudaFuncSetAttribute(kernelA,     cudaFuncAttributeMaxDynamicSharedMemorySize, (int)smemA);
    cudaFuncSetAttribute(kernelC,     cudaFuncAttributeMaxDynamicSharedMemorySize, (int)smemC);
    cudaFuncSetAttribute(kernelB_mma, cudaFuncAttributeMaxDynamicSharedMemorySize, (int)smemB);

    prep_fold<<<CC, CC>>>(Wl, ln_l_g, ln_l_b, bl, pWl, pbLE);
    prep_fold<<<CC, CC>>>(Wr, ln_r_g, ln_r_b, br, pWr, pbRE);
    prep_pack<<<CC, CC>>>(Wg, pWg, pWgS);
    prep_pack<<<CC, CC>>>(Wo, pWo, nullptr);

    kernelA<<<MTOT/128, T, smemA>>>(pair, bg);
    kernelB_mma<<<dim3(NN/128, NN/128, CC), T, smemB>>>();
    kernelC<<<MTOT/128, T, smemC>>>(pair, bo, n_g, n_b, out);
}

// round 13
// speedup vs baseline: 1.9288x; 1.0185x over previous
#include <cuda_runtime.h>
#include <cuda_fp16.h>
#include <math.h>

// Problem constants (fixed by dataset): B=1, N=384, C=H=128
#define NN   384
#define CC   128
#define MTOT (NN*NN)
#define EPS  1e-5f
#define XPAD 136      // data plane row stride (fp16 elems)
#define BPAD 136      // weight / right row stride (fp16 elems)
#define APAD 72       // kernelB left-tile row stride (fp16 elems)
#define T    512      // threads per block (16 warps)

// ---------------- scratch ------------------------------------------------------
__device__ __half g_leftH [(size_t)CC * MTOT];   // [h][i][k]
__device__ __half g_rightH[(size_t)CC * MTOT];   // [h][k][j]
__device__ __half g_gateh [(size_t)CC * MTOT];   // [h][i*N+j] fp16 sigmoid
__device__ __half g_v     [(size_t)CC * MTOT];   // [h][i*N+j] fp16 out*gate
__device__ __half g_Wl[CC*CC], g_Wr[CC*CC], g_Wg[CC*CC], g_Wo[CC*CC];
__device__ float g_bLE[CC], g_bRE[CC], g_WgS[CC];

// ---------------- helpers (baseline PTX only) ----------------------------------
__device__ __forceinline__ unsigned smem_u32(const void* p) {
    return (unsigned)__cvta_generic_to_shared(p);
}
__device__ __forceinline__ void cp16(unsigned saddr, const void* g) {
    asm volatile("cp.async.cg.shared.global [%0], [%1], 16;" :: "r"(saddr), "l"(g));
}
__device__ __forceinline__ void cp_commit() {
    asm volatile("cp.async.commit_group;" ::: "memory");
}
template<int N>
__device__ __forceinline__ void cp_wait() {
    asm volatile("cp.async.wait_group %0;" :: "n"(N) : "memory");
}
__device__ __forceinline__ void ldmx4(unsigned r[4], unsigned addr) {
    asm volatile("ldmatrix.sync.aligned.m8n8.x4.shared.b16 {%0,%1,%2,%3}, [%4];"
        : "=r"(r[0]), "=r"(r[1]), "=r"(r[2]), "=r"(r[3]) : "r"(addr));
}
__device__ __forceinline__ void ldmx4t(unsigned r[4], unsigned addr) {
    asm volatile("ldmatrix.sync.aligned.m8n8.x4.trans.shared.b16 {%0,%1,%2,%3}, [%4];"
        : "=r"(r[0]), "=r"(r[1]), "=r"(r[2]), "=r"(r[3]) : "r"(addr));
}
__device__ __forceinline__ void mma16816(float d[4], const unsigned a[4],
                                         unsigned b0, unsigned b1) {
    asm volatile(
        "mma.sync.aligned.m16n8k16.row.col.f32.f16.f16.f32 "
        "{%0,%1,%2,%3}, {%4,%5,%6,%7}, {%8,%9}, {%0,%1,%2,%3};"
        : "+f"(d[0]), "+f"(d[1]), "+f"(d[2]), "+f"(d[3])
        : "r"(a[0]), "r"(a[1]), "r"(a[2]), "r"(a[3]), "r"(b0), "r"(b1));
}

// ---------------- fused prep kernel (one launch) --------------------------------
// blockIdx.y: 0=Wl(fold ln_l), 1=Wr(fold ln_r), 2=Wg(pack+colsum), 3=Wo(pack)
__global__ void prep_all(const float* __restrict__ Wl,
                         const float* __restrict__ lgl, const float* __restrict__ lbl,
                         const float* __restrict__ bl,
                         const float* __restrict__ Wr,
                         const float* __restrict__ lgr, const float* __restrict__ lbr,
                         const float* __restrict__ br,
                         const float* __restrict__ Wg,
                         const float* __restrict__ Wo,
                         __half* __restrict__ pWl, __half* __restrict__ pWr,
                         __half* __restrict__ pWg, __half* __restrict__ pWo,
                         float* __restrict__ bLE, float* __restrict__ bRE,
                         float* __restrict__ WgS)
{
    int k = blockIdx.x, n = threadIdx.x, which = blockIdx.y;
    if (which == 0) {
        pWl[k*CC + n] = __float2half_rn(lgl[k] * Wl[k*CC + n]);
        if (k == 0) {
            float s = bl[n];
            for (int kk = 0; kk < CC; kk++) s += lbl[kk] * Wl[kk*CC + n];
            bLE[n] = s;
        }
    } else if (which == 1) {
        pWr[k*CC + n] = __float2half_rn(lgr[k] * Wr[k*CC + n]);
        if (k == 0) {
            float s = br[n];
            for (int kk = 0; kk < CC; kk++) s += lbr[kk] * Wr[kk*CC + n];
            bRE[n] = s;
        }
    } else if (which == 2) {
        pWg[k*CC + n] = __float2half_rn(Wg[k*CC + n]);
        if (k == 0) {
            float s = 0.f;
            for (int kk = 0; kk < CC; kk++) s += Wg[kk*CC + n];
            WgS[n] = s;
        }
    } else {
        pWo[k*CC + n] = __float2half_rn(Wo[k*CC + n]);
    }
}

// ---------------- HMMA projection GEMM: single x single, 1 MMA -----------------
__device__ __forceinline__ void hmma_proj(
    const __half* __restrict__ aP,
    const __half* __restrict__ W,
    __half* __restrict__ wst,
    float acc[8][4],
    int tid, int wm, int wn,
    int a_row, int a_kh, int b_kr, int b_nc)
{
    const int PLANE = 64*BPAD;
#pragma unroll
    for (int nj = 0; nj < 8; nj++)
#pragma unroll
        for (int q = 0; q < 4; q++) acc[nj][q] = 0.f;

#pragma unroll
    for (int s = 0; s < 2; s++) {
        __half* d = wst + s*PLANE;
        int k0 = s*64;
#pragma unroll
        for (int t = 0; t < 2; t++) {
            int idx = tid + t*T;            // 0..1023 (64 rows x 16 chunks)
            int r = idx >> 4, c = idx & 15;
            cp16(smem_u32(d + r*BPAD + c*8), W + (k0 + r)*CC + c*8);
        }
        cp_commit();
    }

#pragma unroll
    for (int s = 0; s < 2; s++) {
        if (s == 0) cp_wait<1>(); else cp_wait<0>();
        __syncthreads();
        const __half* bP = wst + s*PLANE;
        int k0 = s*64;
#pragma unroll
        for (int kk = 0; kk < 64; kk += 16) {
            unsigned aF[4];
            ldmx4(aF, smem_u32(aP + (wm + a_row)*XPAD + k0 + kk + a_kh));
#pragma unroll
            for (int nh = 0; nh < 4; nh++) {
                unsigned bF[4];
                ldmx4t(bF, smem_u32(bP + (kk + b_kr)*BPAD + wn + nh*16 + b_nc));
                mma16816(acc[nh*2 + 0], aF, bF[0], bF[1]);
                mma16816(acc[nh*2 + 1], aF, bF[2], bF[3]);
            }
        }
    }
    __syncthreads();   // all wst reads done before caller reuses the region
}

// fragment -> transposed channel-major, single fp16 plane (staged, coalesced)
__device__ __forceinline__ void frag_store_half(
    const float acc[8][4], const float* __restrict__ bias,
    unsigned* __restrict__ stage,
    __half* __restrict__ dstH,
    size_t R0, int lane, int wm, int wn, int tid)
{
    int r = wm + (lane >> 2);
#pragma unroll
    for (int nj = 0; nj < 8; nj++) {
        int c = wn + nj*8 + (lane & 3)*2;
        float b0 = __ldg(bias + c), b1 = __ldg(bias + c + 1);
        stage[c*129 + r]       = (unsigned)__half_as_ushort(__float2half_rn(acc[nj][0] + b0));
        stage[(c+1)*129 + r]   = (unsigned)__half_as_ushort(__float2half_rn(acc[nj][1] + b1));
        stage[c*129 + r+8]     = (unsigned)__half_as_ushort(__float2half_rn(acc[nj][2] + b0));
        stage[(c+1)*129 + r+8] = (unsigned)__half_as_ushort(__float2half_rn(acc[nj][3] + b1));
    }
    __syncthreads();
    for (int idx = tid; idx < 128*64; idx += T) {
        int n = idx >> 6, r2 = idx & 63;
        unsigned w0 = stage[n*129 + 2*r2], w1 = stage[n*129 + 2*r2 + 1];
        unsigned hw = (w0 & 0xFFFFu) | (w1 << 16);
        *reinterpret_cast<unsigned*>(dstH + (size_t)n*MTOT + R0 + 2*r2) = hw;
    }
    __syncthreads();
}

// gate: logit = sd[r]*acc + mu[r]*S[c] + bg[c]; sigmoid; fp16 channel-major
__device__ __forceinline__ void frag_store_gate(
    const float acc[8][4], const float* __restrict__ bg,
    const float* __restrict__ Sg,
    const float* __restrict__ sd_s, const float* __restrict__ mu_s,
    float* __restrict__ stage, __half* __restrict__ dst,
    size_t R0, int lane, int wm, int wn, int tid)
{
    int r = wm + (lane >> 2);
    float sd0 = sd_s[r], mu0 = mu_s[r];
    float sd1 = sd_s[r+8], mu1 = mu_s[r+8];
#pragma unroll
    for (int nj = 0; nj < 8; nj++) {
        int c = wn + nj*8 + (lane & 3)*2;
        float S0 = __ldg(Sg + c) , B0 = __ldg(bg + c);
        float S1 = __ldg(Sg + c+1), B1 = __ldg(bg + c+1);
        float z;
        z = sd0*acc[nj][0] + mu0*S0 + B0; stage[c*129 + r]       = 1.f/(1.f+expf(-z));
        z = sd0*acc[nj][1] + mu0*S1 + B1; stage[(c+1)*129 + r]   = 1.f/(1.f+expf(-z));
        z = sd1*acc[nj][2] + mu1*S0 + B0; stage[c*129 + r+8]     = 1.f/(1.f+expf(-z));
        z = sd1*acc[nj][3] + mu1*S1 + B1; stage[(c+1)*129 + r+8] = 1.f/(1.f+expf(-z));
    }
    __syncthreads();
    for (int idx = tid; idx < 128*64; idx += T) {
        int n = idx >> 6, r2 = idx & 63;
        __half h0 = __float2half_rn(stage[n*129 + 2*r2]);
        __half h1 = __float2half_rn(stage[n*129 + 2*r2 + 1]);
        unsigned hw = (unsigned)__half_as_ushort(h0) | ((unsigned)__half_as_ushort(h1) << 16);
        *reinterpret_cast<unsigned*>(dst + (size_t)n*MTOT + R0 + 2*r2) = hw;
    }
    __syncthreads();
}

// ---------------- kernel A: LN + 3 projections ---------------------------------
// smem (102400 B, 2 CTAs/SM): xh 34816 | stage 66048 (wst aliases first 34816) | stats
__global__ void __launch_bounds__(T, 2)
kernelA(const float* __restrict__ pair,
        const float* __restrict__ bg)
{
    extern __shared__ __align__(16) char smA[];
    __half* xh  = (__half*)smA;                    // [128][XPAD]
    char* stg = smA + 34816;                       // stage region (66048 B)
    __half* wst = (__half*)stg;                    // aliases stage (wst dead outside hmma_proj)
    unsigned* stageU = (unsigned*)stg;
    float*    stageF = (float*)stg;
    float* mu_s = (float*)(smA + 100864);
    float* rs_s = mu_s + 128;
    float* sd_s = rs_s + 128;

    const int tid = threadIdx.x;
    const int lane = tid & 31, wid = tid >> 5;
    const int wm = (wid & 7)*16, wn = (wid >> 3)*64;
    const int a_row = (lane & 7) + ((lane >> 3) & 1)*8;
    const int a_kh  = (lane >> 4)*8;
    const int b_kr  = (lane & 7) + ((lane >> 3) & 1)*8;
    const int b_nc  = (lane >> 4)*8;
    const size_t R0 = (size_t)blockIdx.x * 128;

    // LN stats: warp per 8 rows, coalesced global float4 read + shuffle reduce
#pragma unroll
    for (int rr = 0; rr < 8; rr++) {
        int r = wid*8 + rr;
        float4 v = *reinterpret_cast<const float4*>(pair + (R0 + r)*CC + lane*4);
        float s  = v.x + v.y + v.z + v.w;
        float s2 = v.x*v.x + v.y*v.y + v.z*v.z + v.w*v.w;
#pragma unroll
        for (int off = 16; off > 0; off >>= 1) {
            s  += __shfl_xor_sync(0xffffffffu, s,  off);
            s2 += __shfl_xor_sync(0xffffffffu, s2, off);
        }
        if (lane == 0) {
            float mu  = s * (1.f/128.f);
            float var = fmaxf(s2 * (1.f/128.f) - mu*mu, 0.f) + EPS;
            mu_s[r] = mu;
            rs_s[r] = rsqrtf(var);
            sd_s[r] = sqrtf(var);
        }
    }
    __syncthreads();

    // xhat -> single fp16 plane (pair re-read is L2-hot)
    for (int i = tid; i < 128*32; i += T) {
        int r = i >> 5, c4 = i & 31;
        float4 v = *reinterpret_cast<const float4*>(pair + (R0 + r)*CC + c4*4);
        float mu = mu_s[r], rs = rs_s[r];
        __half2 h0 = __floats2half2_rn((v.x - mu)*rs, (v.y - mu)*rs);
        __half2 h1 = __floats2half2_rn((v.z - mu)*rs, (v.w - mu)*rs);
        *reinterpret_cast<uint2*>(xh + r*XPAD + c4*4) =
            make_uint2(*(unsigned*)&h0, *(unsigned*)&h1);
    }
    // hmma_proj's internal sync (post cp_wait) orders plane writes before ldmatrix

    float acc[8][4];
    hmma_proj(xh, g_Wl, wst, acc, tid, wm, wn, a_row, a_kh, b_kr, b_nc);
    frag_store_half(acc, g_bLE, stageU, g_leftH, R0, lane, wm, wn, tid);
    hmma_proj(xh, g_Wr, wst, acc, tid, wm, wn, a_row, a_kh, b_kr, b_nc);
    frag_store_half(acc, g_bRE, stageU, g_rightH, R0, lane, wm, wn, tid);
    hmma_proj(xh, g_Wg, wst, acc, tid, wm, wn, a_row, a_kh, b_kr, b_nc);
    frag_store_gate(acc, bg, g_WgS, sd_s, mu_s, stageF, g_gateh, R0, lane, wm, wn, tid);
}

// ---------------- kernel B: per-channel 384^3 GEMM + fused gate, 3-stage -------
#define KB_STG (128*APAD + 64*BPAD)   // fp16 elements per stage (17920)

__device__ __forceinline__ void kb_prefetch(
    __half* st,
    const __half* __restrict__ AgH,
    const __half* __restrict__ BgH,
    int k0, int tid)
{
    __half* aH = st;
    __half* bH = st + 128*APAD;
#pragma unroll
    for (int t = 0; t < 2; t++) {
        int idx = tid + t*T;                // 0..1023 (128 rows x 8 chunks)
        int r = idx >> 3, c = idx & 7;
        cp16(smem_u32(aH + r*APAD + c*8), AgH + (size_t)r*NN + k0 + c*8);
    }
#pragma unroll
    for (int t = 0; t < 2; t++) {
        int idx = tid + t*T;                // 0..1023 (64 rows x 16 chunks)
        int r = idx >> 4, c = idx & 15;
        cp16(smem_u32(bH + r*BPAD + c*8), BgH + (size_t)(k0 + r)*NN + c*8);
    }
}

__global__ void __launch_bounds__(T, 2)
kernelB_mma()
{
    extern __shared__ __align__(16) __half smb[];
    const int tid  = threadIdx.x;
    const int lane = tid & 31, wid = tid >> 5;
    const int J0 = blockIdx.x*128, I0 = blockIdx.y*128, h = blockIdx.z;
    const int wm = (wid & 7)*16, wn = (wid >> 3)*64;

    const __half* __restrict__ AgH = g_leftH  + (size_t)h*MTOT + (size_t)I0*NN;
    const __half* __restrict__ BgH = g_rightH + (size_t)h*MTOT + J0;

    float acc[8][4];
#pragma unroll
    for (int nj = 0; nj < 8; nj++)
#pragma unroll
        for (int q = 0; q < 4; q++) acc[nj][q] = 0.f;

    const int a_row = (lane & 7) + ((lane >> 3) & 1)*8;
    const int a_kh  = (lane >> 4)*8;
    const int b_kr  = (lane & 7) + ((lane >> 3) & 1)*8;
    const int b_nc  = (lane >> 4)*8;

    // 3-stage pipeline: stages (ch % 3); two chunks in flight ahead of compute
    kb_prefetch(smb + 0*KB_STG, AgH, BgH, 0,  tid); cp_commit();
    kb_prefetch(smb + 1*KB_STG, AgH, BgH, 64, tid); cp_commit();

    for (int ch = 0; ch < 6; ch++) {
        if (ch + 2 < 6) {
            kb_prefetch(smb + ((ch+2)%3)*KB_STG, AgH, BgH, (ch+2)*64, tid);
            cp_commit();
            cp_wait<2>();
        } else if (ch + 1 < 6) {
            cp_wait<1>();
        } else {
            cp_wait<0>();
        }
        __syncthreads();

        const __half* aH = smb + (ch%3)*KB_STG;
        const __half* bH = aH + 128*APAD;
#pragma unroll
        for (int kk = 0; kk < 64; kk += 16) {
            unsigned aF[4];
            ldmx4(aF, smem_u32(aH + (wm + a_row)*APAD + kk + a_kh));
#pragma unroll
            for (int nh = 0; nh < 4; nh++) {
                unsigned bF[4];
                ldmx4t(bF, smem_u32(bH + (kk + b_kr)*BPAD + wn + nh*16 + b_nc));
                mma16816(acc[nh*2 + 0], aF, bF[0], bF[1]);
                mma16816(acc[nh*2 + 1], aF, bF[2], bF[3]);
            }
        }
        __syncthreads();   // all reads of stage ch done before it is rewritten (ch+3)
    }

    // epilogue: v = out * gate (contiguous 128B per warp-row -> fully sectored)
    const __half* __restrict__ Gg = g_gateh + (size_t)h*MTOT;
    __half* __restrict__       Vd = g_v     + (size_t)h*MTOT;
    int r0 = I0 + wm + (lane >> 2);
#pragma unroll
    for (int nj = 0; nj < 8; nj++) {
        int c = J0 + wn + nj*8 + (lane & 3)*2;
        size_t o0 = (size_t)r0*NN + c;
        size_t o1 = (size_t)(r0+8)*NN + c;
        float2 ga0 = __half22float2(*reinterpret_cast<const __half2*>(Gg + o0));
        float2 ga1 = __half22float2(*reinterpret_cast<const __half2*>(Gg + o1));
        *reinterpret_cast<__half2*>(Vd + o0) =
            __floats2half2_rn(acc[nj][0]*ga0.x, acc[nj][1]*ga0.y);
        *reinterpret_cast<__half2*>(Vd + o1) =
            __floats2half2_rn(acc[nj][2]*ga1.x, acc[nj][3]*ga1.y);
    }
}

// ---------------- kernel C: v @ Wo + bo + residual + LN ------------------------
// smem (101888 B, 2 CTAs/SM): vP 34816 | y_s 66048 (wst aliases first 34816) | stats
__global__ void __launch_bounds__(T, 2)
kernelC(const float* __restrict__ pair,
        const float* __restrict__ bo,
        const float* __restrict__ ng,
        const float* __restrict__ nb,
        float* __restrict__ out)
{
    extern __shared__ __align__(16) char smC[];
    __half* vP  = (__half*)smC;                    // [128][XPAD]
    float* y_s  = (float*)(smC + 34816);           // [128][129]
    __half* wst = (__half*)(smC + 34816);          // aliases y_s (wst dead outside hmma_proj)
    float* mu_s = (float*)(smC + 100864);
    float* rs_s = mu_s + 128;

    const int tid = threadIdx.x;
    const int lane = tid & 31, wid = tid >> 5;
    const int wm = (wid & 7)*16, wn = (wid >> 3)*64;
    const int a_row = (lane & 7) + ((lane >> 3) & 1)*8;
    const int a_kh  = (lane >> 4)*8;
    const int b_kr  = (lane & 7) + ((lane >> 3) & 1)*8;
    const int b_nc  = (lane >> 4)*8;
    const size_t IJ0 = (size_t)blockIdx.x * 128;

    // v (fp16, channel-major) -> y_s (transposed fp32 staging), coalesced reads
    for (int i = tid; i < 128*128; i += T) {
        int h = i >> 7, r = i & 127;
        y_s[r*129 + h] = __half2float(g_v[(size_t)h * MTOT + IJ0 + r]);
    }
    __syncthreads();
    // y_s -> single fp16 plane
    for (int i = tid; i < 128*64; i += T) {
        int r = i >> 6, c2 = i & 63;
        __half2 h2 = __floats2half2_rn(y_s[r*129 + 2*c2], y_s[r*129 + 2*c2 + 1]);
        *reinterpret_cast<unsigned*>(vP + r*XPAD + 2*c2) = *(unsigned*)&h2;
    }
    __syncthreads();   // all y_s reads done before hmma_proj's cp.async hits the alias

    float acc[8][4];
    hmma_proj(vP, g_Wo, wst, acc, tid, wm, wn, a_row, a_kh, b_kr, b_nc);

    // y = acc + bo + pair residual -> y_s (wst dead again)
    {
        int r = wm + (lane >> 2);
#pragma unroll
        for (int nj = 0; nj < 8; nj++) {
            int c = wn + nj*8 + (lane & 3)*2;
            float b0 = __ldg(bo + c), b1 = __ldg(bo + c + 1);
            float2 p0 = *reinterpret_cast<const float2*>(pair + (IJ0 + r)*CC + c);
            float2 p1 = *reinterpret_cast<const float2*>(pair + (IJ0 + r + 8)*CC + c);
            y_s[r*129 + c]       = acc[nj][0] + b0 + p0.x;
            y_s[r*129 + c+1]     = acc[nj][1] + b1 + p0.y;
            y_s[(r+8)*129 + c]   = acc[nj][2] + b0 + p1.x;
            y_s[(r+8)*129 + c+1] = acc[nj][3] + b1 + p1.y;
        }
    }
    __syncthreads();

    // row LN: warp per 8 rows via shuffle — SCALAR smem loads (516B row stride)
#pragma unroll
    for (int rr = 0; rr < 8; rr++) {
        int r = wid*8 + rr;
        const float* row = y_s + r*129 + lane*4;
        float v0 = row[0], v1 = row[1], v2 = row[2], v3 = row[3];
        float s  = v0 + v1 + v2 + v3;
        float s2 = v0*v0 + v1*v1 + v2*v2 + v3*v3;
#pragma unroll
        for (int off = 16; off > 0; off >>= 1) {
            s  += __shfl_xor_sync(0xffffffffu, s,  off);
            s2 += __shfl_xor_sync(0xffffffffu, s2, off);
        }
        if (lane == 0) {
            float mu  = s * (1.f/128.f);
            float var = fmaxf(s2 * (1.f/128.f) - mu*mu, 0.f) + EPS;
            mu_s[r] = mu;
            rs_s[r] = rsqrtf(var);
        }
    }
    __syncthreads();

    for (int i = tid; i < 128*128; i += T) {
        int r = i >> 7, c = i & 127;
        float z = y_s[r*129 + c];
        out[(IJ0 + r)*CC + c] = (z - mu_s[r]) * rs_s[r] * __ldg(ng + c) + __ldg(nb + c);
    }
}

// ---------------- launch --------------------------------------------------------
extern "C" void kernel_launch(void* const* d_in, const int* in_sizes, int n_in,
                              void* d_out, int out_size)
{
    const float* pair   = (const float*)d_in[0];
    const float* ln_l_g = (const float*)d_in[1];
    const float* ln_l_b = (const float*)d_in[2];
    const float* ln_r_g = (const float*)d_in[3];
    const float* ln_r_b = (const float*)d_in[4];
    const float* Wl     = (const float*)d_in[5];
    const float* bl     = (const float*)d_in[6];
    const float* Wr     = (const float*)d_in[7];
    const float* br     = (const float*)d_in[8];
    const float* Wg     = (const float*)d_in[9];
    const float* bg     = (const float*)d_in[10];
    const float* Wo     = (const float*)d_in[11];
    const float* bo     = (const float*)d_in[12];
    const float* n_g    = (const float*)d_in[13];
    const float* n_b    = (const float*)d_in[14];
    float* out = (float*)d_out;

    static __half *pWl = nullptr, *pWr, *pWg, *pWo;
    static float *pbLE, *pbRE, *pWgS;
    if (!pWl) {
        cudaGetSymbolAddress((void**)&pWl, g_Wl);
        cudaGetSymbolAddress((void**)&pWr, g_Wr);
        cudaGetSymbolAddress((void**)&pWg, g_Wg);
        cudaGetSymbolAddress((void**)&pWo, g_Wo);
        cudaGetSymbolAddress((void**)&pbLE, g_bLE);
        cudaGetSymbolAddress((void**)&pbRE, g_bRE);
        cudaGetSymbolAddress((void**)&pWgS, g_WgS);
    }

    const size_t smemA = 102400;   // xh 34816 | stage 66048 (wst alias) | stats
    const size_t smemC = 101888;   // vP 34816 | y_s 66048 (wst alias) | stats
    const size_t smemB = (size_t)3*KB_STG*sizeof(__half);   // 107520 (3-stage)
    cudaFuncSetAttribute(kernelA,     cudaFuncAttributeMaxDynamicSharedMemorySize, (int)smemA);
    cudaFuncSetAttribute(kernelC,     cudaFuncAttributeMaxDynamicSharedMemorySize, (int)smemC);
    cudaFuncSetAttribute(kernelB_mma, cudaFuncAttributeMaxDynamicSharedMemorySize, (int)smemB);

    prep_all<<<dim3(CC, 4), CC>>>(Wl, ln_l_g, ln_l_b, bl,
                                  Wr, ln_r_g, ln_r_b, br,
                                  Wg, Wo,
                                  pWl, pWr, pWg, pWo, pbLE, pbRE, pWgS);

    kernelA<<<MTOT/128, T, smemA>>>(pair, bg);
    kernelB_mma<<<dim3(NN/128, NN/128, CC), T, smemB>>>();
    kernelC<<<MTOT/128, T, smemC>>>(pair, bo, n_g, n_b, out);
}

// round 14
// speedup vs baseline: 1.9781x; 1.0255x over previous
#include <cuda_runtime.h>
#include <cuda_fp16.h>
#include <math.h>

// Problem constants (fixed by dataset): B=1, N=384, C=H=128
#define NN   384
#define CC   128
#define MTOT (NN*NN)
#define EPS  1e-5f
#define XPAD 136      // data plane row stride (fp16 elems)
#define BPAD 136      // weight / right row stride (fp16 elems)
#define APAD 72       // kernelB left-tile row stride (fp16 elems)
#define T    512      // threads per block (16 warps)

// ---------------- scratch ------------------------------------------------------
__device__ __half g_leftH [(size_t)CC * MTOT];   // [h][i][k]
__device__ __half g_rightH[(size_t)CC * MTOT];   // [h][k][j]
__device__ __half g_gateh [(size_t)CC * MTOT];   // [h][i*N+j] fp16 sigmoid
__device__ __half g_v     [(size_t)CC * MTOT];   // [h][i*N+j] fp16 out*gate
__device__ __half g_Wl[CC*CC], g_Wr[CC*CC], g_Wg[CC*CC], g_Wo[CC*CC];
__device__ float g_bLE[CC], g_bRE[CC], g_WgS[CC];

// ---------------- helpers (baseline PTX only) ----------------------------------
__device__ __forceinline__ unsigned smem_u32(const void* p) {
    return (unsigned)__cvta_generic_to_shared(p);
}
__device__ __forceinline__ void cp16(unsigned saddr, const void* g) {
    asm volatile("cp.async.cg.shared.global [%0], [%1], 16;" :: "r"(saddr), "l"(g));
}
__device__ __forceinline__ void cp_commit() {
    asm volatile("cp.async.commit_group;" ::: "memory");
}
template<int N>
__device__ __forceinline__ void cp_wait() {
    asm volatile("cp.async.wait_group %0;" :: "n"(N) : "memory");
}
__device__ __forceinline__ void ldmx4(unsigned r[4], unsigned addr) {
    asm volatile("ldmatrix.sync.aligned.m8n8.x4.shared.b16 {%0,%1,%2,%3}, [%4];"
        : "=r"(r[0]), "=r"(r[1]), "=r"(r[2]), "=r"(r[3]) : "r"(addr));
}
__device__ __forceinline__ void ldmx4t(unsigned r[4], unsigned addr) {
    asm volatile("ldmatrix.sync.aligned.m8n8.x4.trans.shared.b16 {%0,%1,%2,%3}, [%4];"
        : "=r"(r[0]), "=r"(r[1]), "=r"(r[2]), "=r"(r[3]) : "r"(addr));
}
__device__ __forceinline__ void mma16816(float d[4], const unsigned a[4],
                                         unsigned b0, unsigned b1) {
    asm volatile(
        "mma.sync.aligned.m16n8k16.row.col.f32.f16.f16.f32 "
        "{%0,%1,%2,%3}, {%4,%5,%6,%7}, {%8,%9}, {%0,%1,%2,%3};"
        : "+f"(d[0]), "+f"(d[1]), "+f"(d[2]), "+f"(d[3])
        : "r"(a[0]), "r"(a[1]), "r"(a[2]), "r"(a[3]), "r"(b0), "r"(b1));
}

// ---------------- fused prep kernel (one launch) --------------------------------
__global__ void prep_all(const float* __restrict__ Wl,
                         const float* __restrict__ lgl, const float* __restrict__ lbl,
                         const float* __restrict__ bl,
                         const float* __restrict__ Wr,
                         const float* __restrict__ lgr, const float* __restrict__ lbr,
                         const float* __restrict__ br,
                         const float* __restrict__ Wg,
                         const float* __restrict__ Wo,
                         __half* __restrict__ pWl, __half* __restrict__ pWr,
                         __half* __restrict__ pWg, __half* __restrict__ pWo,
                         float* __restrict__ bLE, float* __restrict__ bRE,
                         float* __restrict__ WgS)
{
    int k = blockIdx.x, n = threadIdx.x, which = blockIdx.y;
    if (which == 0) {
        pWl[k*CC + n] = __float2half_rn(lgl[k] * Wl[k*CC + n]);
        if (k == 0) {
            float s = bl[n];
            for (int kk = 0; kk < CC; kk++) s += lbl[kk] * Wl[kk*CC + n];
            bLE[n] = s;
        }
    } else if (which == 1) {
        pWr[k*CC + n] = __float2half_rn(lgr[k] * Wr[k*CC + n]);
        if (k == 0) {
            float s = br[n];
            for (int kk = 0; kk < CC; kk++) s += lbr[kk] * Wr[kk*CC + n];
            bRE[n] = s;
        }
    } else if (which == 2) {
        pWg[k*CC + n] = __float2half_rn(Wg[k*CC + n]);
        if (k == 0) {
            float s = 0.f;
            for (int kk = 0; kk < CC; kk++) s += Wg[kk*CC + n];
            WgS[n] = s;
        }
    } else {
        pWo[k*CC + n] = __float2half_rn(Wo[k*CC + n]);
    }
}

// ---------------- HMMA projection GEMM: 32x32 warp tiles -----------------------
// acc[mi][nj][q]: mi = m16 half (0,1), nj = n8 tile (0..3)
__device__ __forceinline__ void hmma_proj(
    const __half* __restrict__ aP,
    const __half* __restrict__ W,
    __half* __restrict__ wst,
    float acc[2][4][4],
    int tid, int wm, int wn,
    int a_row, int a_kh, int b_kr, int b_nc)
{
    const int PLANE = 64*BPAD;
#pragma unroll
    for (int mi = 0; mi < 2; mi++)
#pragma unroll
        for (int nj = 0; nj < 4; nj++)
#pragma unroll
            for (int q = 0; q < 4; q++) acc[mi][nj][q] = 0.f;

#pragma unroll
    for (int s = 0; s < 2; s++) {
        __half* d = wst + s*PLANE;
        int k0 = s*64;
#pragma unroll
        for (int t = 0; t < 2; t++) {
            int idx = tid + t*T;            // 0..1023 (64 rows x 16 chunks)
            int r = idx >> 4, c = idx & 15;
            cp16(smem_u32(d + r*BPAD + c*8), W + (k0 + r)*CC + c*8);
        }
        cp_commit();
    }

#pragma unroll
    for (int s = 0; s < 2; s++) {
        if (s == 0) cp_wait<1>(); else cp_wait<0>();
        __syncthreads();
        const __half* bP = wst + s*PLANE;
        int k0 = s*64;
#pragma unroll
        for (int kk = 0; kk < 64; kk += 16) {
            unsigned aF[2][4];
#pragma unroll
            for (int mi = 0; mi < 2; mi++)
                ldmx4(aF[mi], smem_u32(aP + (wm + mi*16 + a_row)*XPAD + k0 + kk + a_kh));
#pragma unroll
            for (int nh = 0; nh < 2; nh++) {
                unsigned bF[4];
                ldmx4t(bF, smem_u32(bP + (kk + b_kr)*BPAD + wn + nh*16 + b_nc));
#pragma unroll
                for (int mi = 0; mi < 2; mi++) {
                    mma16816(acc[mi][nh*2 + 0], aF[mi], bF[0], bF[1]);
                    mma16816(acc[mi][nh*2 + 1], aF[mi], bF[2], bF[3]);
                }
            }
        }
    }
    __syncthreads();   // all wst reads done before caller reuses the region
}

// fragment -> transposed channel-major, single fp16 plane (staged, coalesced)
__device__ __forceinline__ void frag_store_half(
    const float acc[2][4][4], const float* __restrict__ bias,
    unsigned* __restrict__ stage,
    __half* __restrict__ dstH,
    size_t R0, int lane, int wm, int wn, int tid)
{
#pragma unroll
    for (int mi = 0; mi < 2; mi++) {
        int r = wm + mi*16 + (lane >> 2);
#pragma unroll
        for (int nj = 0; nj < 4; nj++) {
            int c = wn + nj*8 + (lane & 3)*2;
            float b0 = __ldg(bias + c), b1 = __ldg(bias + c + 1);
            stage[c*129 + r]       = (unsigned)__half_as_ushort(__float2half_rn(acc[mi][nj][0] + b0));
            stage[(c+1)*129 + r]   = (unsigned)__half_as_ushort(__float2half_rn(acc[mi][nj][1] + b1));
            stage[c*129 + r+8]     = (unsigned)__half_as_ushort(__float2half_rn(acc[mi][nj][2] + b0));
            stage[(c+1)*129 + r+8] = (unsigned)__half_as_ushort(__float2half_rn(acc[mi][nj][3] + b1));
        }
    }
    __syncthreads();
    for (int idx = tid; idx < 128*64; idx += T) {
        int n = idx >> 6, r2 = idx & 63;
        unsigned w0 = stage[n*129 + 2*r2], w1 = stage[n*129 + 2*r2 + 1];
        unsigned hw = (w0 & 0xFFFFu) | (w1 << 16);
        *reinterpret_cast<unsigned*>(dstH + (size_t)n*MTOT + R0 + 2*r2) = hw;
    }
    __syncthreads();
}

// gate: logit = sd[r]*acc + mu[r]*S[c] + bg[c]; sigmoid; fp16 channel-major
__device__ __forceinline__ void frag_store_gate(
    const float acc[2][4][4], const float* __restrict__ bg,
    const float* __restrict__ Sg,
    const float* __restrict__ sd_s, const float* __restrict__ mu_s,
    float* __restrict__ stage, __half* __restrict__ dst,
    size_t R0, int lane, int wm, int wn, int tid)
{
#pragma unroll
    for (int mi = 0; mi < 2; mi++) {
        int r = wm + mi*16 + (lane >> 2);
        float sd0 = sd_s[r], mu0 = mu_s[r];
        float sd1 = sd_s[r+8], mu1 = mu_s[r+8];
#pragma unroll
        for (int nj = 0; nj < 4; nj++) {
            int c = wn + nj*8 + (lane & 3)*2;
            float S0 = __ldg(Sg + c) , B0 = __ldg(bg + c);
            float S1 = __ldg(Sg + c+1), B1 = __ldg(bg + c+1);
            float z;
            z = sd0*acc[mi][nj][0] + mu0*S0 + B0; stage[c*129 + r]       = 1.f/(1.f+expf(-z));
            z = sd0*acc[mi][nj][1] + mu0*S1 + B1; stage[(c+1)*129 + r]   = 1.f/(1.f+expf(-z));
            z = sd1*acc[mi][nj][2] + mu1*S0 + B0; stage[c*129 + r+8]     = 1.f/(1.f+expf(-z));
            z = sd1*acc[mi][nj][3] + mu1*S1 + B1; stage[(c+1)*129 + r+8] = 1.f/(1.f+expf(-z));
        }
    }
    __syncthreads();
    for (int idx = tid; idx < 128*64; idx += T) {
        int n = idx >> 6, r2 = idx & 63;
        __half h0 = __float2half_rn(stage[n*129 + 2*r2]);
        __half h1 = __float2half_rn(stage[n*129 + 2*r2 + 1]);
        unsigned hw = (unsigned)__half_as_ushort(h0) | ((unsigned)__half_as_ushort(h1) << 16);
        *reinterpret_cast<unsigned*>(dst + (size_t)n*MTOT + R0 + 2*r2) = hw;
    }
    __syncthreads();
}

// ---------------- kernel A: LN + 3 projections ---------------------------------
// smem (102400 B, 2 CTAs/SM): xh 34816 | stage 66048 (wst alias) | stats
__global__ void __launch_bounds__(T, 2)
kernelA(const float* __restrict__ pair,
        const float* __restrict__ bg)
{
    extern __shared__ __align__(16) char smA[];
    __half* xh  = (__half*)smA;                    // [128][XPAD]
    char* stg = smA + 34816;                       // stage region (66048 B)
    __half* wst = (__half*)stg;                    // aliases stage
    unsigned* stageU = (unsigned*)stg;
    float*    stageF = (float*)stg;
    float* mu_s = (float*)(smA + 100864);
    float* rs_s = mu_s + 128;
    float* sd_s = rs_s + 128;

    const int tid = threadIdx.x;
    const int lane = tid & 31, wid = tid >> 5;
    const int wm = (wid & 3)*32, wn = (wid >> 2)*32;
    const int a_row = (lane & 7) + ((lane >> 3) & 1)*8;
    const int a_kh  = (lane >> 4)*8;
    const int b_kr  = (lane & 7) + ((lane >> 3) & 1)*8;
    const int b_nc  = (lane >> 4)*8;
    const size_t R0 = (size_t)blockIdx.x * 128;

    // LN stats: warp per 8 rows, coalesced global float4 read + shuffle reduce
#pragma unroll
    for (int rr = 0; rr < 8; rr++) {
        int r = wid*8 + rr;
        float4 v = *reinterpret_cast<const float4*>(pair + (R0 + r)*CC + lane*4);
        float s  = v.x + v.y + v.z + v.w;
        float s2 = v.x*v.x + v.y*v.y + v.z*v.z + v.w*v.w;
#pragma unroll
        for (int off = 16; off > 0; off >>= 1) {
            s  += __shfl_xor_sync(0xffffffffu, s,  off);
            s2 += __shfl_xor_sync(0xffffffffu, s2, off);
        }
        if (lane == 0) {
            float mu  = s * (1.f/128.f);
            float var = fmaxf(s2 * (1.f/128.f) - mu*mu, 0.f) + EPS;
            mu_s[r] = mu;
            rs_s[r] = rsqrtf(var);
            sd_s[r] = sqrtf(var);
        }
    }
    __syncthreads();

    // xhat -> single fp16 plane (pair re-read is L2-hot)
    for (int i = tid; i < 128*32; i += T) {
        int r = i >> 5, c4 = i & 31;
        float4 v = *reinterpret_cast<const float4*>(pair + (R0 + r)*CC + c4*4);
        float mu = mu_s[r], rs = rs_s[r];
        __half2 h0 = __floats2half2_rn((v.x - mu)*rs, (v.y - mu)*rs);
        __half2 h1 = __floats2half2_rn((v.z - mu)*rs, (v.w - mu)*rs);
        *reinterpret_cast<uint2*>(xh + r*XPAD + c4*4) =
            make_uint2(*(unsigned*)&h0, *(unsigned*)&h1);
    }
    // hmma_proj's internal sync (post cp_wait) orders plane writes before ldmatrix

    float acc[2][4][4];
    hmma_proj(xh, g_Wl, wst, acc, tid, wm, wn, a_row, a_kh, b_kr, b_nc);
    frag_store_half(acc, g_bLE, stageU, g_leftH, R0, lane, wm, wn, tid);
    hmma_proj(xh, g_Wr, wst, acc, tid, wm, wn, a_row, a_kh, b_kr, b_nc);
    frag_store_half(acc, g_bRE, stageU, g_rightH, R0, lane, wm, wn, tid);
    hmma_proj(xh, g_Wg, wst, acc, tid, wm, wn, a_row, a_kh, b_kr, b_nc);
    frag_store_gate(acc, bg, g_WgS, sd_s, mu_s, stageF, g_gateh, R0, lane, wm, wn, tid);
}

// ---------------- kernel B: per-channel 384^3 GEMM + fused gate, 3-stage -------
#define KB_STG (128*APAD + 64*BPAD)   // fp16 elements per stage (17920)

__device__ __forceinline__ void kb_prefetch(
    __half* st,
    const __half* __restrict__ AgH,
    const __half* __restrict__ BgH,
    int k0, int tid)
{
    __half* aH = st;
    __half* bH = st + 128*APAD;
#pragma unroll
    for (int t = 0; t < 2; t++) {
        int idx = tid + t*T;                // 0..1023 (128 rows x 8 chunks)
        int r = idx >> 3, c = idx & 7;
        cp16(smem_u32(aH + r*APAD + c*8), AgH + (size_t)r*NN + k0 + c*8);
    }
#pragma unroll
    for (int t = 0; t < 2; t++) {
        int idx = tid + t*T;                // 0..1023 (64 rows x 16 chunks)
        int r = idx >> 4, c = idx & 15;
        cp16(smem_u32(bH + r*BPAD + c*8), BgH + (size_t)(k0 + r)*NN + c*8);
    }
}

__global__ void __launch_bounds__(T, 2)
kernelB_mma()
{
    extern __shared__ __align__(16) __half smb[];
    const int tid  = threadIdx.x;
    const int lane = tid & 31, wid = tid >> 5;
    const int J0 = blockIdx.x*128, I0 = blockIdx.y*128, h = blockIdx.z;
    const int wm = (wid & 3)*32, wn = (wid >> 2)*32;

    const __half* __restrict__ AgH = g_leftH  + (size_t)h*MTOT + (size_t)I0*NN;
    const __half* __restrict__ BgH = g_rightH + (size_t)h*MTOT + J0;

    float acc[2][4][4];
#pragma unroll
    for (int mi = 0; mi < 2; mi++)
#pragma unroll
        for (int nj = 0; nj < 4; nj++)
#pragma unroll
            for (int q = 0; q < 4; q++) acc[mi][nj][q] = 0.f;

    const int a_row = (lane & 7) + ((lane >> 3) & 1)*8;
    const int a_kh  = (lane >> 4)*8;
    const int b_kr  = (lane & 7) + ((lane >> 3) & 1)*8;
    const int b_nc  = (lane >> 4)*8;

    kb_prefetch(smb + 0*KB_STG, AgH, BgH, 0,  tid); cp_commit();
    kb_prefetch(smb + 1*KB_STG, AgH, BgH, 64, tid); cp_commit();

    for (int ch = 0; ch < 6; ch++) {
        if (ch + 2 < 6) {
            kb_prefetch(smb + ((ch+2)%3)*KB_STG, AgH, BgH, (ch+2)*64, tid);
            cp_commit();
            cp_wait<2>();
        } else if (ch + 1 < 6) {
            cp_wait<1>();
        } else {
            cp_wait<0>();
        }
        __syncthreads();

        const __half* aH = smb + (ch%3)*KB_STG;
        const __half* bH = aH + 128*APAD;
#pragma unroll
        for (int kk = 0; kk < 64; kk += 16) {
            unsigned aF[2][4];
#pragma unroll
            for (int mi = 0; mi < 2; mi++)
                ldmx4(aF[mi], smem_u32(aH + (wm + mi*16 + a_row)*APAD + kk + a_kh));
#pragma unroll
            for (int nh = 0; nh < 2; nh++) {
                unsigned bF[4];
                ldmx4t(bF, smem_u32(bH + (kk + b_kr)*BPAD + wn + nh*16 + b_nc));
#pragma unroll
                for (int mi = 0; mi < 2; mi++) {
                    mma16816(acc[mi][nh*2 + 0], aF[mi], bF[0], bF[1]);
                    mma16816(acc[mi][nh*2 + 1], aF[mi], bF[2], bF[3]);
                }
            }
        }
        __syncthreads();
    }

    // epilogue: v = out * gate (contiguous windows per warp-row -> sectored)
    const __half* __restrict__ Gg = g_gateh + (size_t)h*MTOT;
    __half* __restrict__       Vd = g_v     + (size_t)h*MTOT;
#pragma unroll
    for (int mi = 0; mi < 2; mi++) {
        int r0 = I0 + wm + mi*16 + (lane >> 2);
#pragma unroll
        for (int nj = 0; nj < 4; nj++) {
            int c = J0 + wn + nj*8 + (lane & 3)*2;
            size_t o0 = (size_t)r0*NN + c;
            size_t o1 = (size_t)(r0+8)*NN + c;
            float2 ga0 = __half22float2(*reinterpret_cast<const __half2*>(Gg + o0));
            float2 ga1 = __half22float2(*reinterpret_cast<const __half2*>(Gg + o1));
            *reinterpret_cast<__half2*>(Vd + o0) =
                __floats2half2_rn(acc[mi][nj][0]*ga0.x, acc[mi][nj][1]*ga0.y);
            *reinterpret_cast<__half2*>(Vd + o1) =
                __floats2half2_rn(acc[mi][nj][2]*ga1.x, acc[mi][nj][3]*ga1.y);
        }
    }
}

// ---------------- kernel C: v @ Wo + bo + residual + LN ------------------------
// smem (101888 B, 2 CTAs/SM): vP 34816 | y_s 66048 (wst alias) | stats
__global__ void __launch_bounds__(T, 2)
kernelC(const float* __restrict__ pair,
        const float* __restrict__ bo,
        const float* __restrict__ ng,
        const float* __restrict__ nb,
        float* __restrict__ out)
{
    extern __shared__ __align__(16) char smC[];
    __half* vP  = (__half*)smC;                    // [128][XPAD]
    float* y_s  = (float*)(smC + 34816);           // [128][129]
    __half* wst = (__half*)(smC + 34816);          // aliases y_s
    float* mu_s = (float*)(smC + 100864);
    float* rs_s = mu_s + 128;

    const int tid = threadIdx.x;
    const int lane = tid & 31, wid = tid >> 5;
    const int wm = (wid & 3)*32, wn = (wid >> 2)*32;
    const int a_row = (lane & 7) + ((lane >> 3) & 1)*8;
    const int a_kh  = (lane >> 4)*8;
    const int b_kr  = (lane & 7) + ((lane >> 3) & 1)*8;
    const int b_nc  = (lane >> 4)*8;
    const size_t IJ0 = (size_t)blockIdx.x * 128;

    // v (fp16, channel-major) -> y_s transposed staging; __half2 reads (2 rows/thread)
    for (int i = tid; i < 128*64; i += T) {
        int h = i >> 6, r2 = i & 63;
        __half2 v = *reinterpret_cast<const __half2*>(g_v + (size_t)h*MTOT + IJ0 + 2*r2);
        y_s[(2*r2)*129 + h]   = __half2float(__low2half(v));
        y_s[(2*r2+1)*129 + h] = __half2float(__high2half(v));
    }
    __syncthreads();
    // y_s -> single fp16 plane
    for (int i = tid; i < 128*64; i += T) {
        int r = i >> 6, c2 = i & 63;
        __half2 h2 = __floats2half2_rn(y_s[r*129 + 2*c2], y_s[r*129 + 2*c2 + 1]);
        *reinterpret_cast<unsigned*>(vP + r*XPAD + 2*c2) = *(unsigned*)&h2;
    }
    __syncthreads();   // all y_s reads done before hmma_proj's cp.async hits the alias

    float acc[2][4][4];
    hmma_proj(vP, g_Wo, wst, acc, tid, wm, wn, a_row, a_kh, b_kr, b_nc);

    // y = acc + bo + pair residual -> y_s (wst dead again)
#pragma unroll
    for (int mi = 0; mi < 2; mi++) {
        int r = wm + mi*16 + (lane >> 2);
#pragma unroll
        for (int nj = 0; nj < 4; nj++) {
            int c = wn + nj*8 + (lane & 3)*2;
            float b0 = __ldg(bo + c), b1 = __ldg(bo + c + 1);
            float2 p0 = *reinterpret_cast<const float2*>(pair + (IJ0 + r)*CC + c);
            float2 p1 = *reinterpret_cast<const float2*>(pair + (IJ0 + r + 8)*CC + c);
            y_s[r*129 + c]       = acc[mi][nj][0] + b0 + p0.x;
            y_s[r*129 + c+1]     = acc[mi][nj][1] + b1 + p0.y;
            y_s[(r+8)*129 + c]   = acc[mi][nj][2] + b0 + p1.x;
            y_s[(r+8)*129 + c+1] = acc[mi][nj][3] + b1 + p1.y;
        }
    }
    __syncthreads();

    // row LN: warp per 8 rows via shuffle — SCALAR smem loads (516B row stride)
#pragma unroll
    for (int rr = 0; rr < 8; rr++) {
        int r = wid*8 + rr;
        const float* row = y_s + r*129 + lane*4;
        float v0 = row[0], v1 = row[1], v2 = row[2], v3 = row[3];
        float s  = v0 + v1 + v2 + v3;
        float s2 = v0*v0 + v1*v1 + v2*v2 + v3*v3;
#pragma unroll
        for (int off = 16; off > 0; off >>= 1) {
            s  += __shfl_xor_sync(0xffffffffu, s,  off);
            s2 += __shfl_xor_sync(0xffffffffu, s2, off);
        }
        if (lane == 0) {
            float mu  = s * (1.f/128.f);
            float var = fmaxf(s2 * (1.f/128.f) - mu*mu, 0.f) + EPS;
            mu_s[r] = mu;
            rs_s[r] = rsqrtf(var);
        }
    }
    __syncthreads();

    // final: LN apply + float4 global writes
    for (int i = tid; i < 128*32; i += T) {
        int r = i >> 5, c4 = (i & 31)*4;
        float mu = mu_s[r], rs = rs_s[r];
        const float* row = y_s + r*129 + c4;
        float4 o;
        o.x = (row[0] - mu) * rs * __ldg(ng + c4 + 0) + __ldg(nb + c4 + 0);
        o.y = (row[1] - mu) * rs * __ldg(ng + c4 + 1) + __ldg(nb + c4 + 1);
        o.z = (row[2] - mu) * rs * __ldg(ng + c4 + 2) + __ldg(nb + c4 + 2);
        o.w = (row[3] - mu) * rs * __ldg(ng + c4 + 3) + __ldg(nb + c4 + 3);
        *reinterpret_cast<float4*>(out + (IJ0 + r)*CC + c4) = o;
    }
}

// ---------------- launch --------------------------------------------------------
extern "C" void kernel_launch(void* const* d_in, const int* in_sizes, int n_in,
                              void* d_out, int out_size)
{
    const float* pair   = (const float*)d_in[0];
    const float* ln_l_g = (const float*)d_in[1];
    const float* ln_l_b = (const float*)d_in[2];
    const float* ln_r_g = (const float*)d_in[3];
    const float* ln_r_b = (const float*)d_in[4];
    const float* Wl     = (const float*)d_in[5];
    const float* bl     = (const float*)d_in[6];
    const float* Wr     = (const float*)d_in[7];
    const float* br     = (const float*)d_in[8];
    const float* Wg     = (const float*)d_in[9];
    const float* bg     = (const float*)d_in[10];
    const float* Wo     = (const float*)d_in[11];
    const float* bo     = (const float*)d_in[12];
    const float* n_g    = (const float*)d_in[13];
    const float* n_b    = (const float*)d_in[14];
    float* out = (float*)d_out;

    static __half *pWl = nullptr, *pWr, *pWg, *pWo;
    static float *pbLE, *pbRE, *pWgS;
    if (!pWl) {
        cudaGetSymbolAddress((void**)&pWl, g_Wl);
        cudaGetSymbolAddress((void**)&pWr, g_Wr);
        cudaGetSymbolAddress((void**)&pWg, g_Wg);
        cudaGetSymbolAddress((void**)&pWo, g_Wo);
        cudaGetSymbolAddress((void**)&pbLE, g_bLE);
        cudaGetSymbolAddress((void**)&pbRE, g_bRE);
        cudaGetSymbolAddress((void**)&pWgS, g_WgS);
    }

    const size_t smemA = 102400;
    const size_t smemC = 101888;
    const size_t smemB = (size_t)3*KB_STG*sizeof(__half);   // 107520
    cudaFuncSetAttribute(kernelA,     cudaFuncAttributeMaxDynamicSharedMemorySize, (int)smemA);
    cudaFuncSetAttribute(kernelC,     cudaFuncAttributeMaxDynamicSharedMemorySize, (int)smemC);
    cudaFuncSetAttribute(kernelB_mma, cudaFuncAttributeMaxDynamicSharedMemorySize, (int)smemB);

    prep_all<<<dim3(CC, 4), CC>>>(Wl, ln_l_g, ln_l_b, bl,
                                  Wr, ln_r_g, ln_r_b, br,
                                  Wg, Wo,
                                  pWl, pWr, pWg, pWo, pbLE, pbRE, pWgS);

    kernelA<<<MTOT/128, T, smemA>>>(pair, bg);
    kernelB_mma<<<dim3(NN/128, NN/128, CC), T, smemB>>>();
    kernelC<<<MTOT/128, T, smemC>>>(pair, bo, n_g, n_b, out);
}

// round 15
// speedup vs baseline: 2.0558x; 1.0393x over previous
#include <cuda_runtime.h>
#include <cuda_fp16.h>
#include <math.h>

// Problem constants (fixed by dataset): B=1, N=384, C=H=128
#define NN   384
#define CC   128
#define MTOT (NN*NN)
#define EPS  1e-5f
#define XPAD 136      // data plane row stride (fp16 elems)
#define BPAD 136      // weight / right row stride (fp16 elems)
#define APAD 72       // kernelB left-tile row stride (fp16 elems)
#define T    512      // threads per block (16 warps)

// ---------------- scratch ------------------------------------------------------
__device__ __half g_leftH [(size_t)CC * MTOT];   // [h][i][k]
__device__ __half g_rightH[(size_t)CC * MTOT];   // [h][k][j]
__device__ __half g_gateh [(size_t)CC * MTOT];   // [h][i*N+j] fp16 sigmoid
__device__ __half g_v     [(size_t)CC * MTOT];   // [h][i*N+j] fp16 out*gate
__device__ __half g_Wl[CC*CC], g_Wr[CC*CC], g_Wg[CC*CC], g_Wo[CC*CC];
__device__ float g_bLE[CC], g_bRE[CC], g_WgS[CC];

// ---------------- helpers (baseline PTX only) ----------------------------------
__device__ __forceinline__ unsigned smem_u32(const void* p) {
    return (unsigned)__cvta_generic_to_shared(p);
}
__device__ __forceinline__ void cp16(unsigned saddr, const void* g) {
    asm volatile("cp.async.cg.shared.global [%0], [%1], 16;" :: "r"(saddr), "l"(g));
}
__device__ __forceinline__ void cp_commit() {
    asm volatile("cp.async.commit_group;" ::: "memory");
}
template<int N>
__device__ __forceinline__ void cp_wait() {
    asm volatile("cp.async.wait_group %0;" :: "n"(N) : "memory");
}
__device__ __forceinline__ void ldmx4(unsigned r[4], unsigned addr) {
    asm volatile("ldmatrix.sync.aligned.m8n8.x4.shared.b16 {%0,%1,%2,%3}, [%4];"
        : "=r"(r[0]), "=r"(r[1]), "=r"(r[2]), "=r"(r[3]) : "r"(addr));
}
__device__ __forceinline__ void ldmx4t(unsigned r[4], unsigned addr) {
    asm volatile("ldmatrix.sync.aligned.m8n8.x4.trans.shared.b16 {%0,%1,%2,%3}, [%4];"
        : "=r"(r[0]), "=r"(r[1]), "=r"(r[2]), "=r"(r[3]) : "r"(addr));
}
__device__ __forceinline__ void mma16816(float d[4], const unsigned a[4],
                                         unsigned b0, unsigned b1) {
    asm volatile(
        "mma.sync.aligned.m16n8k16.row.col.f32.f16.f16.f32 "
        "{%0,%1,%2,%3}, {%4,%5,%6,%7}, {%8,%9}, {%0,%1,%2,%3};"
        : "+f"(d[0]), "+f"(d[1]), "+f"(d[2]), "+f"(d[3])
        : "r"(a[0]), "r"(a[1]), "r"(a[2]), "r"(a[3]), "r"(b0), "r"(b1));
}

// ---------------- fused prep kernel (one launch) --------------------------------
__global__ void prep_all(const float* __restrict__ Wl,
                         const float* __restrict__ lgl, const float* __restrict__ lbl,
                         const float* __restrict__ bl,
                         const float* __restrict__ Wr,
                         const float* __restrict__ lgr, const float* __restrict__ lbr,
                         const float* __restrict__ br,
                         const float* __restrict__ Wg,
                         const float* __restrict__ Wo,
                         __half* __restrict__ pWl, __half* __restrict__ pWr,
                         __half* __restrict__ pWg, __half* __restrict__ pWo,
                         float* __restrict__ bLE, float* __restrict__ bRE,
                         float* __restrict__ WgS)
{
    int k = blockIdx.x, n = threadIdx.x, which = blockIdx.y;
    if (which == 0) {
        pWl[k*CC + n] = __float2half_rn(lgl[k] * Wl[k*CC + n]);
        if (k == 0) {
            float s = bl[n];
            for (int kk = 0; kk < CC; kk++) s += lbl[kk] * Wl[kk*CC + n];
            bLE[n] = s;
        }
    } else if (which == 1) {
        pWr[k*CC + n] = __float2half_rn(lgr[k] * Wr[k*CC + n]);
        if (k == 0) {
            float s = br[n];
            for (int kk = 0; kk < CC; kk++) s += lbr[kk] * Wr[kk*CC + n];
            bRE[n] = s;
        }
    } else if (which == 2) {
        pWg[k*CC + n] = __float2half_rn(Wg[k*CC + n]);
        if (k == 0) {
            float s = 0.f;
            for (int kk = 0; kk < CC; kk++) s += Wg[kk*CC + n];
            WgS[n] = s;
        }
    } else {
        pWo[k*CC + n] = __float2half_rn(Wo[k*CC + n]);
    }
}

// ---------------- HMMA projection GEMM: 32x32 warp tiles -----------------------
__device__ __forceinline__ void hmma_proj(
    const __half* __restrict__ aP,
    const __half* __restrict__ W,
    __half* __restrict__ wst,
    float acc[2][4][4],
    int tid, int wm, int wn,
    int a_row, int a_kh, int b_kr, int b_nc)
{
    const int PLANE = 64*BPAD;
#pragma unroll
    for (int mi = 0; mi < 2; mi++)
#pragma unroll
        for (int nj = 0; nj < 4; nj++)
#pragma unroll
            for (int q = 0; q < 4; q++) acc[mi][nj][q] = 0.f;

#pragma unroll
    for (int s = 0; s < 2; s++) {
        __half* d = wst + s*PLANE;
        int k0 = s*64;
#pragma unroll
        for (int t = 0; t < 2; t++) {
            int idx = tid + t*T;            // 0..1023 (64 rows x 16 chunks)
            int r = idx >> 4, c = idx & 15;
            cp16(smem_u32(d + r*BPAD + c*8), W + (k0 + r)*CC + c*8);
        }
        cp_commit();
    }

#pragma unroll
    for (int s = 0; s < 2; s++) {
        if (s == 0) cp_wait<1>(); else cp_wait<0>();
        __syncthreads();
        const __half* bP = wst + s*PLANE;
        int k0 = s*64;
#pragma unroll
        for (int kk = 0; kk < 64; kk += 16) {
            unsigned aF[2][4];
#pragma unroll
            for (int mi = 0; mi < 2; mi++)
                ldmx4(aF[mi], smem_u32(aP + (wm + mi*16 + a_row)*XPAD + k0 + kk + a_kh));
#pragma unroll
            for (int nh = 0; nh < 2; nh++) {
                unsigned bF[4];
                ldmx4t(bF, smem_u32(bP + (kk + b_kr)*BPAD + wn + nh*16 + b_nc));
#pragma unroll
                for (int mi = 0; mi < 2; mi++) {
                    mma16816(acc[mi][nh*2 + 0], aF[mi], bF[0], bF[1]);
                    mma16816(acc[mi][nh*2 + 1], aF[mi], bF[2], bF[3]);
                }
            }
        }
    }
    __syncthreads();   // all wst reads done before caller reuses the region
}

// fragment -> transposed channel-major, single fp16 plane (staged, coalesced)
__device__ __forceinline__ void frag_store_half(
    const float acc[2][4][4], const float* __restrict__ bias,
    unsigned* __restrict__ stage,
    __half* __restrict__ dstH,
    size_t R0, int lane, int wm, int wn, int tid)
{
#pragma unroll
    for (int mi = 0; mi < 2; mi++) {
        int r = wm + mi*16 + (lane >> 2);
#pragma unroll
        for (int nj = 0; nj < 4; nj++) {
            int c = wn + nj*8 + (lane & 3)*2;
            float b0 = __ldg(bias + c), b1 = __ldg(bias + c + 1);
            stage[c*129 + r]       = (unsigned)__half_as_ushort(__float2half_rn(acc[mi][nj][0] + b0));
            stage[(c+1)*129 + r]   = (unsigned)__half_as_ushort(__float2half_rn(acc[mi][nj][1] + b1));
            stage[c*129 + r+8]     = (unsigned)__half_as_ushort(__float2half_rn(acc[mi][nj][2] + b0));
            stage[(c+1)*129 + r+8] = (unsigned)__half_as_ushort(__float2half_rn(acc[mi][nj][3] + b1));
        }
    }
    __syncthreads();
    for (int idx = tid; idx < 128*64; idx += T) {
        int n = idx >> 6, r2 = idx & 63;
        unsigned w0 = stage[n*129 + 2*r2], w1 = stage[n*129 + 2*r2 + 1];
        unsigned hw = (w0 & 0xFFFFu) | (w1 << 16);
        *reinterpret_cast<unsigned*>(dstH + (size_t)n*MTOT + R0 + 2*r2) = hw;
    }
    __syncthreads();
}

// gate: logit = sd[r]*acc + mu[r]*S[c] + bg[c]; sigmoid; fp16 channel-major
__device__ __forceinline__ void frag_store_gate(
    const float acc[2][4][4], const float* __restrict__ bg,
    const float* __restrict__ Sg,
    const float* __restrict__ sd_s, const float* __restrict__ mu_s,
    float* __restrict__ stage, __half* __restrict__ dst,
    size_t R0, int lane, int wm, int wn, int tid)
{
#pragma unroll
    for (int mi = 0; mi < 2; mi++) {
        int r = wm + mi*16 + (lane >> 2);
        float sd0 = sd_s[r], mu0 = mu_s[r];
        float sd1 = sd_s[r+8], mu1 = mu_s[r+8];
#pragma unroll
        for (int nj = 0; nj < 4; nj++) {
            int c = wn + nj*8 + (lane & 3)*2;
            float S0 = __ldg(Sg + c) , B0 = __ldg(bg + c);
            float S1 = __ldg(Sg + c+1), B1 = __ldg(bg + c+1);
            float z;
            z = sd0*acc[mi][nj][0] + mu0*S0 + B0; stage[c*129 + r]       = 1.f/(1.f+expf(-z));
            z = sd0*acc[mi][nj][1] + mu0*S1 + B1; stage[(c+1)*129 + r]   = 1.f/(1.f+expf(-z));
            z = sd1*acc[mi][nj][2] + mu1*S0 + B0; stage[c*129 + r+8]     = 1.f/(1.f+expf(-z));
            z = sd1*acc[mi][nj][3] + mu1*S1 + B1; stage[(c+1)*129 + r+8] = 1.f/(1.f+expf(-z));
        }
    }
    __syncthreads();
    for (int idx = tid; idx < 128*64; idx += T) {
        int n = idx >> 6, r2 = idx & 63;
        __half h0 = __float2half_rn(stage[n*129 + 2*r2]);
        __half h1 = __float2half_rn(stage[n*129 + 2*r2 + 1]);
        unsigned hw = (unsigned)__half_as_ushort(h0) | ((unsigned)__half_as_ushort(h1) << 16);
        *reinterpret_cast<unsigned*>(dst + (size_t)n*MTOT + R0 + 2*r2) = hw;
    }
    __syncthreads();
}

// ---------------- kernel A: LN + 3 projections ---------------------------------
// smem (102400 B, 2 CTAs/SM): xh 34816 | stage 66048 (wst alias) | stats
__global__ void __launch_bounds__(T, 2)
kernelA(const float* __restrict__ pair,
        const float* __restrict__ bg)
{
    extern __shared__ __align__(16) char smA[];
    __half* xh  = (__half*)smA;                    // [128][XPAD]
    char* stg = smA + 34816;                       // stage region (66048 B)
    __half* wst = (__half*)stg;                    // aliases stage
    unsigned* stageU = (unsigned*)stg;
    float*    stageF = (float*)stg;
    float* mu_s = (float*)(smA + 100864);
    float* rs_s = mu_s + 128;
    float* sd_s = rs_s + 128;

    const int tid = threadIdx.x;
    const int lane = tid & 31, wid = tid >> 5;
    const int wm = (wid & 3)*32, wn = (wid >> 2)*32;
    const int a_row = (lane & 7) + ((lane >> 3) & 1)*8;
    const int a_kh  = (lane >> 4)*8;
    const int b_kr  = (lane & 7) + ((lane >> 3) & 1)*8;
    const int b_nc  = (lane >> 4)*8;
    const size_t R0 = (size_t)blockIdx.x * 128;

    // LN stats: warp per 8 rows, coalesced global float4 read + shuffle reduce
#pragma unroll
    for (int rr = 0; rr < 8; rr++) {
        int r = wid*8 + rr;
        float4 v = *reinterpret_cast<const float4*>(pair + (R0 + r)*CC + lane*4);
        float s  = v.x + v.y + v.z + v.w;
        float s2 = v.x*v.x + v.y*v.y + v.z*v.z + v.w*v.w;
#pragma unroll
        for (int off = 16; off > 0; off >>= 1) {
            s  += __shfl_xor_sync(0xffffffffu, s,  off);
            s2 += __shfl_xor_sync(0xffffffffu, s2, off);
        }
        if (lane == 0) {
            float mu  = s * (1.f/128.f);
            float var = fmaxf(s2 * (1.f/128.f) - mu*mu, 0.f) + EPS;
            mu_s[r] = mu;
            rs_s[r] = rsqrtf(var);
            sd_s[r] = sqrtf(var);
        }
    }
    __syncthreads();

    // xhat -> single fp16 plane (pair re-read is L2-hot)
    for (int i = tid; i < 128*32; i += T) {
        int r = i >> 5, c4 = i & 31;
        float4 v = *reinterpret_cast<const float4*>(pair + (R0 + r)*CC + c4*4);
        float mu = mu_s[r], rs = rs_s[r];
        __half2 h0 = __floats2half2_rn((v.x - mu)*rs, (v.y - mu)*rs);
        __half2 h1 = __floats2half2_rn((v.z - mu)*rs, (v.w - mu)*rs);
        *reinterpret_cast<uint2*>(xh + r*XPAD + c4*4) =
            make_uint2(*(unsigned*)&h0, *(unsigned*)&h1);
    }
    // hmma_proj's internal sync (post cp_wait) orders plane writes before ldmatrix

    float acc[2][4][4];
    hmma_proj(xh, g_Wl, wst, acc, tid, wm, wn, a_row, a_kh, b_kr, b_nc);
    frag_store_half(acc, g_bLE, stageU, g_leftH, R0, lane, wm, wn, tid);
    hmma_proj(xh, g_Wr, wst, acc, tid, wm, wn, a_row, a_kh, b_kr, b_nc);
    frag_store_half(acc, g_bRE, stageU, g_rightH, R0, lane, wm, wn, tid);
    hmma_proj(xh, g_Wg, wst, acc, tid, wm, wn, a_row, a_kh, b_kr, b_nc);
    frag_store_gate(acc, bg, g_WgS, sd_s, mu_s, stageF, g_gateh, R0, lane, wm, wn, tid);
}

// ---------------- kernel B: per-channel 384^3 GEMM + fused gate, 3-stage -------
#define KB_STG (128*APAD + 64*BPAD)   // fp16 elements per stage (17920)

__device__ __forceinline__ void kb_prefetch(
    __half* st,
    const __half* __restrict__ AgH,
    const __half* __restrict__ BgH,
    int k0, int tid)
{
    __half* aH = st;
    __half* bH = st + 128*APAD;
#pragma unroll
    for (int t = 0; t < 2; t++) {
        int idx = tid + t*T;                // 0..1023 (128 rows x 8 chunks)
        int r = idx >> 3, c = idx & 7;
        cp16(smem_u32(aH + r*APAD + c*8), AgH + (size_t)r*NN + k0 + c*8);
    }
#pragma unroll
    for (int t = 0; t < 2; t++) {
        int idx = tid + t*T;                // 0..1023 (64 rows x 16 chunks)
        int r = idx >> 4, c = idx & 15;
        cp16(smem_u32(bH + r*BPAD + c*8), BgH + (size_t)(k0 + r)*NN + c*8);
    }
}

__global__ void __launch_bounds__(T, 2)
kernelB_mma()
{
    extern __shared__ __align__(16) __half smb[];
    const int tid  = threadIdx.x;
    const int lane = tid & 31, wid = tid >> 5;
    const int J0 = blockIdx.x*128, I0 = blockIdx.y*128, h = blockIdx.z;
    const int wm = (wid & 3)*32, wn = (wid >> 2)*32;

    const __half* __restrict__ AgH = g_leftH  + (size_t)h*MTOT + (size_t)I0*NN;
    const __half* __restrict__ BgH = g_rightH + (size_t)h*MTOT + J0;

    float acc[2][4][4];
#pragma unroll
    for (int mi = 0; mi < 2; mi++)
#pragma unroll
        for (int nj = 0; nj < 4; nj++)
#pragma unroll
            for (int q = 0; q < 4; q++) acc[mi][nj][q] = 0.f;

    const int a_row = (lane & 7) + ((lane >> 3) & 1)*8;
    const int a_kh  = (lane >> 4)*8;
    const int b_kr  = (lane & 7) + ((lane >> 3) & 1)*8;
    const int b_nc  = (lane >> 4)*8;

    kb_prefetch(smb + 0*KB_STG, AgH, BgH, 0,  tid); cp_commit();
    kb_prefetch(smb + 1*KB_STG, AgH, BgH, 64, tid); cp_commit();

    for (int ch = 0; ch < 6; ch++) {
        if (ch + 2 < 6) {
            kb_prefetch(smb + ((ch+2)%3)*KB_STG, AgH, BgH, (ch+2)*64, tid);
            cp_commit();
            cp_wait<2>();
        } else if (ch + 1 < 6) {
            cp_wait<1>();
        } else {
            cp_wait<0>();
        }
        __syncthreads();

        const __half* aH = smb + (ch%3)*KB_STG;
        const __half* bH = aH + 128*APAD;
#pragma unroll
        for (int kk = 0; kk < 64; kk += 16) {
            unsigned aF[2][4];
#pragma unroll
            for (int mi = 0; mi < 2; mi++)
                ldmx4(aF[mi], smem_u32(aH + (wm + mi*16 + a_row)*APAD + kk + a_kh));
#pragma unroll
            for (int nh = 0; nh < 2; nh++) {
                unsigned bF[4];
                ldmx4t(bF, smem_u32(bH + (kk + b_kr)*BPAD + wn + nh*16 + b_nc));
#pragma unroll
                for (int mi = 0; mi < 2; mi++) {
                    mma16816(acc[mi][nh*2 + 0], aF[mi], bF[0], bF[1]);
                    mma16816(acc[mi][nh*2 + 1], aF[mi], bF[2], bF[3]);
                }
            }
        }
        __syncthreads();
    }

    // epilogue: v = out * gate (contiguous windows per warp-row -> sectored)
    const __half* __restrict__ Gg = g_gateh + (size_t)h*MTOT;
    __half* __restrict__       Vd = g_v     + (size_t)h*MTOT;
#pragma unroll
    for (int mi = 0; mi < 2; mi++) {
        int r0 = I0 + wm + mi*16 + (lane >> 2);
#pragma unroll
        for (int nj = 0; nj < 4; nj++) {
            int c = J0 + wn + nj*8 + (lane & 3)*2;
            size_t o0 = (size_t)r0*NN + c;
            size_t o1 = (size_t)(r0+8)*NN + c;
            float2 ga0 = __half22float2(*reinterpret_cast<const __half2*>(Gg + o0));
            float2 ga1 = __half22float2(*reinterpret_cast<const __half2*>(Gg + o1));
            *reinterpret_cast<__half2*>(Vd + o0) =
                __floats2half2_rn(acc[mi][nj][0]*ga0.x, acc[mi][nj][1]*ga0.y);
            *reinterpret_cast<__half2*>(Vd + o1) =
                __floats2half2_rn(acc[mi][nj][2]*ga1.x, acc[mi][nj][3]*ga1.y);
        }
    }
}

// ---------------- kernel C: v @ Wo + bo + residual + LN ------------------------
// smem (101888 B, 2 CTAs/SM): vP 34816 | y_s 66048 (wst alias) | stats
__global__ void __launch_bounds__(T, 2)
kernelC(const float* __restrict__ pair,
        const float* __restrict__ bo,
        const float* __restrict__ ng,
        const float* __restrict__ nb,
        float* __restrict__ out)
{
    extern __shared__ __align__(16) char smC[];
    __half* vP  = (__half*)smC;                    // [128][XPAD]
    float* y_s  = (float*)(smC + 34816);           // [128][129]
    __half* wst = (__half*)(smC + 34816);          // aliases y_s
    float* mu_s = (float*)(smC + 100864);
    float* rs_s = mu_s + 128;

    const int tid = threadIdx.x;
    const int lane = tid & 31, wid = tid >> 5;
    const int wm = (wid & 3)*32, wn = (wid >> 2)*32;
    const int a_row = (lane & 7) + ((lane >> 3) & 1)*8;
    const int a_kh  = (lane >> 4)*8;
    const int b_kr  = (lane & 7) + ((lane >> 3) & 1)*8;
    const int b_nc  = (lane >> 4)*8;
    const size_t IJ0 = (size_t)blockIdx.x * 128;

    // v (fp16, channel-major) -> y_s transposed staging (R13 pattern: r is the
    // fast thread index -> stride-129 STS, conflict-free; coalesced LDG)
    for (int i = tid; i < 128*128; i += T) {
        int h = i >> 7, r = i & 127;
        y_s[r*129 + h] = __half2float(g_v[(size_t)h * MTOT + IJ0 + r]);
    }
    __syncthreads();
    // y_s -> single fp16 plane
    for (int i = tid; i < 128*64; i += T) {
        int r = i >> 6, c2 = i & 63;
        __half2 h2 = __floats2half2_rn(y_s[r*129 + 2*c2], y_s[r*129 + 2*c2 + 1]);
        *reinterpret_cast<unsigned*>(vP + r*XPAD + 2*c2) = *(unsigned*)&h2;
    }
    __syncthreads();   // all y_s reads done before hmma_proj's cp.async hits the alias

    float acc[2][4][4];
    hmma_proj(vP, g_Wo, wst, acc, tid, wm, wn, a_row, a_kh, b_kr, b_nc);

    // y = acc + bo + pair residual -> y_s (wst dead again)
#pragma unroll
    for (int mi = 0; mi < 2; mi++) {
        int r = wm + mi*16 + (lane >> 2);
#pragma unroll
        for (int nj = 0; nj < 4; nj++) {
            int c = wn + nj*8 + (lane & 3)*2;
            float b0 = __ldg(bo + c), b1 = __ldg(bo + c + 1);
            float2 p0 = *reinterpret_cast<const float2*>(pair + (IJ0 + r)*CC + c);
            float2 p1 = *reinterpret_cast<const float2*>(pair + (IJ0 + r + 8)*CC + c);
            y_s[r*129 + c]       = acc[mi][nj][0] + b0 + p0.x;
            y_s[r*129 + c+1]     = acc[mi][nj][1] + b1 + p0.y;
            y_s[(r+8)*129 + c]   = acc[mi][nj][2] + b0 + p1.x;
            y_s[(r+8)*129 + c+1] = acc[mi][nj][3] + b1 + p1.y;
        }
    }
    __syncthreads();

    // row LN: warp per 8 rows via shuffle — SCALAR smem loads (516B row stride)
#pragma unroll
    for (int rr = 0; rr < 8; rr++) {
        int r = wid*8 + rr;
        const float* row = y_s + r*129 + lane*4;
        float v0 = row[0], v1 = row[1], v2 = row[2], v3 = row[3];
        float s  = v0 + v1 + v2 + v3;
        float s2 = v0*v0 + v1*v1 + v2*v2 + v3*v3;
#pragma unroll
        for (int off = 16; off > 0; off >>= 1) {
            s  += __shfl_xor_sync(0xffffffffu, s,  off);
            s2 += __shfl_xor_sync(0xffffffffu, s2, off);
        }
        if (lane == 0) {
            float mu  = s * (1.f/128.f);
            float var = fmaxf(s2 * (1.f/128.f) - mu*mu, 0.f) + EPS;
            mu_s[r] = mu;
            rs_s[r] = rsqrtf(var);
        }
    }
    __syncthreads();

    // final: LN apply, scalar per-element (R13 pattern: c fast -> conflict-free,
    // coalesced fp32 STG)
    for (int i = tid; i < 128*128; i += T) {
        int r = i >> 7, c = i & 127;
        float z = y_s[r*129 + c];
        out[(IJ0 + r)*CC + c] = (z - mu_s[r]) * rs_s[r] * __ldg(ng + c) + __ldg(nb + c);
    }
}

// ---------------- launch --------------------------------------------------------
extern "C" void kernel_launch(void* const* d_in, const int* in_sizes, int n_in,
                              void* d_out, int out_size)
{
    const float* pair   = (const float*)d_in[0];
    const float* ln_l_g = (const float*)d_in[1];
    const float* ln_l_b = (const float*)d_in[2];
    const float* ln_r_g = (const float*)d_in[3];
    const float* ln_r_b = (const float*)d_in[4];
    const float* Wl     = (const float*)d_in[5];
    const float* bl     = (const float*)d_in[6];
    const float* Wr     = (const float*)d_in[7];
    const float* br     = (const float*)d_in[8];
    const float* Wg     = (const float*)d_in[9];
    const float* bg     = (const float*)d_in[10];
    const float* Wo     = (const float*)d_in[11];
    const float* bo     = (const float*)d_in[12];
    const float* n_g    = (const float*)d_in[13];
    const float* n_b    = (const float*)d_in[14];
    float* out = (float*)d_out;

    static __half *pWl = nullptr, *pWr, *pWg, *pWo;
    static float *pbLE, *pbRE, *pWgS;
    if (!pWl) {
        cudaGetSymbolAddress((void**)&pWl, g_Wl);
        cudaGetSymbolAddress((void**)&pWr, g_Wr);
        cudaGetSymbolAddress((void**)&pWg, g_Wg);
        cudaGetSymbolAddress((void**)&pWo, g_Wo);
        cudaGetSymbolAddress((void**)&pbLE, g_bLE);
        cudaGetSymbolAddress((void**)&pbRE, g_bRE);
        cudaGetSymbolAddress((void**)&pWgS, g_WgS);
    }

    const size_t smemA = 102400;
    const size_t smemC = 101888;
    const size_t smemB = (size_t)3*KB_STG*sizeof(__half);   // 107520
    cudaFuncSetAttribute(kernelA,     cudaFuncAttributeMaxDynamicSharedMemorySize, (int)smemA);
    cudaFuncSetAttribute(kernelC,     cudaFuncAttributeMaxDynamicSharedMemorySize, (int)smemC);
    cudaFuncSetAttribute(kernelB_mma, cudaFuncAttributeMaxDynamicSharedMemorySize, (int)smemB);

    prep_all<<<dim3(CC, 4), CC>>>(Wl, ln_l_g, ln_l_b, bl,
                                  Wr, ln_r_g, ln_r_b, br,
                                  Wg, Wo,
                                  pWl, pWr, pWg, pWo, pbLE, pbRE, pWgS);

    kernelA<<<MTOT/128, T, smemA>>>(pair, bg);
    kernelB_mma<<<dim3(NN/128, NN/128, CC), T, smemB>>>();
    kernelC<<<MTOT/128, T, smemC>>>(pair, bo, n_g, n_b, out);
}

// round 16
// speedup vs baseline: 2.1663x; 1.0538x over previous
#include <cuda_runtime.h>
#include <cuda_fp16.h>
#include <math.h>

// Problem constants (fixed by dataset): B=1, N=384, C=H=128
#define NN   384
#define CC   128
#define MTOT (NN*NN)
#define EPS  1e-5f
#define XPAD 136      // data plane row stride (fp16 elems)
#define BPAD 136      // weight / right row stride (fp16 elems)
#define APAD 72       // kernelB left-tile row stride (fp16 elems)
#define T    512      // threads per block (16 warps)

// ---------------- scratch ------------------------------------------------------
__device__ __half g_leftH [(size_t)CC * MTOT];   // [h][i][k]
__device__ __half g_rightH[(size_t)CC * MTOT];   // [h][k][j]
__device__ __half g_gateh [(size_t)CC * MTOT];   // [h][i*N+j] fp16 sigmoid
__device__ __half g_v     [(size_t)CC * MTOT];   // [h][i*N+j] fp16 out*gate
__device__ __half g_Wl[CC*CC], g_Wr[CC*CC], g_Wg[CC*CC], g_Wo[CC*CC];
__device__ float g_bLE[CC], g_bRE[CC], g_WgS[CC];

// ---------------- helpers (baseline PTX only) ----------------------------------
__device__ __forceinline__ unsigned smem_u32(const void* p) {
    return (unsigned)__cvta_generic_to_shared(p);
}
__device__ __forceinline__ void cp16(unsigned saddr, const void* g) {
    asm volatile("cp.async.cg.shared.global [%0], [%1], 16;" :: "r"(saddr), "l"(g));
}
__device__ __forceinline__ void cp_commit() {
    asm volatile("cp.async.commit_group;" ::: "memory");
}
template<int N>
__device__ __forceinline__ void cp_wait() {
    asm volatile("cp.async.wait_group %0;" :: "n"(N) : "memory");
}
__device__ __forceinline__ void ldmx4(unsigned r[4], unsigned addr) {
    asm volatile("ldmatrix.sync.aligned.m8n8.x4.shared.b16 {%0,%1,%2,%3}, [%4];"
        : "=r"(r[0]), "=r"(r[1]), "=r"(r[2]), "=r"(r[3]) : "r"(addr));
}
__device__ __forceinline__ void ldmx4t(unsigned r[4], unsigned addr) {
    asm volatile("ldmatrix.sync.aligned.m8n8.x4.trans.shared.b16 {%0,%1,%2,%3}, [%4];"
        : "=r"(r[0]), "=r"(r[1]), "=r"(r[2]), "=r"(r[3]) : "r"(addr));
}
__device__ __forceinline__ void mma16816(float d[4], const unsigned a[4],
                                         unsigned b0, unsigned b1) {
    asm volatile(
        "mma.sync.aligned.m16n8k16.row.col.f32.f16.f16.f32 "
        "{%0,%1,%2,%3}, {%4,%5,%6,%7}, {%8,%9}, {%0,%1,%2,%3};"
        : "+f"(d[0]), "+f"(d[1]), "+f"(d[2]), "+f"(d[3])
        : "r"(a[0]), "r"(a[1]), "r"(a[2]), "r"(a[3]), "r"(b0), "r"(b1));
}

// ---------------- fused prep kernel (one launch) --------------------------------
__global__ void prep_all(const float* __restrict__ Wl,
                         const float* __restrict__ lgl, const float* __restrict__ lbl,
                         const float* __restrict__ bl,
                         const float* __restrict__ Wr,
                         const float* __restrict__ lgr, const float* __restrict__ lbr,
                         const float* __restrict__ br,
                         const float* __restrict__ Wg,
                         const float* __restrict__ Wo,
                         __half* __restrict__ pWl, __half* __restrict__ pWr,
                         __half* __restrict__ pWg, __half* __restrict__ pWo,
                         float* __restrict__ bLE, float* __restrict__ bRE,
                         float* __restrict__ WgS)
{
    int k = blockIdx.x, n = threadIdx.x, which = blockIdx.y;
    if (which == 0) {
        pWl[k*CC + n] = __float2half_rn(lgl[k] * Wl[k*CC + n]);
        if (k == 0) {
            float s = bl[n];
            for (int kk = 0; kk < CC; kk++) s += lbl[kk] * Wl[kk*CC + n];
            bLE[n] = s;
        }
    } else if (which == 1) {
        pWr[k*CC + n] = __float2half_rn(lgr[k] * Wr[k*CC + n]);
        if (k == 0) {
            float s = br[n];
            for (int kk = 0; kk < CC; kk++) s += lbr[kk] * Wr[kk*CC + n];
            bRE[n] = s;
        }
    } else if (which == 2) {
        pWg[k*CC + n] = __float2half_rn(Wg[k*CC + n]);
        if (k == 0) {
            float s = 0.f;
            for (int kk = 0; kk < CC; kk++) s += Wg[kk*CC + n];
            WgS[n] = s;
        }
    } else {
        pWo[k*CC + n] = __float2half_rn(Wo[k*CC + n]);
    }
}

// ---------------- HMMA projection GEMM: 32x32 warp tiles, row-major A ----------
__device__ __forceinline__ void hmma_proj(
    const __half* __restrict__ aP,
    const __half* __restrict__ W,
    __half* __restrict__ wst,
    float acc[2][4][4],
    int tid, int wm, int wn,
    int a_row, int a_kh, int b_kr, int b_nc)
{
    const int PLANE = 64*BPAD;
#pragma unroll
    for (int mi = 0; mi < 2; mi++)
#pragma unroll
        for (int nj = 0; nj < 4; nj++)
#pragma unroll
            for (int q = 0; q < 4; q++) acc[mi][nj][q] = 0.f;

#pragma unroll
    for (int s = 0; s < 2; s++) {
        __half* d = wst + s*PLANE;
        int k0 = s*64;
#pragma unroll
        for (int t = 0; t < 2; t++) {
            int idx = tid + t*T;            // 0..1023 (64 rows x 16 chunks)
            int r = idx >> 4, c = idx & 15;
            cp16(smem_u32(d + r*BPAD + c*8), W + (k0 + r)*CC + c*8);
        }
        cp_commit();
    }

#pragma unroll
    for (int s = 0; s < 2; s++) {
        if (s == 0) cp_wait<1>(); else cp_wait<0>();
        __syncthreads();
        const __half* bP = wst + s*PLANE;
        int k0 = s*64;
#pragma unroll
        for (int kk = 0; kk < 64; kk += 16) {
            unsigned aF[2][4];
#pragma unroll
            for (int mi = 0; mi < 2; mi++)
                ldmx4(aF[mi], smem_u32(aP + (wm + mi*16 + a_row)*XPAD + k0 + kk + a_kh));
#pragma unroll
            for (int nh = 0; nh < 2; nh++) {
                unsigned bF[4];
                ldmx4t(bF, smem_u32(bP + (kk + b_kr)*BPAD + wn + nh*16 + b_nc));
#pragma unroll
                for (int mi = 0; mi < 2; mi++) {
                    mma16816(acc[mi][nh*2 + 0], aF[mi], bF[0], bF[1]);
                    mma16816(acc[mi][nh*2 + 1], aF[mi], bF[2], bF[3]);
                }
            }
        }
    }
    __syncthreads();   // all wst reads done before caller reuses the region
}

// ---------------- HMMA projection GEMM variant: K-major A (trans fragments) ----
// aT is stored [k][m] (k rows, stride XPAD). A fragments via ldmatrix.trans:
// lane map: k_off = (lane&7) + ((lane>>4)&1)*8, m_off = ((lane>>3)&1)*8.
__device__ __forceinline__ void hmma_projT(
    const __half* __restrict__ aT,
    const __half* __restrict__ W,
    __half* __restrict__ wst,
    float acc[2][4][4],
    int tid, int wm, int wn,
    int at_kr, int at_mc, int b_kr, int b_nc)
{
    const int PLANE = 64*BPAD;
#pragma unroll
    for (int mi = 0; mi < 2; mi++)
#pragma unroll
        for (int nj = 0; nj < 4; nj++)
#pragma unroll
            for (int q = 0; q < 4; q++) acc[mi][nj][q] = 0.f;

#pragma unroll
    for (int s = 0; s < 2; s++) {
        __half* d = wst + s*PLANE;
        int k0 = s*64;
#pragma unroll
        for (int t = 0; t < 2; t++) {
            int idx = tid + t*T;
            int r = idx >> 4, c = idx & 15;
            cp16(smem_u32(d + r*BPAD + c*8), W + (k0 + r)*CC + c*8);
        }
        cp_commit();
    }

#pragma unroll
    for (int s = 0; s < 2; s++) {
        if (s == 0) cp_wait<1>(); else cp_wait<0>();
        __syncthreads();
        const __half* bP = wst + s*PLANE;
        int k0 = s*64;
#pragma unroll
        for (int kk = 0; kk < 64; kk += 16) {
            unsigned aF[2][4];
#pragma unroll
            for (int mi = 0; mi < 2; mi++)
                ldmx4t(aF[mi], smem_u32(aT + (k0 + kk + at_kr)*XPAD + wm + mi*16 + at_mc));
#pragma unroll
            for (int nh = 0; nh < 2; nh++) {
                unsigned bF[4];
                ldmx4t(bF, smem_u32(bP + (kk + b_kr)*BPAD + wn + nh*16 + b_nc));
#pragma unroll
                for (int mi = 0; mi < 2; mi++) {
                    mma16816(acc[mi][nh*2 + 0], aF[mi], bF[0], bF[1]);
                    mma16816(acc[mi][nh*2 + 1], aF[mi], bF[2], bF[3]);
                }
            }
        }
    }
    __syncthreads();
}

// fragment -> transposed channel-major, single fp16 plane (staged, coalesced)
__device__ __forceinline__ void frag_store_half(
    const float acc[2][4][4], const float* __restrict__ bias,
    unsigned* __restrict__ stage,
    __half* __restrict__ dstH,
    size_t R0, int lane, int wm, int wn, int tid)
{
#pragma unroll
    for (int mi = 0; mi < 2; mi++) {
        int r = wm + mi*16 + (lane >> 2);
#pragma unroll
        for (int nj = 0; nj < 4; nj++) {
            int c = wn + nj*8 + (lane & 3)*2;
            float b0 = __ldg(bias + c), b1 = __ldg(bias + c + 1);
            stage[c*129 + r]       = (unsigned)__half_as_ushort(__float2half_rn(acc[mi][nj][0] + b0));
            stage[(c+1)*129 + r]   = (unsigned)__half_as_ushort(__float2half_rn(acc[mi][nj][1] + b1));
            stage[c*129 + r+8]     = (unsigned)__half_as_ushort(__float2half_rn(acc[mi][nj][2] + b0));
            stage[(c+1)*129 + r+8] = (unsigned)__half_as_ushort(__float2half_rn(acc[mi][nj][3] + b1));
        }
    }
    __syncthreads();
    for (int idx = tid; idx < 128*64; idx += T) {
        int n = idx >> 6, r2 = idx & 63;
        unsigned w0 = stage[n*129 + 2*r2], w1 = stage[n*129 + 2*r2 + 1];
        unsigned hw = (w0 & 0xFFFFu) | (w1 << 16);
        *reinterpret_cast<unsigned*>(dstH + (size_t)n*MTOT + R0 + 2*r2) = hw;
    }
    __syncthreads();
}

// gate: logit = sd[r]*acc + mu[r]*S[c] + bg[c]; sigmoid; fp16 channel-major
__device__ __forceinline__ void frag_store_gate(
    const float acc[2][4][4], const float* __restrict__ bg,
    const float* __restrict__ Sg,
    const float* __restrict__ sd_s, const float* __restrict__ mu_s,
    float* __restrict__ stage, __half* __restrict__ dst,
    size_t R0, int lane, int wm, int wn, int tid)
{
#pragma unroll
    for (int mi = 0; mi < 2; mi++) {
        int r = wm + mi*16 + (lane >> 2);
        float sd0 = sd_s[r], mu0 = mu_s[r];
        float sd1 = sd_s[r+8], mu1 = mu_s[r+8];
#pragma unroll
        for (int nj = 0; nj < 4; nj++) {
            int c = wn + nj*8 + (lane & 3)*2;
            float S0 = __ldg(Sg + c) , B0 = __ldg(bg + c);
            float S1 = __ldg(Sg + c+1), B1 = __ldg(bg + c+1);
            float z;
            z = sd0*acc[mi][nj][0] + mu0*S0 + B0; stage[c*129 + r]       = 1.f/(1.f+expf(-z));
            z = sd0*acc[mi][nj][1] + mu0*S1 + B1; stage[(c+1)*129 + r]   = 1.f/(1.f+expf(-z));
            z = sd1*acc[mi][nj][2] + mu1*S0 + B0; stage[c*129 + r+8]     = 1.f/(1.f+expf(-z));
            z = sd1*acc[mi][nj][3] + mu1*S1 + B1; stage[(c+1)*129 + r+8] = 1.f/(1.f+expf(-z));
        }
    }
    __syncthreads();
    for (int idx = tid; idx < 128*64; idx += T) {
        int n = idx >> 6, r2 = idx & 63;
        __half h0 = __float2half_rn(stage[n*129 + 2*r2]);
        __half h1 = __float2half_rn(stage[n*129 + 2*r2 + 1]);
        unsigned hw = (unsigned)__half_as_ushort(h0) | ((unsigned)__half_as_ushort(h1) << 16);
        *reinterpret_cast<unsigned*>(dst + (size_t)n*MTOT + R0 + 2*r2) = hw;
    }
    __syncthreads();
}

// ---------------- kernel A: LN + 3 projections ---------------------------------
// smem (102400 B, 2 CTAs/SM): xh 34816 | stage 66048 (wst alias) | stats
__global__ void __launch_bounds__(T, 2)
kernelA(const float* __restrict__ pair,
        const float* __restrict__ bg)
{
    extern __shared__ __align__(16) char smA[];
    __half* xh  = (__half*)smA;                    // [128][XPAD]
    char* stg = smA + 34816;                       // stage region (66048 B)
    __half* wst = (__half*)stg;                    // aliases stage
    unsigned* stageU = (unsigned*)stg;
    float*    stageF = (float*)stg;
    float* mu_s = (float*)(smA + 100864);
    float* rs_s = mu_s + 128;
    float* sd_s = rs_s + 128;

    const int tid = threadIdx.x;
    const int lane = tid & 31, wid = tid >> 5;
    const int wm = (wid & 3)*32, wn = (wid >> 2)*32;
    const int a_row = (lane & 7) + ((lane >> 3) & 1)*8;
    const int a_kh  = (lane >> 4)*8;
    const int b_kr  = (lane & 7) + ((lane >> 3) & 1)*8;
    const int b_nc  = (lane >> 4)*8;
    const size_t R0 = (size_t)blockIdx.x * 128;

    // LN stats: warp per 8 rows, coalesced global float4 read + shuffle reduce
#pragma unroll
    for (int rr = 0; rr < 8; rr++) {
        int r = wid*8 + rr;
        float4 v = *reinterpret_cast<const float4*>(pair + (R0 + r)*CC + lane*4);
        float s  = v.x + v.y + v.z + v.w;
        float s2 = v.x*v.x + v.y*v.y + v.z*v.z + v.w*v.w;
#pragma unroll
        for (int off = 16; off > 0; off >>= 1) {
            s  += __shfl_xor_sync(0xffffffffu, s,  off);
            s2 += __shfl_xor_sync(0xffffffffu, s2, off);
        }
        if (lane == 0) {
            float mu  = s * (1.f/128.f);
            float var = fmaxf(s2 * (1.f/128.f) - mu*mu, 0.f) + EPS;
            mu_s[r] = mu;
            rs_s[r] = rsqrtf(var);
            sd_s[r] = sqrtf(var);
        }
    }
    __syncthreads();

    // xhat -> single fp16 plane (pair re-read is L2-hot)
    for (int i = tid; i < 128*32; i += T) {
        int r = i >> 5, c4 = i & 31;
        float4 v = *reinterpret_cast<const float4*>(pair + (R0 + r)*CC + c4*4);
        float mu = mu_s[r], rs = rs_s[r];
        __half2 h0 = __floats2half2_rn((v.x - mu)*rs, (v.y - mu)*rs);
        __half2 h1 = __floats2half2_rn((v.z - mu)*rs, (v.w - mu)*rs);
        *reinterpret_cast<uint2*>(xh + r*XPAD + c4*4) =
            make_uint2(*(unsigned*)&h0, *(unsigned*)&h1);
    }
    // hmma_proj's internal sync (post cp_wait) orders plane writes before ldmatrix

    float acc[2][4][4];
    hmma_proj(xh, g_Wl, wst, acc, tid, wm, wn, a_row, a_kh, b_kr, b_nc);
    frag_store_half(acc, g_bLE, stageU, g_leftH, R0, lane, wm, wn, tid);
    hmma_proj(xh, g_Wr, wst, acc, tid, wm, wn, a_row, a_kh, b_kr, b_nc);
    frag_store_half(acc, g_bRE, stageU, g_rightH, R0, lane, wm, wn, tid);
    hmma_proj(xh, g_Wg, wst, acc, tid, wm, wn, a_row, a_kh, b_kr, b_nc);
    frag_store_gate(acc, bg, g_WgS, sd_s, mu_s, stageF, g_gateh, R0, lane, wm, wn, tid);
}

// ---------------- kernel B: per-channel 384^3 GEMM + fused gate, 3-stage -------
#define KB_STG (128*APAD + 64*BPAD)   // fp16 elements per stage (17920)

__device__ __forceinline__ void kb_prefetch(
    __half* st,
    const __half* __restrict__ AgH,
    const __half* __restrict__ BgH,
    int k0, int tid)
{
    __half* aH = st;
    __half* bH = st + 128*APAD;
#pragma unroll
    for (int t = 0; t < 2; t++) {
        int idx = tid + t*T;                // 0..1023 (128 rows x 8 chunks)
        int r = idx >> 3, c = idx & 7;
        cp16(smem_u32(aH + r*APAD + c*8), AgH + (size_t)r*NN + k0 + c*8);
    }
#pragma unroll
    for (int t = 0; t < 2; t++) {
        int idx = tid + t*T;                // 0..1023 (64 rows x 16 chunks)
        int r = idx >> 4, c = idx & 15;
        cp16(smem_u32(bH + r*BPAD + c*8), BgH + (size_t)(k0 + r)*NN + c*8);
    }
}

__global__ void __launch_bounds__(T, 2)
kernelB_mma()
{
    extern __shared__ __align__(16) __half smb[];
    const int tid  = threadIdx.x;
    const int lane = tid & 31, wid = tid >> 5;
    const int J0 = blockIdx.x*128, I0 = blockIdx.y*128, h = blockIdx.z;
    const int wm = (wid & 3)*32, wn = (wid >> 2)*32;

    const __half* __restrict__ AgH = g_leftH  + (size_t)h*MTOT + (size_t)I0*NN;
    const __half* __restrict__ BgH = g_rightH + (size_t)h*MTOT + J0;

    float acc[2][4][4];
#pragma unroll
    for (int mi = 0; mi < 2; mi++)
#pragma unroll
        for (int nj = 0; nj < 4; nj++)
#pragma unroll
            for (int q = 0; q < 4; q++) acc[mi][nj][q] = 0.f;

    const int a_row = (lane & 7) + ((lane >> 3) & 1)*8;
    const int a_kh  = (lane >> 4)*8;
    const int b_kr  = (lane & 7) + ((lane >> 3) & 1)*8;
    const int b_nc  = (lane >> 4)*8;

    kb_prefetch(smb + 0*KB_STG, AgH, BgH, 0,  tid); cp_commit();
    kb_prefetch(smb + 1*KB_STG, AgH, BgH, 64, tid); cp_commit();

    for (int ch = 0; ch < 6; ch++) {
        if (ch + 2 < 6) {
            kb_prefetch(smb + ((ch+2)%3)*KB_STG, AgH, BgH, (ch+2)*64, tid);
            cp_commit();
            cp_wait<2>();
        } else if (ch + 1 < 6) {
            cp_wait<1>();
        } else {
            cp_wait<0>();
        }
        __syncthreads();

        const __half* aH = smb + (ch%3)*KB_STG;
        const __half* bH = aH + 128*APAD;
#pragma unroll
        for (int kk = 0; kk < 64; kk += 16) {
            unsigned aF[2][4];
#pragma unroll
            for (int mi = 0; mi < 2; mi++)
                ldmx4(aF[mi], smem_u32(aH + (wm + mi*16 + a_row)*APAD + kk + a_kh));
#pragma unroll
            for (int nh = 0; nh < 2; nh++) {
                unsigned bF[4];
                ldmx4t(bF, smem_u32(bH + (kk + b_kr)*BPAD + wn + nh*16 + b_nc));
#pragma unroll
                for (int mi = 0; mi < 2; mi++) {
                    mma16816(acc[mi][nh*2 + 0], aF[mi], bF[0], bF[1]);
                    mma16816(acc[mi][nh*2 + 1], aF[mi], bF[2], bF[3]);
                }
            }
        }
        __syncthreads();
    }

    // epilogue: v = out * gate (contiguous windows per warp-row -> sectored)
    const __half* __restrict__ Gg = g_gateh + (size_t)h*MTOT;
    __half* __restrict__       Vd = g_v     + (size_t)h*MTOT;
#pragma unroll
    for (int mi = 0; mi < 2; mi++) {
        int r0 = I0 + wm + mi*16 + (lane >> 2);
#pragma unroll
        for (int nj = 0; nj < 4; nj++) {
            int c = J0 + wn + nj*8 + (lane & 3)*2;
            size_t o0 = (size_t)r0*NN + c;
            size_t o1 = (size_t)(r0+8)*NN + c;
            float2 ga0 = __half22float2(*reinterpret_cast<const __half2*>(Gg + o0));
            float2 ga1 = __half22float2(*reinterpret_cast<const __half2*>(Gg + o1));
            *reinterpret_cast<__half2*>(Vd + o0) =
                __floats2half2_rn(acc[mi][nj][0]*ga0.x, acc[mi][nj][1]*ga0.y);
            *reinterpret_cast<__half2*>(Vd + o1) =
                __floats2half2_rn(acc[mi][nj][2]*ga1.x, acc[mi][nj][3]*ga1.y);
        }
    }
}

// ---------------- kernel C: v @ Wo + bo + residual + LN ------------------------
// smem (101888 B, 2 CTAs/SM): vS 34816 (K-major v tile) | y_s 66048 (wst alias) | stats
__global__ void __launch_bounds__(T, 2)
kernelC(const float* __restrict__ pair,
        const float* __restrict__ bo,
        const float* __restrict__ ng,
        const float* __restrict__ nb,
        float* __restrict__ out)
{
    extern __shared__ __align__(16) char smC[];
    __half* vS  = (__half*)smC;                    // [128 h][XPAD] K-major v tile
    float* y_s  = (float*)(smC + 34816);           // [128][129]
    __half* wst = (__half*)(smC + 34816);          // aliases y_s
    float* mu_s = (float*)(smC + 100864);
    float* rs_s = mu_s + 128;

    const int tid = threadIdx.x;
    const int lane = tid & 31, wid = tid >> 5;
    const int wm = (wid & 3)*32, wn = (wid >> 2)*32;
    const int at_kr = (lane & 7) + ((lane >> 4) & 1)*8;   // trans-A: k from bit4
    const int at_mc = ((lane >> 3) & 1)*8;                // trans-A: m from bit3
    const int b_kr  = (lane & 7) + ((lane >> 3) & 1)*8;
    const int b_nc  = (lane >> 4)*8;
    const size_t IJ0 = (size_t)blockIdx.x * 128;

    // v tile in native [h][m] layout via cp.async (coalesced 16B chunks; no
    // staging transpose — A-fragments come from ldmatrix.trans)
#pragma unroll
    for (int t = 0; t < 4; t++) {
        int idx = tid + t*T;                 // 0..2047 (128 h x 16 chunks)
        int h = idx >> 4, c = idx & 15;
        cp16(smem_u32(vS + h*XPAD + c*8), g_v + (size_t)h*MTOT + IJ0 + c*8);
    }
    cp_commit();
    // hmma_projT's first cp_wait<1> covers [vS, W-stage0]; its syncthreads
    // orders visibility before ldmatrix.

    float acc[2][4][4];
    hmma_projT(vS, g_Wo, wst, acc, tid, wm, wn, at_kr, at_mc, b_kr, b_nc);

    // y = acc + bo + pair residual -> y_s (wst dead again)
#pragma unroll
    for (int mi = 0; mi < 2; mi++) {
        int r = wm + mi*16 + (lane >> 2);
#pragma unroll
        for (int nj = 0; nj < 4; nj++) {
            int c = wn + nj*8 + (lane & 3)*2;
            float b0 = __ldg(bo + c), b1 = __ldg(bo + c + 1);
            float2 p0 = *reinterpret_cast<const float2*>(pair + (IJ0 + r)*CC + c);
            float2 p1 = *reinterpret_cast<const float2*>(pair + (IJ0 + r + 8)*CC + c);
            y_s[r*129 + c]       = acc[mi][nj][0] + b0 + p0.x;
            y_s[r*129 + c+1]     = acc[mi][nj][1] + b1 + p0.y;
            y_s[(r+8)*129 + c]   = acc[mi][nj][2] + b0 + p1.x;
            y_s[(r+8)*129 + c+1] = acc[mi][nj][3] + b1 + p1.y;
        }
    }
    __syncthreads();

    // row LN: warp per 8 rows via shuffle — SCALAR smem loads (516B row stride)
#pragma unroll
    for (int rr = 0; rr < 8; rr++) {
        int r = wid*8 + rr;
        const float* row = y_s + r*129 + lane*4;
        float v0 = row[0], v1 = row[1], v2 = row[2], v3 = row[3];
        float s  = v0 + v1 + v2 + v3;
        float s2 = v0*v0 + v1*v1 + v2*v2 + v3*v3;
#pragma unroll
        for (int off = 16; off > 0; off >>= 1) {
            s  += __shfl_xor_sync(0xffffffffu, s,  off);
            s2 += __shfl_xor_sync(0xffffffffu, s2, off);
        }
        if (lane == 0) {
            float mu  = s * (1.f/128.f);
            float var = fmaxf(s2 * (1.f/128.f) - mu*mu, 0.f) + EPS;
            mu_s[r] = mu;
            rs_s[r] = rsqrtf(var);
        }
    }
    __syncthreads();

    // final: LN apply, scalar per-element (c fast -> conflict-free, coalesced STG)
    for (int i = tid; i < 128*128; i += T) {
        int r = i >> 7, c = i & 127;
        float z = y_s[r*129 + c];
        out[(IJ0 + r)*CC + c] = (z - mu_s[r]) * rs_s[r] * __ldg(ng + c) + __ldg(nb + c);
    }
}

// ---------------- launch --------------------------------------------------------
extern "C" void kernel_launch(void* const* d_in, const int* in_sizes, int n_in,
                              void* d_out, int out_size)
{
    const float* pair   = (const float*)d_in[0];
    const float* ln_l_g = (const float*)d_in[1];
    const float* ln_l_b = (const float*)d_in[2];
    const float* ln_r_g = (const float*)d_in[3];
    const float* ln_r_b = (const float*)d_in[4];
    const float* Wl     = (const float*)d_in[5];
    const float* bl     = (const float*)d_in[6];
    const float* Wr     = (const float*)d_in[7];
    const float* br     = (const float*)d_in[8];
    const float* Wg     = (const float*)d_in[9];
    const float* bg     = (const float*)d_in[10];
    const float* Wo     = (const float*)d_in[11];
    const float* bo     = (const float*)d_in[12];
    const float* n_g    = (const float*)d_in[13];
    const float* n_b    = (const float*)d_in[14];
    float* out = (float*)d_out;

    static __half *pWl = nullptr, *pWr, *pWg, *pWo;
    static float *pbLE, *pbRE, *pWgS;
    if (!pWl) {
        cudaGetSymbolAddress((void**)&pWl, g_Wl);
        cudaGetSymbolAddress((void**)&pWr, g_Wr);
        cudaGetSymbolAddress((void**)&pWg, g_Wg);
        cudaGetSymbolAddress((void**)&pWo, g_Wo);
        cudaGetSymbolAddress((void**)&pbLE, g_bLE);
        cudaGetSymbolAddress((void**)&pbRE, g_bRE);
        cudaGetSymbolAddress((void**)&pWgS, g_WgS);
    }

    const size_t smemA = 102400;
    const size_t smemC = 101888;
    const size_t smemB = (size_t)3*KB_STG*sizeof(__half);   // 107520
    cudaFuncSetAttribute(kernelA,     cudaFuncAttributeMaxDynamicSharedMemorySize, (int)smemA);
    cudaFuncSetAttribute(kernelC,     cudaFuncAttributeMaxDynamicSharedMemorySize, (int)smemC);
    cudaFuncSetAttribute(kernelB_mma, cudaFuncAttributeMaxDynamicSharedMemorySize, (int)smemB);

    prep_all<<<dim3(CC, 4), CC>>>(Wl, ln_l_g, ln_l_b, bl,
                                  Wr, ln_r_g, ln_r_b, br,
                                  Wg, Wo,
                                  pWl, pWr, pWg, pWo, pbLE, pbRE, pWgS);

    kernelA<<<MTOT/128, T, smemA>>>(pair, bg);
    kernelB_mma<<<dim3(NN/128, NN/128, CC), T, smemB>>>();
    kernelC<<<MTOT/128, T, smemC>>>(pair, bo, n_g, n_b, out);
}

// round 17
// speedup vs baseline: 2.2582x; 1.0424x over previous
#include <cuda_runtime.h>
#include <cuda_fp16.h>
#include <math.h>

// Problem constants (fixed by dataset): B=1, N=384, C=H=128
#define NN   384
#define CC   128
#define MTOT (NN*NN)
#define EPS  1e-5f
#define XPAD 136      // data plane row stride (fp16 elems)
#define BPAD 136      // weight / right row stride (fp16 elems)
#define APAD 72       // kernelB left-tile row stride (fp16 elems)
#define YST  132      // fp32 staging row stride (16B-aligned rows)
#define T    512      // threads per block (16 warps)

// ---------------- scratch ------------------------------------------------------
__device__ __half g_leftH [(size_t)CC * MTOT];   // [h][i][k]
__device__ __half g_rightH[(size_t)CC * MTOT];   // [h][k][j]
__device__ __half g_gateh [(size_t)CC * MTOT];   // [h][i*N+j] fp16 sigmoid
__device__ __half g_v     [(size_t)CC * MTOT];   // [h][i*N+j] fp16 out*gate
__device__ __half g_Wl[CC*CC], g_Wr[CC*CC], g_Wg[CC*CC], g_Wo[CC*CC];
__device__ float g_bLE[CC], g_bRE[CC], g_WgS[CC];

// ---------------- helpers (baseline PTX only) ----------------------------------
__device__ __forceinline__ unsigned smem_u32(const void* p) {
    return (unsigned)__cvta_generic_to_shared(p);
}
__device__ __forceinline__ void cp16(unsigned saddr, const void* g) {
    asm volatile("cp.async.cg.shared.global [%0], [%1], 16;" :: "r"(saddr), "l"(g));
}
__device__ __forceinline__ void cp_commit() {
    asm volatile("cp.async.commit_group;" ::: "memory");
}
template<int N>
__device__ __forceinline__ void cp_wait() {
    asm volatile("cp.async.wait_group %0;" :: "n"(N) : "memory");
}
__device__ __forceinline__ void ldmx4(unsigned r[4], unsigned addr) {
    asm volatile("ldmatrix.sync.aligned.m8n8.x4.shared.b16 {%0,%1,%2,%3}, [%4];"
        : "=r"(r[0]), "=r"(r[1]), "=r"(r[2]), "=r"(r[3]) : "r"(addr));
}
__device__ __forceinline__ void ldmx4t(unsigned r[4], unsigned addr) {
    asm volatile("ldmatrix.sync.aligned.m8n8.x4.trans.shared.b16 {%0,%1,%2,%3}, [%4];"
        : "=r"(r[0]), "=r"(r[1]), "=r"(r[2]), "=r"(r[3]) : "r"(addr));
}
__device__ __forceinline__ void mma16816(float d[4], const unsigned a[4],
                                         unsigned b0, unsigned b1) {
    asm volatile(
        "mma.sync.aligned.m16n8k16.row.col.f32.f16.f16.f32 "
        "{%0,%1,%2,%3}, {%4,%5,%6,%7}, {%8,%9}, {%0,%1,%2,%3};"
        : "+f"(d[0]), "+f"(d[1]), "+f"(d[2]), "+f"(d[3])
        : "r"(a[0]), "r"(a[1]), "r"(a[2]), "r"(a[3]), "r"(b0), "r"(b1));
}

// ---------------- fused prep kernel (one launch) --------------------------------
__global__ void prep_all(const float* __restrict__ Wl,
                         const float* __restrict__ lgl, const float* __restrict__ lbl,
                         const float* __restrict__ bl,
                         const float* __restrict__ Wr,
                         const float* __restrict__ lgr, const float* __restrict__ lbr,
                         const float* __restrict__ br,
                         const float* __restrict__ Wg,
                         const float* __restrict__ Wo,
                         __half* __restrict__ pWl, __half* __restrict__ pWr,
                         __half* __restrict__ pWg, __half* __restrict__ pWo,
                         float* __restrict__ bLE, float* __restrict__ bRE,
                         float* __restrict__ WgS)
{
    int k = blockIdx.x, n = threadIdx.x, which = blockIdx.y;
    if (which == 0) {
        pWl[k*CC + n] = __float2half_rn(lgl[k] * Wl[k*CC + n]);
        if (k == 0) {
            float s = bl[n];
            for (int kk = 0; kk < CC; kk++) s += lbl[kk] * Wl[kk*CC + n];
            bLE[n] = s;
        }
    } else if (which == 1) {
        pWr[k*CC + n] = __float2half_rn(lgr[k] * Wr[k*CC + n]);
        if (k == 0) {
            float s = br[n];
            for (int kk = 0; kk < CC; kk++) s += lbr[kk] * Wr[kk*CC + n];
            bRE[n] = s;
        }
    } else if (which == 2) {
        pWg[k*CC + n] = __float2half_rn(Wg[k*CC + n]);
        if (k == 0) {
            float s = 0.f;
            for (int kk = 0; kk < CC; kk++) s += Wg[kk*CC + n];
            WgS[n] = s;
        }
    } else {
        pWo[k*CC + n] = __float2half_rn(Wo[k*CC + n]);
    }
}

// ---------------- HMMA projection GEMM: 32x32 warp tiles, row-major A ----------
__device__ __forceinline__ void hmma_proj(
    const __half* __restrict__ aP,
    const __half* __restrict__ W,
    __half* __restrict__ wst,
    float acc[2][4][4],
    int tid, int wm, int wn,
    int a_row, int a_kh, int b_kr, int b_nc)
{
    const int PLANE = 64*BPAD;
#pragma unroll
    for (int mi = 0; mi < 2; mi++)
#pragma unroll
        for (int nj = 0; nj < 4; nj++)
#pragma unroll
            for (int q = 0; q < 4; q++) acc[mi][nj][q] = 0.f;

#pragma unroll
    for (int s = 0; s < 2; s++) {
        __half* d = wst + s*PLANE;
        int k0 = s*64;
#pragma unroll
        for (int t = 0; t < 2; t++) {
            int idx = tid + t*T;            // 0..1023 (64 rows x 16 chunks)
            int r = idx >> 4, c = idx & 15;
            cp16(smem_u32(d + r*BPAD + c*8), W + (k0 + r)*CC + c*8);
        }
        cp_commit();
    }

#pragma unroll
    for (int s = 0; s < 2; s++) {
        if (s == 0) cp_wait<1>(); else cp_wait<0>();
        __syncthreads();
        const __half* bP = wst + s*PLANE;
        int k0 = s*64;
#pragma unroll
        for (int kk = 0; kk < 64; kk += 16) {
            unsigned aF[2][4];
#pragma unroll
            for (int mi = 0; mi < 2; mi++)
                ldmx4(aF[mi], smem_u32(aP + (wm + mi*16 + a_row)*XPAD + k0 + kk + a_kh));
#pragma unroll
            for (int nh = 0; nh < 2; nh++) {
                unsigned bF[4];
                ldmx4t(bF, smem_u32(bP + (kk + b_kr)*BPAD + wn + nh*16 + b_nc));
#pragma unroll
                for (int mi = 0; mi < 2; mi++) {
                    mma16816(acc[mi][nh*2 + 0], aF[mi], bF[0], bF[1]);
                    mma16816(acc[mi][nh*2 + 1], aF[mi], bF[2], bF[3]);
                }
            }
        }
    }
    __syncthreads();   // all wst reads done before caller reuses the region
}

// ---------------- HMMA projection GEMM variant: K-major A (trans fragments) ----
__device__ __forceinline__ void hmma_projT(
    const __half* __restrict__ aT,
    const __half* __restrict__ W,
    __half* __restrict__ wst,
    float acc[2][4][4],
    int tid, int wm, int wn,
    int at_kr, int at_mc, int b_kr, int b_nc)
{
    const int PLANE = 64*BPAD;
#pragma unroll
    for (int mi = 0; mi < 2; mi++)
#pragma unroll
        for (int nj = 0; nj < 4; nj++)
#pragma unroll
            for (int q = 0; q < 4; q++) acc[mi][nj][q] = 0.f;

#pragma unroll
    for (int s = 0; s < 2; s++) {
        __half* d = wst + s*PLANE;
        int k0 = s*64;
#pragma unroll
        for (int t = 0; t < 2; t++) {
            int idx = tid + t*T;
            int r = idx >> 4, c = idx & 15;
            cp16(smem_u32(d + r*BPAD + c*8), W + (k0 + r)*CC + c*8);
        }
        cp_commit();
    }

#pragma unroll
    for (int s = 0; s < 2; s++) {
        if (s == 0) cp_wait<1>(); else cp_wait<0>();
        __syncthreads();
        const __half* bP = wst + s*PLANE;
        int k0 = s*64;
#pragma unroll
        for (int kk = 0; kk < 64; kk += 16) {
            unsigned aF[2][4];
#pragma unroll
            for (int mi = 0; mi < 2; mi++)
                ldmx4t(aF[mi], smem_u32(aT + (k0 + kk + at_kr)*XPAD + wm + mi*16 + at_mc));
#pragma unroll
            for (int nh = 0; nh < 2; nh++) {
                unsigned bF[4];
                ldmx4t(bF, smem_u32(bP + (kk + b_kr)*BPAD + wn + nh*16 + b_nc));
#pragma unroll
                for (int mi = 0; mi < 2; mi++) {
                    mma16816(acc[mi][nh*2 + 0], aF[mi], bF[0], bF[1]);
                    mma16816(acc[mi][nh*2 + 1], aF[mi], bF[2], bF[3]);
                }
            }
        }
    }
    __syncthreads();
}

// fragment -> transposed channel-major, single fp16 plane (staged, coalesced)
__device__ __forceinline__ void frag_store_half(
    const float acc[2][4][4], const float* __restrict__ bias,
    unsigned* __restrict__ stage,
    __half* __restrict__ dstH,
    size_t R0, int lane, int wm, int wn, int tid)
{
#pragma unroll
    for (int mi = 0; mi < 2; mi++) {
        int r = wm + mi*16 + (lane >> 2);
#pragma unroll
        for (int nj = 0; nj < 4; nj++) {
            int c = wn + nj*8 + (lane & 3)*2;
            float b0 = __ldg(bias + c), b1 = __ldg(bias + c + 1);
            stage[c*129 + r]       = (unsigned)__half_as_ushort(__float2half_rn(acc[mi][nj][0] + b0));
            stage[(c+1)*129 + r]   = (unsigned)__half_as_ushort(__float2half_rn(acc[mi][nj][1] + b1));
            stage[c*129 + r+8]     = (unsigned)__half_as_ushort(__float2half_rn(acc[mi][nj][2] + b0));
            stage[(c+1)*129 + r+8] = (unsigned)__half_as_ushort(__float2half_rn(acc[mi][nj][3] + b1));
        }
    }
    __syncthreads();
    for (int idx = tid; idx < 128*64; idx += T) {
        int n = idx >> 6, r2 = idx & 63;
        unsigned w0 = stage[n*129 + 2*r2], w1 = stage[n*129 + 2*r2 + 1];
        unsigned hw = (w0 & 0xFFFFu) | (w1 << 16);
        *reinterpret_cast<unsigned*>(dstH + (size_t)n*MTOT + R0 + 2*r2) = hw;
    }
    __syncthreads();
}

// gate: logit = sd[r]*acc + mu[r]*S[c] + bg[c]; sigmoid; fp16 channel-major
__device__ __forceinline__ void frag_store_gate(
    const float acc[2][4][4], const float* __restrict__ bg,
    const float* __restrict__ Sg,
    const float* __restrict__ sd_s, const float* __restrict__ mu_s,
    float* __restrict__ stage, __half* __restrict__ dst,
    size_t R0, int lane, int wm, int wn, int tid)
{
#pragma unroll
    for (int mi = 0; mi < 2; mi++) {
        int r = wm + mi*16 + (lane >> 2);
        float sd0 = sd_s[r], mu0 = mu_s[r];
        float sd1 = sd_s[r+8], mu1 = mu_s[r+8];
#pragma unroll
        for (int nj = 0; nj < 4; nj++) {
            int c = wn + nj*8 + (lane & 3)*2;
            float S0 = __ldg(Sg + c) , B0 = __ldg(bg + c);
            float S1 = __ldg(Sg + c+1), B1 = __ldg(bg + c+1);
            float z;
            z = sd0*acc[mi][nj][0] + mu0*S0 + B0; stage[c*129 + r]       = 1.f/(1.f+expf(-z));
            z = sd0*acc[mi][nj][1] + mu0*S1 + B1; stage[(c+1)*129 + r]   = 1.f/(1.f+expf(-z));
            z = sd1*acc[mi][nj][2] + mu1*S0 + B0; stage[c*129 + r+8]     = 1.f/(1.f+expf(-z));
            z = sd1*acc[mi][nj][3] + mu1*S1 + B1; stage[(c+1)*129 + r+8] = 1.f/(1.f+expf(-z));
        }
    }
    __syncthreads();
    for (int idx = tid; idx < 128*64; idx += T) {
        int n = idx >> 6, r2 = idx & 63;
        __half h0 = __float2half_rn(stage[n*129 + 2*r2]);
        __half h1 = __float2half_rn(stage[n*129 + 2*r2 + 1]);
        unsigned hw = (unsigned)__half_as_ushort(h0) | ((unsigned)__half_as_ushort(h1) << 16);
        *reinterpret_cast<unsigned*>(dst + (size_t)n*MTOT + R0 + 2*r2) = hw;
    }
    __syncthreads();
}

// ---------------- kernel A: LN + 3 projections ---------------------------------
// smem (103936 B, 2 CTAs/SM): xh 34816 | stage 67584 (pair-cache / wst / frag
// stage, all lifetime-disjoint) | stats 1536
__global__ void __launch_bounds__(T, 2)
kernelA(const float* __restrict__ pair,
        const float* __restrict__ bg)
{
    extern __shared__ __align__(16) char smA[];
    __half* xh  = (__half*)smA;                    // [128][XPAD]
    char* stg = smA + 34816;                       // stage region (67584 B)
    __half* wst = (__half*)stg;                    // aliases stage
    unsigned* stageU = (unsigned*)stg;
    float*    stageF = (float*)stg;                // pair cache [128][YST]
    float* mu_s = (float*)(smA + 102400);
    float* rs_s = mu_s + 128;
    float* sd_s = rs_s + 128;

    const int tid = threadIdx.x;
    const int lane = tid & 31, wid = tid >> 5;
    const int wm = (wid & 3)*32, wn = (wid >> 2)*32;
    const int a_row = (lane & 7) + ((lane >> 3) & 1)*8;
    const int a_kh  = (lane >> 4)*8;
    const int b_kr  = (lane & 7) + ((lane >> 3) & 1)*8;
    const int b_nc  = (lane >> 4)*8;
    const size_t R0 = (size_t)blockIdx.x * 128;

    // LN stats: warp per 8 rows; pair tile cached to smem (single global read)
#pragma unroll
    for (int rr = 0; rr < 8; rr++) {
        int r = wid*8 + rr;
        float4 v = *reinterpret_cast<const float4*>(pair + (R0 + r)*CC + lane*4);
        *reinterpret_cast<float4*>(stageF + r*YST + lane*4) = v;   // aligned, conflict-free
        float s  = v.x + v.y + v.z + v.w;
        float s2 = v.x*v.x + v.y*v.y + v.z*v.z + v.w*v.w;
#pragma unroll
        for (int off = 16; off > 0; off >>= 1) {
            s  += __shfl_xor_sync(0xffffffffu, s,  off);
            s2 += __shfl_xor_sync(0xffffffffu, s2, off);
        }
        if (lane == 0) {
            float mu  = s * (1.f/128.f);
            float var = fmaxf(s2 * (1.f/128.f) - mu*mu, 0.f) + EPS;
            mu_s[r] = mu;
            rs_s[r] = rsqrtf(var);
            sd_s[r] = sqrtf(var);
        }
    }
    __syncthreads();

    // xhat from cached tile -> single fp16 plane
    for (int i = tid; i < 128*32; i += T) {
        int r = i >> 5, c4 = i & 31;
        float4 v = *reinterpret_cast<const float4*>(stageF + r*YST + c4*4);
        float mu = mu_s[r], rs = rs_s[r];
        __half2 h0 = __floats2half2_rn((v.x - mu)*rs, (v.y - mu)*rs);
        __half2 h1 = __floats2half2_rn((v.z - mu)*rs, (v.w - mu)*rs);
        *reinterpret_cast<uint2*>(xh + r*XPAD + c4*4) =
            make_uint2(*(unsigned*)&h0, *(unsigned*)&h1);
    }
    __syncthreads();   // pair-cache reads done before hmma_proj's cp.async hits the alias

    float acc[2][4][4];
    hmma_proj(xh, g_Wl, wst, acc, tid, wm, wn, a_row, a_kh, b_kr, b_nc);
    frag_store_half(acc, g_bLE, stageU, g_leftH, R0, lane, wm, wn, tid);
    hmma_proj(xh, g_Wr, wst, acc, tid, wm, wn, a_row, a_kh, b_kr, b_nc);
    frag_store_half(acc, g_bRE, stageU, g_rightH, R0, lane, wm, wn, tid);
    hmma_proj(xh, g_Wg, wst, acc, tid, wm, wn, a_row, a_kh, b_kr, b_nc);
    frag_store_gate(acc, bg, g_WgS, sd_s, mu_s, stageF, g_gateh, R0, lane, wm, wn, tid);
}

// ---------------- kernel B: per-channel 384^3 GEMM + fused gate, 3-stage -------
#define KB_STG (128*APAD + 64*BPAD)   // fp16 elements per stage (17920)

__device__ __forceinline__ void kb_prefetch(
    __half* st,
    const __half* __restrict__ AgH,
    const __half* __restrict__ BgH,
    int k0, int tid)
{
    __half* aH = st;
    __half* bH = st + 128*APAD;
#pragma unroll
    for (int t = 0; t < 2; t++) {
        int idx = tid + t*T;                // 0..1023 (128 rows x 8 chunks)
        int r = idx >> 3, c = idx & 7;
        cp16(smem_u32(aH + r*APAD + c*8), AgH + (size_t)r*NN + k0 + c*8);
    }
#pragma unroll
    for (int t = 0; t < 2; t++) {
        int idx = tid + t*T;                // 0..1023 (64 rows x 16 chunks)
        int r = idx >> 4, c = idx & 15;
        cp16(smem_u32(bH + r*BPAD + c*8), BgH + (size_t)(k0 + r)*NN + c*8);
    }
}

__global__ void __launch_bounds__(T, 2)
kernelB_mma()
{
    extern __shared__ __align__(16) __half smb[];
    const int tid  = threadIdx.x;
    const int lane = tid & 31, wid = tid >> 5;
    const int J0 = blockIdx.x*128, I0 = blockIdx.y*128, h = blockIdx.z;
    const int wm = (wid & 3)*32, wn = (wid >> 2)*32;

    const __half* __restrict__ AgH = g_leftH  + (size_t)h*MTOT + (size_t)I0*NN;
    const __half* __restrict__ BgH = g_rightH + (size_t)h*MTOT + J0;

    float acc[2][4][4];
#pragma unroll
    for (int mi = 0; mi < 2; mi++)
#pragma unroll
        for (int nj = 0; nj < 4; nj++)
#pragma unroll
            for (int q = 0; q < 4; q++) acc[mi][nj][q] = 0.f;

    const int a_row = (lane & 7) + ((lane >> 3) & 1)*8;
    const int a_kh  = (lane >> 4)*8;
    const int b_kr  = (lane & 7) + ((lane >> 3) & 1)*8;
    const int b_nc  = (lane >> 4)*8;

    kb_prefetch(smb + 0*KB_STG, AgH, BgH, 0,  tid); cp_commit();
    kb_prefetch(smb + 1*KB_STG, AgH, BgH, 64, tid); cp_commit();

    for (int ch = 0; ch < 6; ch++) {
        if (ch + 2 < 6) {
            kb_prefetch(smb + ((ch+2)%3)*KB_STG, AgH, BgH, (ch+2)*64, tid);
            cp_commit();
            cp_wait<2>();
        } else if (ch + 1 < 6) {
            cp_wait<1>();
        } else {
            cp_wait<0>();
        }
        __syncthreads();

        const __half* aH = smb + (ch%3)*KB_STG;
        const __half* bH = aH + 128*APAD;
#pragma unroll
        for (int kk = 0; kk < 64; kk += 16) {
            unsigned aF[2][4];
#pragma unroll
            for (int mi = 0; mi < 2; mi++)
                ldmx4(aF[mi], smem_u32(aH + (wm + mi*16 + a_row)*APAD + kk + a_kh));
#pragma unroll
            for (int nh = 0; nh < 2; nh++) {
                unsigned bF[4];
                ldmx4t(bF, smem_u32(bH + (kk + b_kr)*BPAD + wn + nh*16 + b_nc));
#pragma unroll
                for (int mi = 0; mi < 2; mi++) {
                    mma16816(acc[mi][nh*2 + 0], aF[mi], bF[0], bF[1]);
                    mma16816(acc[mi][nh*2 + 1], aF[mi], bF[2], bF[3]);
                }
            }
        }
        __syncthreads();
    }

    // epilogue: v = out * gate (contiguous windows per warp-row -> sectored)
    const __half* __restrict__ Gg = g_gateh + (size_t)h*MTOT;
    __half* __restrict__       Vd = g_v     + (size_t)h*MTOT;
#pragma unroll
    for (int mi = 0; mi < 2; mi++) {
        int r0 = I0 + wm + mi*16 + (lane >> 2);
#pragma unroll
        for (int nj = 0; nj < 4; nj++) {
            int c = J0 + wn + nj*8 + (lane & 3)*2;
            size_t o0 = (size_t)r0*NN + c;
            size_t o1 = (size_t)(r0+8)*NN + c;
            float2 ga0 = __half22float2(*reinterpret_cast<const __half2*>(Gg + o0));
            float2 ga1 = __half22float2(*reinterpret_cast<const __half2*>(Gg + o1));
            *reinterpret_cast<__half2*>(Vd + o0) =
                __floats2half2_rn(acc[mi][nj][0]*ga0.x, acc[mi][nj][1]*ga0.y);
            *reinterpret_cast<__half2*>(Vd + o1) =
                __floats2half2_rn(acc[mi][nj][2]*ga1.x, acc[mi][nj][3]*ga1.y);
        }
    }
}

// ---------------- kernel C: v @ Wo + bo + residual + LN ------------------------
// smem (103424 B, 2 CTAs/SM): vS 34816 | y_s [128][YST] 67584 (wst alias) | stats
__global__ void __launch_bounds__(T, 2)
kernelC(const float* __restrict__ pair,
        const float* __restrict__ bo,
        const float* __restrict__ ng,
        const float* __restrict__ nb,
        float* __restrict__ out)
{
    extern __shared__ __align__(16) char smC[];
    __half* vS  = (__half*)smC;                    // [128 h][XPAD] K-major v tile
    float* y_s  = (float*)(smC + 34816);           // [128][YST]
    __half* wst = (__half*)(smC + 34816);          // aliases y_s
    float* mu_s = (float*)(smC + 102400);
    float* rs_s = mu_s + 128;

    const int tid = threadIdx.x;
    const int lane = tid & 31, wid = tid >> 5;
    const int wm = (wid & 3)*32, wn = (wid >> 2)*32;
    const int at_kr = (lane & 7) + ((lane >> 4) & 1)*8;   // trans-A: k from bit4
    const int at_mc = ((lane >> 3) & 1)*8;                // trans-A: m from bit3
    const int b_kr  = (lane & 7) + ((lane >> 3) & 1)*8;
    const int b_nc  = (lane >> 4)*8;
    const size_t IJ0 = (size_t)blockIdx.x * 128;

    // v tile in native [h][m] layout via cp.async
#pragma unroll
    for (int t = 0; t < 4; t++) {
        int idx = tid + t*T;                 // 0..2047 (128 h x 16 chunks)
        int h = idx >> 4, c = idx & 15;
        cp16(smem_u32(vS + h*XPAD + c*8), g_v + (size_t)h*MTOT + IJ0 + c*8);
    }
    cp_commit();

    float acc[2][4][4];
    hmma_projT(vS, g_Wo, wst, acc, tid, wm, wn, at_kr, at_mc, b_kr, b_nc);

    // y = acc + bo + pair residual -> y_s (wst dead again)
#pragma unroll
    for (int mi = 0; mi < 2; mi++) {
        int r = wm + mi*16 + (lane >> 2);
#pragma unroll
        for (int nj = 0; nj < 4; nj++) {
            int c = wn + nj*8 + (lane & 3)*2;
            float b0 = __ldg(bo + c), b1 = __ldg(bo + c + 1);
            float2 p0 = *reinterpret_cast<const float2*>(pair + (IJ0 + r)*CC + c);
            float2 p1 = *reinterpret_cast<const float2*>(pair + (IJ0 + r + 8)*CC + c);
            y_s[r*YST + c]       = acc[mi][nj][0] + b0 + p0.x;
            y_s[r*YST + c+1]     = acc[mi][nj][1] + b1 + p0.y;
            y_s[(r+8)*YST + c]   = acc[mi][nj][2] + b0 + p1.x;
            y_s[(r+8)*YST + c+1] = acc[mi][nj][3] + b1 + p1.y;
        }
    }
    __syncthreads();

    // row LN: warp per 8 rows via shuffle — LDS.128 (YST rows are 16B-aligned)
#pragma unroll
    for (int rr = 0; rr < 8; rr++) {
        int r = wid*8 + rr;
        float4 v = *reinterpret_cast<const float4*>(y_s + r*YST + lane*4);
        float s  = v.x + v.y + v.z + v.w;
        float s2 = v.x*v.x + v.y*v.y + v.z*v.z + v.w*v.w;
#pragma unroll
        for (int off = 16; off > 0; off >>= 1) {
            s  += __shfl_xor_sync(0xffffffffu, s,  off);
            s2 += __shfl_xor_sync(0xffffffffu, s2, off);
        }
        if (lane == 0) {
            float mu  = s * (1.f/128.f);
            float var = fmaxf(s2 * (1.f/128.f) - mu*mu, 0.f) + EPS;
            mu_s[r] = mu;
            rs_s[r] = rsqrtf(var);
        }
    }
    __syncthreads();

    // final: LN apply via float4 smem reads + coalesced float4 STG
    for (int i = tid; i < 128*32; i += T) {
        int r = i >> 5, c4 = (i & 31)*4;
        float mu = mu_s[r], rs = rs_s[r];
        float4 z = *reinterpret_cast<const float4*>(y_s + r*YST + c4);
        float4 o;
        o.x = (z.x - mu) * rs * __ldg(ng + c4 + 0) + __ldg(nb + c4 + 0);
        o.y = (z.y - mu) * rs * __ldg(ng + c4 + 1) + __ldg(nb + c4 + 1);
        o.z = (z.z - mu) * rs * __ldg(ng + c4 + 2) + __ldg(nb + c4 + 2);
        o.w = (z.w - mu) * rs * __ldg(ng + c4 + 3) + __ldg(nb + c4 + 3);
        *reinterpret_cast<float4*>(out + (IJ0 + r)*CC + c4) = o;
    }
}

// ---------------- launch --------------------------------------------------------
extern "C" void kernel_launch(void* const* d_in, const int* in_sizes, int n_in,
                              void* d_out, int out_size)
{
    const float* pair   = (const float*)d_in[0];
    const float* ln_l_g = (const float*)d_in[1];
    const float* ln_l_b = (const float*)d_in[2];
    const float* ln_r_g = (const float*)d_in[3];
    const float* ln_r_b = (const float*)d_in[4];
    const float* Wl     = (const float*)d_in[5];
    const float* bl     = (const float*)d_in[6];
    const float* Wr     = (const float*)d_in[7];
    const float* br     = (const float*)d_in[8];
    const float* Wg     = (const float*)d_in[9];
    const float* bg     = (const float*)d_in[10];
    const float* Wo     = (const float*)d_in[11];
    const float* bo     = (const float*)d_in[12];
    const float* n_g    = (const float*)d_in[13];
    const float* n_b    = (const float*)d_in[14];
    float* out = (float*)d_out;

    static __half *pWl = nullptr, *pWr, *pWg, *pWo;
    static float *pbLE, *pbRE, *pWgS;
    if (!pWl) {
        cudaGetSymbolAddress((void**)&pWl, g_Wl);
        cudaGetSymbolAddress((void**)&pWr, g_Wr);
        cudaGetSymbolAddress((void**)&pWg, g_Wg);
        cudaGetSymbolAddress((void**)&pWo, g_Wo);
        cudaGetSymbolAddress((void**)&pbLE, g_bLE);
        cudaGetSymbolAddress((void**)&pbRE, g_bRE);
        cudaGetSymbolAddress((void**)&pWgS, g_WgS);
    }

    const size_t smemA = 103936;   // xh 34816 | stage 67584 | stats 1536
    const size_t smemC = 103424;   // vS 34816 | y_s 67584 | stats 1024
    const size_t smemB = (size_t)3*KB_STG*sizeof(__half);   // 107520
    cudaFuncSetAttribute(kernelA,     cudaFuncAttributeMaxDynamicSharedMemorySize, (int)smemA);
    cudaFuncSetAttribute(kernelC,     cudaFuncAttributeMaxDynamicSharedMemorySize, (int)smemC);
    cudaFuncSetAttribute(kernelB_mma, cudaFuncAttributeMaxDynamicSharedMemorySize, (int)smemB);

    prep_all<<<dim3(CC, 4), CC>>>(Wl, ln_l_g, ln_l_b, bl,
                                  Wr, ln_r_g, ln_r_b, br,
                                  Wg, Wo,
                                  pWl, pWr, pWg, pWo, pbLE, pbRE, pWgS);

    kernelA<<<MTOT/128, T, smemA>>>(pair, bg);
    kernelB_mma<<<dim3(NN/128, NN/128, CC), T, smemB>>>();
    kernelC<<<MTOT/128, T, smemC>>>(pair, bo, n_g, n_b, out);
}